// round 7
// baseline (speedup 1.0000x reference)
#include <cuda_runtime.h>
#include <cuda_bf16.h>
#include <math.h>
#include <stdint.h>

#define B_   8
#define T_   4096
#define BT   (B_*T_)          // 32768 rows
#define DM   512
#define NH   8
#define HD   64

#define PADH 40               // smem row stride in halves (80B; conflict-free)
#define TILEB  (128*PADH*2)   // 10240 B per tile
#define STAGEB (4*TILEB)      // 40960 B per stage
#define SMEMB  (2*STAGEB)     // 81920 B

// ---------------- scratch (static device globals; no allocation) ------------
__device__ float g_Q   [(size_t)BT * DM];      // Q fp32 (raw; roped in attn)
__device__ float g_KV  [(size_t)BT * 1024];    // kv raw fp32 (K roped in context)
__device__ float g_Ctx [B_*NH*HD*HD];
__device__ float g_Ksum[B_*NH*HD];
__device__ float g_RopC[T_*32];
__device__ float g_RopS[T_*32];

__device__ __nv_bfloat16 g_Xhi[(size_t)BT*DM],  g_Xlo[(size_t)BT*DM];
__device__ __nv_bfloat16 g_Chi[(size_t)BT*128], g_Clo[(size_t)BT*128];
__device__ __nv_bfloat16 g_AtH[(size_t)BT*DM],  g_AtL[(size_t)BT*DM];
__device__ __nv_bfloat16 g_WqdH[640*512], g_WqdL[640*512];   // [Wq|Wd]^T rows
__device__ __nv_bfloat16 g_WuH[1024*128], g_WuL[1024*128];
__device__ __nv_bfloat16 g_WoH[512*512],  g_WoL[512*512];

// ---------------- helpers ---------------------------------------------------
__device__ __forceinline__ uint32_t smem_u32(const void* p) {
    uint32_t a;
    asm("{ .reg .u64 t; cvta.to.shared.u64 t, %1; cvt.u32.u64 %0, t; }"
        : "=r"(a) : "l"(p));
    return a;
}
__device__ __forceinline__ void mma16816(float* d, const uint32_t* a, const uint32_t* b)
{
    asm volatile(
        "mma.sync.aligned.m16n8k16.row.col.f32.bf16.bf16.f32 "
        "{%0,%1,%2,%3}, {%4,%5,%6,%7}, {%8,%9}, {%0,%1,%2,%3};"
        : "+f"(d[0]), "+f"(d[1]), "+f"(d[2]), "+f"(d[3])
        : "r"(a[0]), "r"(a[1]), "r"(a[2]), "r"(a[3]), "r"(b[0]), "r"(b[1]));
}
__device__ __forceinline__ void ldsm_x4(uint32_t* r, uint32_t addr) {
    asm volatile("ldmatrix.sync.aligned.m8n8.x4.shared.b16 {%0,%1,%2,%3}, [%4];"
        : "=r"(r[0]), "=r"(r[1]), "=r"(r[2]), "=r"(r[3]) : "r"(addr));
}
__device__ __forceinline__ uint32_t pack_bf2(__nv_bfloat16 a, __nv_bfloat16 b)
{
    __nv_bfloat162 p; p.x = a; p.y = b;
    return *(uint32_t*)&p;
}

// ========== bf16 split-3 GEMM, 512 thr, double-buffered, 1 sync/chunk =======
// D = Ahi@Bhi^T + Alo@Bhi^T + Ahi@Blo^T (+bias).  A[*,K], B[N,K] bf16 rowmajor.
// 128x128 CTA tile, BK=32, 16 warps (4x4), warp tile 32x32.
// Tiles with n0 <  NS  -> fp32 out to outF   (row stride NS,  bias1[col])
// Tiles with n0 >= NS  -> bf16 hi/lo to outHi/outLo (row stride ldH, bias2)
__global__ __launch_bounds__(512) void bgemm3(
    const __nv_bfloat16* __restrict__ Ahi, const __nv_bfloat16* __restrict__ Alo,
    const __nv_bfloat16* __restrict__ Bhi, const __nv_bfloat16* __restrict__ Blo,
    const float* __restrict__ bias1, const float* __restrict__ bias2,
    float* __restrict__ outF,
    __nv_bfloat16* __restrict__ outHi, __nv_bfloat16* __restrict__ outLo,
    int NS, int ldH, int K)
{
    extern __shared__ char smem[];
    const uint32_t sbase = smem_u32(smem);

    const int tid  = threadIdx.x;
    const int lane = tid & 31;
    const int wid  = tid >> 5;                 // 0..15
    const int wm   = (wid >> 2) * 32;          // 0,32,64,96
    const int wn   = (wid & 3) * 32;
    const int g    = lane >> 2;
    const int t2   = (lane & 3) * 2;
    const int m0   = blockIdx.y * 128;
    const int n0   = blockIdx.x * 128;

    // loader: 512 threads = 1 uint4 (16B) per tile per chunk
    const int lrow = tid >> 2;                 // 0..127
    const int lseg = tid & 3;                  // 16B segment in 64B row
    const __nv_bfloat16* gA0 = Ahi + (size_t)(m0 + lrow) * K + lseg * 8;
    const __nv_bfloat16* gA1 = Alo + (size_t)(m0 + lrow) * K + lseg * 8;
    const __nv_bfloat16* gB0 = Bhi + (size_t)(n0 + lrow) * K + lseg * 8;
    const __nv_bfloat16* gB1 = Blo + (size_t)(n0 + lrow) * K + lseg * 8;
    const uint32_t soff = (uint32_t)(lrow * (PADH*2) + lseg * 16);

    // ldmatrix lane address components
    const int a_row  = ((lane >> 3) & 1) * 8 + (lane & 7);
    const int a_col8 = (lane >> 4) * 8;
    const int b_row  = ((lane >> 4) & 1) * 8 + (lane & 7);   // paired-n x4
    const int b_col8 = ((lane >> 3) & 1) * 8;

    const int nch = K >> 5;

    uint4 p0, p1, p2, p3;
    auto loadc = [&](int ch) {
        const int ko = ch * 32;
        p0 = *(const uint4*)(gA0 + ko);
        p1 = *(const uint4*)(gA1 + ko);
        p2 = *(const uint4*)(gB0 + ko);
        p3 = *(const uint4*)(gB1 + ko);
    };
    auto storec = [&](int st) {
        char* s = smem + st * STAGEB + soff;
        *(uint4*)(s)            = p0;
        *(uint4*)(s + TILEB)    = p1;
        *(uint4*)(s + 2*TILEB)  = p2;
        *(uint4*)(s + 3*TILEB)  = p3;
    };

    float acc[2][4][4];
    #pragma unroll
    for (int mt = 0; mt < 2; ++mt)
        #pragma unroll
        for (int nt = 0; nt < 4; ++nt)
            #pragma unroll
            for (int i = 0; i < 4; ++i) acc[mt][nt][i] = 0.f;

    loadc(0);
    storec(0);
    if (nch > 1) loadc(1);
    __syncthreads();

    for (int ch = 0; ch < nch; ++ch) {
        const int st = ch & 1;
        if (ch + 1 < nch) storec(st ^ 1);
        if (ch + 2 < nch) loadc(ch + 2);

        const uint32_t uS = sbase + st * STAGEB;
        #pragma unroll
        for (int ks = 0; ks < 2; ++ks) {
            const int k0 = ks * 16;
            uint32_t ah[2][4], al[2][4];
            #pragma unroll
            for (int mt = 0; mt < 2; ++mt) {
                uint32_t off = (uint32_t)(((wm + mt*16 + a_row) * PADH + k0 + a_col8) * 2);
                ldsm_x4(ah[mt], uS + off);
                ldsm_x4(al[mt], uS + TILEB + off);
            }
            #pragma unroll
            for (int pr = 0; pr < 2; ++pr) {       // n-pair: nt = 2*pr + sub
                uint32_t boff = (uint32_t)(((wn + pr*16 + b_row) * PADH + k0 + b_col8) * 2);
                uint32_t bh4[4], bl4[4];
                ldsm_x4(bh4, uS + 2*TILEB + boff);
                ldsm_x4(bl4, uS + 3*TILEB + boff);
                #pragma unroll
                for (int sub = 0; sub < 2; ++sub) {
                    const uint32_t* bh = &bh4[sub*2];
                    const uint32_t* bl = &bl4[sub*2];
                    const int nt = pr*2 + sub;
                    #pragma unroll
                    for (int mt = 0; mt < 2; ++mt) {
                        mma16816(acc[mt][nt], ah[mt], bh);
                        mma16816(acc[mt][nt], al[mt], bh);
                        mma16816(acc[mt][nt], ah[mt], bl);
                    }
                }
            }
        }
        __syncthreads();
    }

    // epilogue
    if (n0 < NS) {
        #pragma unroll
        for (int mt = 0; mt < 2; ++mt) {
            int row = m0 + wm + mt * 16 + g;
            #pragma unroll
            for (int nt = 0; nt < 4; ++nt) {
                int col = n0 + wn + nt * 8 + t2;
                float b0 = bias1[col], b1 = bias1[col + 1];
                *(float2*)(outF + (size_t)row * NS + col) =
                    make_float2(acc[mt][nt][0] + b0, acc[mt][nt][1] + b1);
                *(float2*)(outF + (size_t)(row + 8) * NS + col) =
                    make_float2(acc[mt][nt][2] + b0, acc[mt][nt][3] + b1);
            }
        }
    } else {
        #pragma unroll
        for (int mt = 0; mt < 2; ++mt) {
            int row = m0 + wm + mt * 16 + g;
            #pragma unroll
            for (int nt = 0; nt < 4; ++nt) {
                int col = (n0 - NS) + wn + nt * 8 + t2;
                float b0 = bias2[col], b1 = bias2[col + 1];
                float v00 = acc[mt][nt][0] + b0, v01 = acc[mt][nt][1] + b1;
                float v10 = acc[mt][nt][2] + b0, v11 = acc[mt][nt][3] + b1;
                __nv_bfloat16 h00 = __float2bfloat16_rn(v00);
                __nv_bfloat16 h01 = __float2bfloat16_rn(v01);
                __nv_bfloat16 h10 = __float2bfloat16_rn(v10);
                __nv_bfloat16 h11 = __float2bfloat16_rn(v11);
                *(uint32_t*)(outHi + (size_t)row * ldH + col)       = pack_bf2(h00, h01);
                *(uint32_t*)(outHi + (size_t)(row + 8) * ldH + col) = pack_bf2(h10, h11);
                *(uint32_t*)(outLo + (size_t)row * ldH + col) = pack_bf2(
                    __float2bfloat16_rn(v00 - __bfloat162float(h00)),
                    __float2bfloat16_rn(v01 - __bfloat162float(h01)));
                *(uint32_t*)(outLo + (size_t)(row + 8) * ldH + col) = pack_bf2(
                    __float2bfloat16_rn(v10 - __bfloat162float(h10)),
                    __float2bfloat16_rn(v11 - __bfloat162float(h11)));
            }
        }
    }
}

// ---------------- split fp32 -> bf16 hi/lo (no transpose) -------------------
__global__ __launch_bounds__(256) void split_rows(
    const float* __restrict__ X, __nv_bfloat16* __restrict__ Hi,
    __nv_bfloat16* __restrict__ Lo)
{
    size_t e0 = ((size_t)blockIdx.x * 256 + threadIdx.x) * 4;
    float4 v = *(const float4*)(X + e0);
    __nv_bfloat16 h0 = __float2bfloat16_rn(v.x), h1 = __float2bfloat16_rn(v.y);
    __nv_bfloat16 h2 = __float2bfloat16_rn(v.z), h3 = __float2bfloat16_rn(v.w);
    uint2 hh = make_uint2(pack_bf2(h0, h1), pack_bf2(h2, h3));
    uint2 ll = make_uint2(
        pack_bf2(__float2bfloat16_rn(v.x - __bfloat162float(h0)),
                 __float2bfloat16_rn(v.y - __bfloat162float(h1))),
        pack_bf2(__float2bfloat16_rn(v.z - __bfloat162float(h2)),
                 __float2bfloat16_rn(v.w - __bfloat162float(h3))));
    *(uint2*)(Hi + e0) = hh;
    *(uint2*)(Lo + e0) = ll;
}

// ------- weight transpose + split: W[K,N] -> WtHi/WtLo[N,K] bf16 ------------
__global__ __launch_bounds__(256) void split_weightT(
    const float* __restrict__ W, __nv_bfloat16* __restrict__ Whi,
    __nv_bfloat16* __restrict__ Wlo, int K, int N)
{
    __shared__ float t[32][33];
    int kb = blockIdx.y * 32, nb = blockIdx.x * 32;
    int x = threadIdx.x & 31, y = threadIdx.x >> 5;
    #pragma unroll
    for (int i = 0; i < 32; i += 8)
        t[y + i][x] = W[(size_t)(kb + y + i) * N + nb + x];
    __syncthreads();
    #pragma unroll
    for (int i = 0; i < 32; i += 8) {
        float v = t[x][y + i];
        __nv_bfloat16 h = __float2bfloat16_rn(v);
        Whi[(size_t)(nb + y + i) * K + kb + x] = h;
        Wlo[(size_t)(nb + y + i) * K + kb + x] =
            __float2bfloat16_rn(v - __bfloat162float(h));
    }
}

// ---------------- rope cos/sin table ----------------------------------------
__global__ __launch_bounds__(128) void rope_table()
{
    int idx = blockIdx.x * 128 + threadIdx.x;    // T_*32
    int t = idx >> 5, j = idx & 31;
    const float LOG2_1E4 = 13.2877123795494f;
    float freq = exp2f(-(float)j * (LOG2_1E4 / 32.f));
    float s, c;
    sincosf((float)t * freq, &s, &c);
    g_RopC[idx] = c;
    g_RopS[idx] = s;
}

__device__ __forceinline__ float elu1(float x) {
    return (x > 0.f) ? (x + 1.f) : expf(x);
}

// ------- context[b,h] = sum_t rope_elu(k)(t) outer v(t); ksum too -----------
__global__ __launch_bounds__(256) void context_kernel()
{
    const int p  = blockIdx.y;
    const int b  = p >> 3;
    const int h  = p & 7;
    const int t0 = blockIdx.x * 256;

    __shared__ float Ks[32][64];
    __shared__ float Vs[32][64];

    const int tid = threadIdx.x;
    const int tx  = tid & 15;
    const int ty  = tid >> 4;
    const int kr_ = tid >> 3;          // 0..31
    const int kc4 = (tid & 7) * 4;     // 0..28

    float acc[4][4];
    #pragma unroll
    for (int i = 0; i < 4; ++i)
        #pragma unroll
        for (int j = 0; j < 4; ++j) acc[i][j] = 0.f;
    float ksm[4] = {0.f, 0.f, 0.f, 0.f};

    for (int tt = 0; tt < 256; tt += 32) {
        {
            int t = t0 + tt + kr_;
            size_t base = (size_t)(b * T_ + t) * 1024 + h * 128;
            float4 x1 = *(const float4*)(g_KV + base + kc4);
            float4 x2 = *(const float4*)(g_KV + base + 32 + kc4);
            float4 cs = *(const float4*)(g_RopC + t * 32 + kc4);
            float4 sn = *(const float4*)(g_RopS + t * 32 + kc4);
            Ks[kr_][kc4+0]    = elu1(x1.x*cs.x - x2.x*sn.x);
            Ks[kr_][kc4+1]    = elu1(x1.y*cs.y - x2.y*sn.y);
            Ks[kr_][kc4+2]    = elu1(x1.z*cs.z - x2.z*sn.z);
            Ks[kr_][kc4+3]    = elu1(x1.w*cs.w - x2.w*sn.w);
            Ks[kr_][kc4+32]   = elu1(x1.x*sn.x + x2.x*cs.x);
            Ks[kr_][kc4+33]   = elu1(x1.y*sn.y + x2.y*cs.y);
            Ks[kr_][kc4+34]   = elu1(x1.z*sn.z + x2.z*cs.z);
            Ks[kr_][kc4+35]   = elu1(x1.w*sn.w + x2.w*cs.w);
        }
        #pragma unroll
        for (int ii = 0; ii < 2; ++ii) {
            int i = tid + ii * 256;
            int r = i >> 4;
            int c = (i & 15) * 4;
            size_t base = (size_t)(b * T_ + t0 + tt + r) * 1024 + h * 128;
            *(float4*)&Vs[r][c] = *(const float4*)(g_KV + base + 64 + c);
        }
        __syncthreads();
        #pragma unroll 8
        for (int t = 0; t < 32; ++t) {
            float kr[4], vr[4];
            *(float4*)kr = *(const float4*)&Ks[t][ty*4];
            *(float4*)vr = *(const float4*)&Vs[t][tx*4];
            #pragma unroll
            for (int i = 0; i < 4; ++i)
                #pragma unroll
                for (int j = 0; j < 4; ++j)
                    acc[i][j] = fmaf(kr[i], vr[j], acc[i][j]);
            if (tx == 0) {
                #pragma unroll
                for (int i = 0; i < 4; ++i) ksm[i] += kr[i];
            }
        }
        __syncthreads();
    }

    float* ctx = g_Ctx + (size_t)p * HD * HD;
    #pragma unroll
    for (int i = 0; i < 4; ++i)
        #pragma unroll
        for (int j = 0; j < 4; ++j)
            atomicAdd(&ctx[(ty*4 + i) * HD + tx*4 + j], acc[i][j]);
    if (tx == 0) {
        #pragma unroll
        for (int i = 0; i < 4; ++i)
            atomicAdd(&g_Ksum[p * HD + ty*4 + i], ksm[i]);
    }
}

// ------- attn: out = (rope_elu(q) @ ctx) * z ; writes bf16 hi/lo ------------
__global__ __launch_bounds__(256) void attn_kernel()
{
    const int h  = blockIdx.y;
    const int r0 = blockIdx.x * 64;
    const int b  = r0 >> 12;
    const int p  = b * NH + h;

    __shared__ float Cs[64][64];
    __shared__ float Qs[64][65];
    __shared__ float ks[64];
    __shared__ float zs[64];

    const int tid = threadIdx.x;

    for (int i = tid; i < 64*64; i += 256)
        Cs[i >> 6][i & 63] = g_Ctx[(size_t)p * HD * HD + i];
    if (tid < 64) ks[tid] = g_Ksum[p * HD + tid];

    #pragma unroll
    for (int ii = 0; ii < 2; ++ii) {
        int i = tid + ii * 256;
        int r = i >> 3;
        int c4 = (i & 7) * 4;
        int t = (r0 + r) & (T_ - 1);
        size_t base = (size_t)(r0 + r) * DM + h * HD;
        float4 x1 = *(const float4*)(g_Q + base + c4);
        float4 x2 = *(const float4*)(g_Q + base + 32 + c4);
        float4 cs = *(const float4*)(g_RopC + t * 32 + c4);
        float4 sn = *(const float4*)(g_RopS + t * 32 + c4);
        Qs[r][c4+0]  = elu1(x1.x*cs.x - x2.x*sn.x);
        Qs[r][c4+1]  = elu1(x1.y*cs.y - x2.y*sn.y);
        Qs[r][c4+2]  = elu1(x1.z*cs.z - x2.z*sn.z);
        Qs[r][c4+3]  = elu1(x1.w*cs.w - x2.w*sn.w);
        Qs[r][c4+32] = elu1(x1.x*sn.x + x2.x*cs.x);
        Qs[r][c4+33] = elu1(x1.y*sn.y + x2.y*cs.y);
        Qs[r][c4+34] = elu1(x1.z*sn.z + x2.z*cs.z);
        Qs[r][c4+35] = elu1(x1.w*sn.w + x2.w*cs.w);
    }
    __syncthreads();

    if (tid < 64) {
        float dsum = 0.f;
        #pragma unroll
        for (int d = 0; d < 64; ++d) dsum += Qs[tid][d] * ks[d];
        zs[tid] = 1.f / (dsum + 1e-6f);
    }
    __syncthreads();

    const int tx = tid & 15;
    const int ty = tid >> 4;
    float acc[4][4];
    #pragma unroll
    for (int i = 0; i < 4; ++i)
        #pragma unroll
        for (int j = 0; j < 4; ++j) acc[i][j] = 0.f;

    #pragma unroll
    for (int d = 0; d < 64; ++d) {
        float4 cv = *(const float4*)&Cs[d][tx*4];
        float q0 = Qs[ty*4+0][d];
        float q1 = Qs[ty*4+1][d];
        float q2 = Qs[ty*4+2][d];
        float q3 = Qs[ty*4+3][d];
        acc[0][0] = fmaf(q0, cv.x, acc[0][0]); acc[0][1] = fmaf(q0, cv.y, acc[0][1]);
        acc[0][2] = fmaf(q0, cv.z, acc[0][2]); acc[0][3] = fmaf(q0, cv.w, acc[0][3]);
        acc[1][0] = fmaf(q1, cv.x, acc[1][0]); acc[1][1] = fmaf(q1, cv.y, acc[1][1]);
        acc[1][2] = fmaf(q1, cv.z, acc[1][2]); acc[1][3] = fmaf(q1, cv.w, acc[1][3]);
        acc[2][0] = fmaf(q2, cv.x, acc[2][0]); acc[2][1] = fmaf(q2, cv.y, acc[2][1]);
        acc[2][2] = fmaf(q2, cv.z, acc[2][2]); acc[2][3] = fmaf(q2, cv.w, acc[2][3]);
        acc[3][0] = fmaf(q3, cv.x, acc[3][0]); acc[3][1] = fmaf(q3, cv.y, acc[3][1]);
        acc[3][2] = fmaf(q3, cv.z, acc[3][2]); acc[3][3] = fmaf(q3, cv.w, acc[3][3]);
    }

    #pragma unroll
    for (int i = 0; i < 4; ++i) {
        int r = ty*4 + i;
        float z = zs[r];
        float v0 = acc[i][0]*z, v1 = acc[i][1]*z, v2 = acc[i][2]*z, v3 = acc[i][3]*z;
        size_t off = (size_t)(r0 + r) * DM + h * HD + tx*4;
        __nv_bfloat16 h0 = __float2bfloat16_rn(v0), h1 = __float2bfloat16_rn(v1);
        __nv_bfloat16 h2 = __float2bfloat16_rn(v2), h3 = __float2bfloat16_rn(v3);
        *(uint32_t*)(g_AtH + off)     = pack_bf2(h0, h1);
        *(uint32_t*)(g_AtH + off + 2) = pack_bf2(h2, h3);
        *(uint32_t*)(g_AtL + off) = pack_bf2(
            __float2bfloat16_rn(v0 - __bfloat162float(h0)),
            __float2bfloat16_rn(v1 - __bfloat162float(h1)));
        *(uint32_t*)(g_AtL + off + 2) = pack_bf2(
            __float2bfloat16_rn(v2 - __bfloat162float(h2)),
            __float2bfloat16_rn(v3 - __bfloat162float(h3)));
    }
}

// ---------------------------------------------------------------------------
extern "C" void kernel_launch(void* const* d_in, const int* in_sizes, int n_in,
                              void* d_out, int out_size)
{
    const float* x  = (const float*)d_in[0];
    const float* Wq = (const float*)d_in[1];
    const float* bq = (const float*)d_in[2];
    const float* Wd = (const float*)d_in[3];
    const float* bd = (const float*)d_in[4];
    const float* Wu = (const float*)d_in[5];
    const float* bu = (const float*)d_in[6];
    const float* Wo = (const float*)d_in[7];
    const float* bo = (const float*)d_in[8];
    float* out = (float*)d_out;

    float *pQ, *pKV, *pCtx, *pKsum;
    __nv_bfloat16 *pXh, *pXl, *pCh, *pCl, *pAh, *pAl;
    __nv_bfloat16 *pWqdH, *pWqdL, *pWuH, *pWuL, *pWoH, *pWoL;
    cudaGetSymbolAddress((void**)&pQ,    g_Q);
    cudaGetSymbolAddress((void**)&pKV,   g_KV);
    cudaGetSymbolAddress((void**)&pCtx,  g_Ctx);
    cudaGetSymbolAddress((void**)&pKsum, g_Ksum);
    cudaGetSymbolAddress((void**)&pXh,   g_Xhi);
    cudaGetSymbolAddress((void**)&pXl,   g_Xlo);
    cudaGetSymbolAddress((void**)&pCh,   g_Chi);
    cudaGetSymbolAddress((void**)&pCl,   g_Clo);
    cudaGetSymbolAddress((void**)&pAh,   g_AtH);
    cudaGetSymbolAddress((void**)&pAl,   g_AtL);
    cudaGetSymbolAddress((void**)&pWqdH, g_WqdH);
    cudaGetSymbolAddress((void**)&pWqdL, g_WqdL);
    cudaGetSymbolAddress((void**)&pWuH,  g_WuH);
    cudaGetSymbolAddress((void**)&pWuL,  g_WuL);
    cudaGetSymbolAddress((void**)&pWoH,  g_WoH);
    cudaGetSymbolAddress((void**)&pWoL,  g_WoL);

    cudaFuncSetAttribute(bgemm3, cudaFuncAttributeMaxDynamicSharedMemorySize, SMEMB);

    // weights: transpose + split. Wq rows [0,512), Wd rows [512,640) of Wqd.
    split_weightT<<<dim3(512/32, 512/32), 256>>>(Wq, pWqdH, pWqdL, 512, 512);
    split_weightT<<<dim3(128/32, 512/32), 256>>>(Wd, pWqdH + (size_t)512*512,
                                                 pWqdL + (size_t)512*512, 512, 128);
    split_weightT<<<dim3(1024/32, 128/32), 256>>>(Wu, pWuH, pWuL, 128, 1024);
    split_weightT<<<dim3(512/32, 512/32), 256>>>(Wo, pWoH, pWoL, 512, 512);
    // rope table
    rope_table<<<T_*32/128, 128>>>();
    // x split
    split_rows<<<(size_t)BT*512/4/256, 256>>>(x, pXh, pXl);

    // fused [Q | C] = x @ [Wq | Wd] + [bq | bd]   (Q fp32; C bf16 hi/lo)
    bgemm3<<<dim3(5, BT/128), 512, SMEMB>>>(pXh, pXl, pWqdH, pWqdL, bq, bd,
                                            pQ, pCh, pCl, 512, 128, 512);
    // KV = C @ Wu + bu (fp32)
    bgemm3<<<dim3(8, BT/128), 512, SMEMB>>>(pCh, pCl, pWuH, pWuL, bu, bu,
                                            pKV, nullptr, nullptr, 1024, 0, 128);

    // context (rope+elu on K fused into load)
    cudaMemsetAsync(pCtx,  0, sizeof(float) * B_*NH*HD*HD);
    cudaMemsetAsync(pKsum, 0, sizeof(float) * B_*NH*HD);
    context_kernel<<<dim3(T_/256, B_*NH), 256>>>();

    // attn (rope+elu on Q fused; writes bf16 hi/lo)
    attn_kernel<<<dim3(BT/64, NH), 256>>>();

    // out = Attn @ Wo + bo (fp32)
    bgemm3<<<dim3(4, BT/128), 512, SMEMB>>>(pAh, pAl, pWoH, pWoL, bo, bo,
                                            out, nullptr, nullptr, 512, 0, 512);
}

// round 8
// speedup vs baseline: 1.2332x; 1.2332x over previous
#include <cuda_runtime.h>
#include <cuda_fp16.h>
#include <math.h>
#include <stdint.h>

#define B_   8
#define T_   4096
#define BT   (B_*T_)          // 32768 rows
#define DM   512
#define NH   8
#define HD   64

#define PADH 40               // smem row stride in halves (80B; conflict-free)

// ---------------- scratch (static device globals; no allocation) ------------
__device__ float g_Q   [(size_t)BT * DM];      // Q fp32 (raw; roped in attn)
__device__ float g_KV  [(size_t)BT * 1024];    // kv raw fp32 (K roped in context)
__device__ float g_Ctx [B_*NH*HD*HD];
__device__ float g_Ksum[B_*NH*HD];
__device__ float g_RopC[T_*32];
__device__ float g_RopS[T_*32];

__device__ __half g_Xhi[(size_t)BT*DM],  g_Xlo[(size_t)BT*DM];
__device__ __half g_Chi[(size_t)BT*128], g_Clo[(size_t)BT*128];
__device__ __half g_AtH[(size_t)BT*DM],  g_AtL[(size_t)BT*DM];
__device__ __half g_WqH[512*512];
__device__ __half g_WdH[128*512];
__device__ __half g_WuH[1024*128];
__device__ __half g_WoH[512*512];

// ---------------- helpers ---------------------------------------------------
__device__ __forceinline__ uint32_t smem_u32(const void* p) {
    uint32_t a;
    asm("{ .reg .u64 t; cvta.to.shared.u64 t, %1; cvt.u32.u64 %0, t; }"
        : "=r"(a) : "l"(p));
    return a;
}
__device__ __forceinline__ void mma16816(float* d, const uint32_t* a, const uint32_t* b)
{
    asm volatile(
        "mma.sync.aligned.m16n8k16.row.col.f32.f16.f16.f32 "
        "{%0,%1,%2,%3}, {%4,%5,%6,%7}, {%8,%9}, {%0,%1,%2,%3};"
        : "+f"(d[0]), "+f"(d[1]), "+f"(d[2]), "+f"(d[3])
        : "r"(a[0]), "r"(a[1]), "r"(a[2]), "r"(a[3]), "r"(b[0]), "r"(b[1]));
}
__device__ __forceinline__ void ldsm_x4(uint32_t* r, uint32_t addr) {
    asm volatile("ldmatrix.sync.aligned.m8n8.x4.shared.b16 {%0,%1,%2,%3}, [%4];"
        : "=r"(r[0]), "=r"(r[1]), "=r"(r[2]), "=r"(r[3]) : "r"(addr));
}
__device__ __forceinline__ void ldsm_x2(uint32_t* r, uint32_t addr) {
    asm volatile("ldmatrix.sync.aligned.m8n8.x2.shared.b16 {%0,%1}, [%2];"
        : "=r"(r[0]), "=r"(r[1]) : "r"(addr));
}
__device__ __forceinline__ uint32_t pack_h2(__half a, __half b)
{
    __half2 p = __halves2half2(a, b);
    return *(uint32_t*)&p;
}

// ========== fp16 split-2 GEMM: D = (Ah+Al) @ Bh^T + bias ====================
// A split into fp16 hi/lo; B rounded once to fp16. 2 MMAs per term-pair.
// 128x128 tile, BK=32, 256 threads (8 warps 2x4), warp tile 64x32.
__global__ __launch_bounds__(256) void bgemm2(
    const __half* __restrict__ Ahi, const __half* __restrict__ Alo,
    const __half* __restrict__ Bh16,
    const float* __restrict__ bias,
    float* __restrict__ outF,
    __half* __restrict__ outHi, __half* __restrict__ outLo,
    int N, int K)
{
    __shared__ __half sAh[128*PADH];
    __shared__ __half sAl[128*PADH];
    __shared__ __half sBh[128*PADH];

    const int tid  = threadIdx.x;
    const int lane = tid & 31;
    const int wid  = tid >> 5;
    const int wm   = (wid >> 2) * 64;
    const int wn   = (wid & 3) * 32;
    const int g    = lane >> 2;
    const int t2   = (lane & 3) * 2;
    const int m0   = blockIdx.y * 128;
    const int n0   = blockIdx.x * 128;

    const int lrow = tid >> 2;           // 0..63
    const int lseg = tid & 3;            // 16B seg within 64B row

    const __half* gA0 = Ahi  + (size_t)(m0 + lrow) * K + lseg * 8;
    const __half* gA1 = Alo  + (size_t)(m0 + lrow) * K + lseg * 8;
    const __half* gB0 = Bh16 + (size_t)(n0 + lrow) * K + lseg * 8;
    const size_t rstep = (size_t)64 * K;

    const int a_row  = ((lane >> 3) & 1) * 8 + (lane & 7);
    const int a_col8 = (lane >> 4) * 8;
    const int b_row  = (lane & 7);
    const int b_col8 = ((lane >> 3) & 1) * 8;

    const uint32_t uAh = smem_u32(sAh);
    const uint32_t uAl = smem_u32(sAl);
    const uint32_t uBh = smem_u32(sBh);

    const uint32_t soff  = (uint32_t)(lrow * (PADH*2) + lseg * 16);
    const uint32_t soff2 = soff + (uint32_t)(64 * PADH * 2);

    const int nch = K >> 5;

    uint4 pA0[2], pA1[2], pB0[2];
    pA0[0] = *(const uint4*)gA0; pA0[1] = *(const uint4*)(gA0 + rstep);
    pA1[0] = *(const uint4*)gA1; pA1[1] = *(const uint4*)(gA1 + rstep);
    pB0[0] = *(const uint4*)gB0; pB0[1] = *(const uint4*)(gB0 + rstep);

    float acc[4][4][4];
    #pragma unroll
    for (int mt = 0; mt < 4; ++mt)
        #pragma unroll
        for (int nt = 0; nt < 4; ++nt)
            #pragma unroll
            for (int i = 0; i < 4; ++i) acc[mt][nt][i] = 0.f;

    for (int ch = 0; ch < nch; ++ch) {
        *(uint4*)((char*)sAh + soff)  = pA0[0];
        *(uint4*)((char*)sAh + soff2) = pA0[1];
        *(uint4*)((char*)sAl + soff)  = pA1[0];
        *(uint4*)((char*)sAl + soff2) = pA1[1];
        *(uint4*)((char*)sBh + soff)  = pB0[0];
        *(uint4*)((char*)sBh + soff2) = pB0[1];
        __syncthreads();

        if (ch + 1 < nch) {
            const int ko = (ch + 1) * 32;
            pA0[0] = *(const uint4*)(gA0 + ko); pA0[1] = *(const uint4*)(gA0 + rstep + ko);
            pA1[0] = *(const uint4*)(gA1 + ko); pA1[1] = *(const uint4*)(gA1 + rstep + ko);
            pB0[0] = *(const uint4*)(gB0 + ko); pB0[1] = *(const uint4*)(gB0 + rstep + ko);
        }

        #pragma unroll
        for (int ks = 0; ks < 2; ++ks) {
            const int k0 = ks * 16;
            uint32_t ah[4][4], al[4][4];
            #pragma unroll
            for (int mt = 0; mt < 4; ++mt) {
                uint32_t off = (uint32_t)(((wm + mt*16 + a_row) * PADH + k0 + a_col8) * 2);
                ldsm_x4(ah[mt], uAh + off);
                ldsm_x4(al[mt], uAl + off);
            }
            #pragma unroll
            for (int nt = 0; nt < 4; ++nt) {
                uint32_t boff = (uint32_t)(((wn + nt*8 + b_row) * PADH + k0 + b_col8) * 2);
                uint32_t bh[2];
                ldsm_x2(bh, uBh + boff);
                #pragma unroll
                for (int mt = 0; mt < 4; ++mt) {
                    mma16816(acc[mt][nt], ah[mt], bh);
                    mma16816(acc[mt][nt], al[mt], bh);
                }
            }
        }
        __syncthreads();
    }

    // epilogue
    #pragma unroll
    for (int mt = 0; mt < 4; ++mt) {
        int row = m0 + wm + mt * 16 + g;
        #pragma unroll
        for (int nt = 0; nt < 4; ++nt) {
            int col = n0 + wn + nt * 8 + t2;
            float b0 = bias[col], b1 = bias[col + 1];
            float v00 = acc[mt][nt][0] + b0, v01 = acc[mt][nt][1] + b1;
            float v10 = acc[mt][nt][2] + b0, v11 = acc[mt][nt][3] + b1;
            if (outF) {
                *(float2*)(outF + (size_t)row * N + col)       = make_float2(v00, v01);
                *(float2*)(outF + (size_t)(row + 8) * N + col) = make_float2(v10, v11);
            } else {
                __half h00 = __float2half_rn(v00);
                __half h01 = __float2half_rn(v01);
                __half h10 = __float2half_rn(v10);
                __half h11 = __float2half_rn(v11);
                *(uint32_t*)(outHi + (size_t)row * N + col)       = pack_h2(h00, h01);
                *(uint32_t*)(outHi + (size_t)(row + 8) * N + col) = pack_h2(h10, h11);
                *(uint32_t*)(outLo + (size_t)row * N + col) = pack_h2(
                    __float2half_rn(v00 - __half2float(h00)),
                    __float2half_rn(v01 - __half2float(h01)));
                *(uint32_t*)(outLo + (size_t)(row + 8) * N + col) = pack_h2(
                    __float2half_rn(v10 - __half2float(h10)),
                    __float2half_rn(v11 - __half2float(h11)));
            }
        }
    }
}

// ---------------- split fp32 -> fp16 hi/lo (no transpose) -------------------
__global__ __launch_bounds__(256) void split_rows(
    const float* __restrict__ X, __half* __restrict__ Hi,
    __half* __restrict__ Lo)
{
    size_t e0 = ((size_t)blockIdx.x * 256 + threadIdx.x) * 4;
    float4 v = *(const float4*)(X + e0);
    __half h0 = __float2half_rn(v.x), h1 = __float2half_rn(v.y);
    __half h2 = __float2half_rn(v.z), h3 = __float2half_rn(v.w);
    uint2 hh = make_uint2(pack_h2(h0, h1), pack_h2(h2, h3));
    uint2 ll = make_uint2(
        pack_h2(__float2half_rn(v.x - __half2float(h0)),
                __float2half_rn(v.y - __half2float(h1))),
        pack_h2(__float2half_rn(v.z - __half2float(h2)),
                __float2half_rn(v.w - __half2float(h3))));
    *(uint2*)(Hi + e0) = hh;
    *(uint2*)(Lo + e0) = ll;
}

// ------- weight transpose + round: W[K,N] -> Wt[N,K] fp16 -------------------
__global__ __launch_bounds__(256) void round_weightT(
    const float* __restrict__ W, __half* __restrict__ Wh, int K, int N)
{
    __shared__ float t[32][33];
    int kb = blockIdx.y * 32, nb = blockIdx.x * 32;
    int x = threadIdx.x & 31, y = threadIdx.x >> 5;
    #pragma unroll
    for (int i = 0; i < 32; i += 8)
        t[y + i][x] = W[(size_t)(kb + y + i) * N + nb + x];
    __syncthreads();
    #pragma unroll
    for (int i = 0; i < 32; i += 8)
        Wh[(size_t)(nb + y + i) * K + kb + x] = __float2half_rn(t[x][y + i]);
}

// ---------------- rope cos/sin table ----------------------------------------
__global__ __launch_bounds__(128) void rope_table()
{
    int idx = blockIdx.x * 128 + threadIdx.x;    // T_*32
    int t = idx >> 5, j = idx & 31;
    const float LOG2_1E4 = 13.2877123795494f;
    float freq = exp2f(-(float)j * (LOG2_1E4 / 32.f));
    float s, c;
    sincosf((float)t * freq, &s, &c);
    g_RopC[idx] = c;
    g_RopS[idx] = s;
}

__device__ __forceinline__ float elu1(float x) {
    return (x > 0.f) ? (x + 1.f) : expf(x);
}

// ------- context[b,h] = sum_t rope_elu(k)(t) outer v(t); ksum too -----------
__global__ __launch_bounds__(256) void context_kernel()
{
    const int p  = blockIdx.y;
    const int b  = p >> 3;
    const int h  = p & 7;
    const int t0 = blockIdx.x * 256;

    __shared__ float Ks[32][64];
    __shared__ float Vs[32][64];

    const int tid = threadIdx.x;
    const int tx  = tid & 15;
    const int ty  = tid >> 4;
    const int kr_ = tid >> 3;          // 0..31
    const int kc4 = (tid & 7) * 4;     // 0..28

    float acc[4][4];
    #pragma unroll
    for (int i = 0; i < 4; ++i)
        #pragma unroll
        for (int j = 0; j < 4; ++j) acc[i][j] = 0.f;
    float ksm[4] = {0.f, 0.f, 0.f, 0.f};

    for (int tt = 0; tt < 256; tt += 32) {
        {
            int t = t0 + tt + kr_;
            size_t base = (size_t)(b * T_ + t) * 1024 + h * 128;
            float4 x1 = *(const float4*)(g_KV + base + kc4);
            float4 x2 = *(const float4*)(g_KV + base + 32 + kc4);
            float4 cs = *(const float4*)(g_RopC + t * 32 + kc4);
            float4 sn = *(const float4*)(g_RopS + t * 32 + kc4);
            Ks[kr_][kc4+0]    = elu1(x1.x*cs.x - x2.x*sn.x);
            Ks[kr_][kc4+1]    = elu1(x1.y*cs.y - x2.y*sn.y);
            Ks[kr_][kc4+2]    = elu1(x1.z*cs.z - x2.z*sn.z);
            Ks[kr_][kc4+3]    = elu1(x1.w*cs.w - x2.w*sn.w);
            Ks[kr_][kc4+32]   = elu1(x1.x*sn.x + x2.x*cs.x);
            Ks[kr_][kc4+33]   = elu1(x1.y*sn.y + x2.y*cs.y);
            Ks[kr_][kc4+34]   = elu1(x1.z*sn.z + x2.z*cs.z);
            Ks[kr_][kc4+35]   = elu1(x1.w*sn.w + x2.w*cs.w);
        }
        #pragma unroll
        for (int ii = 0; ii < 2; ++ii) {
            int i = tid + ii * 256;
            int r = i >> 4;
            int c = (i & 15) * 4;
            size_t base = (size_t)(b * T_ + t0 + tt + r) * 1024 + h * 128;
            *(float4*)&Vs[r][c] = *(const float4*)(g_KV + base + 64 + c);
        }
        __syncthreads();
        #pragma unroll 8
        for (int t = 0; t < 32; ++t) {
            float kr[4], vr[4];
            *(float4*)kr = *(const float4*)&Ks[t][ty*4];
            *(float4*)vr = *(const float4*)&Vs[t][tx*4];
            #pragma unroll
            for (int i = 0; i < 4; ++i)
                #pragma unroll
                for (int j = 0; j < 4; ++j)
                    acc[i][j] = fmaf(kr[i], vr[j], acc[i][j]);
            if (tx == 0) {
                #pragma unroll
                for (int i = 0; i < 4; ++i) ksm[i] += kr[i];
            }
        }
        __syncthreads();
    }

    float* ctx = g_Ctx + (size_t)p * HD * HD;
    #pragma unroll
    for (int i = 0; i < 4; ++i)
        #pragma unroll
        for (int j = 0; j < 4; ++j)
            atomicAdd(&ctx[(ty*4 + i) * HD + tx*4 + j], acc[i][j]);
    if (tx == 0) {
        #pragma unroll
        for (int i = 0; i < 4; ++i)
            atomicAdd(&g_Ksum[p * HD + ty*4 + i], ksm[i]);
    }
}

// ------- attn: out = (rope_elu(q) @ ctx) * z ; writes fp16 hi/lo ------------
__global__ __launch_bounds__(256) void attn_kernel()
{
    const int h  = blockIdx.y;
    const int r0 = blockIdx.x * 64;
    const int b  = r0 >> 12;
    const int p  = b * NH + h;

    __shared__ float Cs[64][64];
    __shared__ float Qs[64][65];
    __shared__ float ks[64];
    __shared__ float zs[64];

    const int tid = threadIdx.x;

    for (int i = tid; i < 64*64; i += 256)
        Cs[i >> 6][i & 63] = g_Ctx[(size_t)p * HD * HD + i];
    if (tid < 64) ks[tid] = g_Ksum[p * HD + tid];

    #pragma unroll
    for (int ii = 0; ii < 2; ++ii) {
        int i = tid + ii * 256;
        int r = i >> 3;
        int c4 = (i & 7) * 4;
        int t = (r0 + r) & (T_ - 1);
        size_t base = (size_t)(r0 + r) * DM + h * HD;
        float4 x1 = *(const float4*)(g_Q + base + c4);
        float4 x2 = *(const float4*)(g_Q + base + 32 + c4);
        float4 cs = *(const float4*)(g_RopC + t * 32 + c4);
        float4 sn = *(const float4*)(g_RopS + t * 32 + c4);
        Qs[r][c4+0]  = elu1(x1.x*cs.x - x2.x*sn.x);
        Qs[r][c4+1]  = elu1(x1.y*cs.y - x2.y*sn.y);
        Qs[r][c4+2]  = elu1(x1.z*cs.z - x2.z*sn.z);
        Qs[r][c4+3]  = elu1(x1.w*cs.w - x2.w*sn.w);
        Qs[r][c4+32] = elu1(x1.x*sn.x + x2.x*cs.x);
        Qs[r][c4+33] = elu1(x1.y*sn.y + x2.y*cs.y);
        Qs[r][c4+34] = elu1(x1.z*sn.z + x2.z*cs.z);
        Qs[r][c4+35] = elu1(x1.w*sn.w + x2.w*cs.w);
    }
    __syncthreads();

    if (tid < 64) {
        float dsum = 0.f;
        #pragma unroll
        for (int d = 0; d < 64; ++d) dsum += Qs[tid][d] * ks[d];
        zs[tid] = 1.f / (dsum + 1e-6f);
    }
    __syncthreads();

    const int tx = tid & 15;
    const int ty = tid >> 4;
    float acc[4][4];
    #pragma unroll
    for (int i = 0; i < 4; ++i)
        #pragma unroll
        for (int j = 0; j < 4; ++j) acc[i][j] = 0.f;

    #pragma unroll
    for (int d = 0; d < 64; ++d) {
        float4 cv = *(const float4*)&Cs[d][tx*4];
        float q0 = Qs[ty*4+0][d];
        float q1 = Qs[ty*4+1][d];
        float q2 = Qs[ty*4+2][d];
        float q3 = Qs[ty*4+3][d];
        acc[0][0] = fmaf(q0, cv.x, acc[0][0]); acc[0][1] = fmaf(q0, cv.y, acc[0][1]);
        acc[0][2] = fmaf(q0, cv.z, acc[0][2]); acc[0][3] = fmaf(q0, cv.w, acc[0][3]);
        acc[1][0] = fmaf(q1, cv.x, acc[1][0]); acc[1][1] = fmaf(q1, cv.y, acc[1][1]);
        acc[1][2] = fmaf(q1, cv.z, acc[1][2]); acc[1][3] = fmaf(q1, cv.w, acc[1][3]);
        acc[2][0] = fmaf(q2, cv.x, acc[2][0]); acc[2][1] = fmaf(q2, cv.y, acc[2][1]);
        acc[2][2] = fmaf(q2, cv.z, acc[2][2]); acc[2][3] = fmaf(q2, cv.w, acc[2][3]);
        acc[3][0] = fmaf(q3, cv.x, acc[3][0]); acc[3][1] = fmaf(q3, cv.y, acc[3][1]);
        acc[3][2] = fmaf(q3, cv.z, acc[3][2]); acc[3][3] = fmaf(q3, cv.w, acc[3][3]);
    }

    #pragma unroll
    for (int i = 0; i < 4; ++i) {
        int r = ty*4 + i;
        float z = zs[r];
        float v0 = acc[i][0]*z, v1 = acc[i][1]*z, v2 = acc[i][2]*z, v3 = acc[i][3]*z;
        size_t off = (size_t)(r0 + r) * DM + h * HD + tx*4;
        __half h0 = __float2half_rn(v0), h1 = __float2half_rn(v1);
        __half h2 = __float2half_rn(v2), h3 = __float2half_rn(v3);
        *(uint32_t*)(g_AtH + off)     = pack_h2(h0, h1);
        *(uint32_t*)(g_AtH + off + 2) = pack_h2(h2, h3);
        *(uint32_t*)(g_AtL + off) = pack_h2(
            __float2half_rn(v0 - __half2float(h0)),
            __float2half_rn(v1 - __half2float(h1)));
        *(uint32_t*)(g_AtL + off + 2) = pack_h2(
            __float2half_rn(v2 - __half2float(h2)),
            __float2half_rn(v3 - __half2float(h3)));
    }
}

// ---------------------------------------------------------------------------
extern "C" void kernel_launch(void* const* d_in, const int* in_sizes, int n_in,
                              void* d_out, int out_size)
{
    const float* x  = (const float*)d_in[0];
    const float* Wq = (const float*)d_in[1];
    const float* bq = (const float*)d_in[2];
    const float* Wd = (const float*)d_in[3];
    const float* bd = (const float*)d_in[4];
    const float* Wu = (const float*)d_in[5];
    const float* bu = (const float*)d_in[6];
    const float* Wo = (const float*)d_in[7];
    const float* bo = (const float*)d_in[8];
    float* out = (float*)d_out;

    float *pQ, *pKV, *pCtx, *pKsum;
    __half *pXh, *pXl, *pCh, *pCl, *pAh, *pAl;
    __half *pWqH, *pWdH, *pWuH, *pWoH;
    cudaGetSymbolAddress((void**)&pQ,    g_Q);
    cudaGetSymbolAddress((void**)&pKV,   g_KV);
    cudaGetSymbolAddress((void**)&pCtx,  g_Ctx);
    cudaGetSymbolAddress((void**)&pKsum, g_Ksum);
    cudaGetSymbolAddress((void**)&pXh,   g_Xhi);
    cudaGetSymbolAddress((void**)&pXl,   g_Xlo);
    cudaGetSymbolAddress((void**)&pCh,   g_Chi);
    cudaGetSymbolAddress((void**)&pCl,   g_Clo);
    cudaGetSymbolAddress((void**)&pAh,   g_AtH);
    cudaGetSymbolAddress((void**)&pAl,   g_AtL);
    cudaGetSymbolAddress((void**)&pWqH,  g_WqH);
    cudaGetSymbolAddress((void**)&pWdH,  g_WdH);
    cudaGetSymbolAddress((void**)&pWuH,  g_WuH);
    cudaGetSymbolAddress((void**)&pWoH,  g_WoH);

    static bool init = false;
    static cudaStream_t s1;
    static cudaEvent_t evFork, evQ;
    if (!init) {
        cudaStreamCreateWithFlags(&s1, cudaStreamNonBlocking);
        cudaEventCreateWithFlags(&evFork, cudaEventDisableTiming);
        cudaEventCreateWithFlags(&evQ,   cudaEventDisableTiming);
        init = true;
    }

    // --- preprocessing (default stream) ---
    cudaMemsetAsync(pCtx,  0, sizeof(float) * B_*NH*HD*HD);
    cudaMemsetAsync(pKsum, 0, sizeof(float) * B_*NH*HD);
    round_weightT<<<dim3(512/32, 512/32), 256>>>(Wq, pWqH, 512, 512);
    round_weightT<<<dim3(128/32, 512/32), 256>>>(Wd, pWdH, 512, 128);
    round_weightT<<<dim3(1024/32, 128/32), 256>>>(Wu, pWuH, 128, 1024);
    round_weightT<<<dim3(512/32, 512/32), 256>>>(Wo, pWoH, 512, 512);
    rope_table<<<T_*32/128, 128>>>();
    split_rows<<<(size_t)BT*512/4/256, 256>>>(x, pXh, pXl);

    // --- fork: Q GEMM on side stream, concurrent with C->KV->context --------
    cudaEventRecord(evFork, 0);
    cudaStreamWaitEvent(s1, evFork, 0);
    bgemm2<<<dim3(4, BT/128), 256, 0, s1>>>(pXh, pXl, pWqH, bq,
                                            pQ, nullptr, nullptr, 512, 512);
    cudaEventRecord(evQ, s1);

    // C = x @ Wd + bd (fp16 hi/lo out)
    bgemm2<<<dim3(1, BT/128), 256>>>(pXh, pXl, pWdH, bd,
                                     nullptr, pCh, pCl, 128, 512);
    // KV = C @ Wu + bu (fp32 out)
    bgemm2<<<dim3(8, BT/128), 256>>>(pCh, pCl, pWuH, bu,
                                     pKV, nullptr, nullptr, 1024, 128);
    // context (rope+elu on K fused)
    context_kernel<<<dim3(T_/256, B_*NH), 256>>>();

    // --- join: attn needs Q and context --------------------------------------
    cudaStreamWaitEvent(0, evQ, 0);
    attn_kernel<<<dim3(BT/64, NH), 256>>>();

    // out = Attn @ Wo + bo (fp32 out)
    bgemm2<<<dim3(4, BT/128), 256>>>(pAh, pAl, pWoH, bo,
                                     out, nullptr, nullptr, 512, 512);
}

// round 9
// speedup vs baseline: 1.3639x; 1.1060x over previous
#include <cuda_runtime.h>
#include <cuda_fp16.h>
#include <math.h>
#include <stdint.h>

#define B_   8
#define T_   4096
#define BT   (B_*T_)          // 32768 rows
#define DM   512
#define NH   8
#define HD   64

#define PADH 40               // smem row stride in halves (80B; conflict-free)
#define ZSCALE     16384.0f   // 2^14: keeps z*q' and M/S in fp16-normal range
#define INV_ZSCALE (1.0f/16384.0f)

// ---------------- scratch (static device globals; no allocation) ------------
__device__ float  g_Q   [(size_t)BT * DM];     // Q fp32 (raw; roped in qprep)
__device__ __half g_KV  [(size_t)BT * 1024];   // kv fp16 (rounded once)
__device__ float  g_Ctx [B_*NH*HD*HD];
__device__ float  g_Ksum[B_*NH*HD];
__device__ float  g_RopC[T_*32];
__device__ float  g_RopS[T_*32];

__device__ __half g_Xhi[(size_t)BT*DM],  g_Xlo[(size_t)BT*DM];
__device__ __half g_Chi[(size_t)BT*128], g_Clo[(size_t)BT*128];
__device__ __half g_QsH[(size_t)BT*DM],  g_QsL[(size_t)BT*DM];  // z-scaled q'
__device__ __half g_M  [(size_t)B_*512*512];                    // per-batch Ctx@Wo / S
__device__ __half g_WqH[512*512];
__device__ __half g_WdH[128*512];
__device__ __half g_WuH[1024*128];

// ---------------- helpers ---------------------------------------------------
__device__ __forceinline__ uint32_t smem_u32(const void* p) {
    uint32_t a;
    asm("{ .reg .u64 t; cvta.to.shared.u64 t, %1; cvt.u32.u64 %0, t; }"
        : "=r"(a) : "l"(p));
    return a;
}
__device__ __forceinline__ void mma16816(float* d, const uint32_t* a, const uint32_t* b)
{
    asm volatile(
        "mma.sync.aligned.m16n8k16.row.col.f32.f16.f16.f32 "
        "{%0,%1,%2,%3}, {%4,%5,%6,%7}, {%8,%9}, {%0,%1,%2,%3};"
        : "+f"(d[0]), "+f"(d[1]), "+f"(d[2]), "+f"(d[3])
        : "r"(a[0]), "r"(a[1]), "r"(a[2]), "r"(a[3]), "r"(b[0]), "r"(b[1]));
}
__device__ __forceinline__ void ldsm_x4(uint32_t* r, uint32_t addr) {
    asm volatile("ldmatrix.sync.aligned.m8n8.x4.shared.b16 {%0,%1,%2,%3}, [%4];"
        : "=r"(r[0]), "=r"(r[1]), "=r"(r[2]), "=r"(r[3]) : "r"(addr));
}
__device__ __forceinline__ void ldsm_x2(uint32_t* r, uint32_t addr) {
    asm volatile("ldmatrix.sync.aligned.m8n8.x2.shared.b16 {%0,%1}, [%2];"
        : "=r"(r[0]), "=r"(r[1]) : "r"(addr));
}
__device__ __forceinline__ uint32_t pack_h2(__half a, __half b)
{
    __half2 p = __halves2half2(a, b);
    return *(uint32_t*)&p;
}
// load 4 consecutive halves -> 4 floats
__device__ __forceinline__ void ld4h(const __half* p, float* o)
{
    uint2 u = *(const uint2*)p;
    const __half2* h = (const __half2*)&u;
    float2 a = __half22float2(h[0]);
    float2 b = __half22float2(h[1]);
    o[0] = a.x; o[1] = a.y; o[2] = b.x; o[3] = b.y;
}

// ========== fp16 split-2 GEMM: D = (Ah+Al) @ Bh^T + bias ====================
// 128x128 tile, BK=32, 256 threads (8 warps 2x4), warp tile 64x32.
// Output modes: outF -> fp32; else outLo -> fp16 hi/lo; else outHi fp16 single.
// bStride: per-batch B stride (batch = m0>>12), 0 for shared B.
__global__ __launch_bounds__(256) void bgemm2(
    const __half* __restrict__ Ahi, const __half* __restrict__ Alo,
    const __half* __restrict__ Bh16,
    const float* __restrict__ bias,
    float* __restrict__ outF,
    __half* __restrict__ outHi, __half* __restrict__ outLo,
    int N, int K, int bStride)
{
    __shared__ __half sAh[128*PADH];
    __shared__ __half sAl[128*PADH];
    __shared__ __half sBh[128*PADH];

    const int tid  = threadIdx.x;
    const int lane = tid & 31;
    const int wid  = tid >> 5;
    const int wm   = (wid >> 2) * 64;
    const int wn   = (wid & 3) * 32;
    const int g    = lane >> 2;
    const int t2   = (lane & 3) * 2;
    const int m0   = blockIdx.y * 128;
    const int n0   = blockIdx.x * 128;

    const int lrow = tid >> 2;           // 0..63
    const int lseg = tid & 3;            // 16B seg within 64B row

    const __half* gA0 = Ahi  + (size_t)(m0 + lrow) * K + lseg * 8;
    const __half* gA1 = Alo  + (size_t)(m0 + lrow) * K + lseg * 8;
    const __half* gB0 = Bh16 + (size_t)(m0 >> 12) * bStride
                             + (size_t)(n0 + lrow) * K + lseg * 8;
    const size_t rstep = (size_t)64 * K;

    const int a_row  = ((lane >> 3) & 1) * 8 + (lane & 7);
    const int a_col8 = (lane >> 4) * 8;
    const int b_row  = (lane & 7);
    const int b_col8 = ((lane >> 3) & 1) * 8;

    const uint32_t uAh = smem_u32(sAh);
    const uint32_t uAl = smem_u32(sAl);
    const uint32_t uBh = smem_u32(sBh);

    const uint32_t soff  = (uint32_t)(lrow * (PADH*2) + lseg * 16);
    const uint32_t soff2 = soff + (uint32_t)(64 * PADH * 2);

    const int nch = K >> 5;

    uint4 pA0[2], pA1[2], pB0[2];
    pA0[0] = *(const uint4*)gA0; pA0[1] = *(const uint4*)(gA0 + rstep);
    pA1[0] = *(const uint4*)gA1; pA1[1] = *(const uint4*)(gA1 + rstep);
    pB0[0] = *(const uint4*)gB0; pB0[1] = *(const uint4*)(gB0 + rstep);

    float acc[4][4][4];
    #pragma unroll
    for (int mt = 0; mt < 4; ++mt)
        #pragma unroll
        for (int nt = 0; nt < 4; ++nt)
            #pragma unroll
            for (int i = 0; i < 4; ++i) acc[mt][nt][i] = 0.f;

    for (int ch = 0; ch < nch; ++ch) {
        *(uint4*)((char*)sAh + soff)  = pA0[0];
        *(uint4*)((char*)sAh + soff2) = pA0[1];
        *(uint4*)((char*)sAl + soff)  = pA1[0];
        *(uint4*)((char*)sAl + soff2) = pA1[1];
        *(uint4*)((char*)sBh + soff)  = pB0[0];
        *(uint4*)((char*)sBh + soff2) = pB0[1];
        __syncthreads();

        if (ch + 1 < nch) {
            const int ko = (ch + 1) * 32;
            pA0[0] = *(const uint4*)(gA0 + ko); pA0[1] = *(const uint4*)(gA0 + rstep + ko);
            pA1[0] = *(const uint4*)(gA1 + ko); pA1[1] = *(const uint4*)(gA1 + rstep + ko);
            pB0[0] = *(const uint4*)(gB0 + ko); pB0[1] = *(const uint4*)(gB0 + rstep + ko);
        }

        #pragma unroll
        for (int ks = 0; ks < 2; ++ks) {
            const int k0 = ks * 16;
            uint32_t ah[4][4], al[4][4];
            #pragma unroll
            for (int mt = 0; mt < 4; ++mt) {
                uint32_t off = (uint32_t)(((wm + mt*16 + a_row) * PADH + k0 + a_col8) * 2);
                ldsm_x4(ah[mt], uAh + off);
                ldsm_x4(al[mt], uAl + off);
            }
            #pragma unroll
            for (int nt = 0; nt < 4; ++nt) {
                uint32_t boff = (uint32_t)(((wn + nt*8 + b_row) * PADH + k0 + b_col8) * 2);
                uint32_t bh[2];
                ldsm_x2(bh, uBh + boff);
                #pragma unroll
                for (int mt = 0; mt < 4; ++mt) {
                    mma16816(acc[mt][nt], ah[mt], bh);
                    mma16816(acc[mt][nt], al[mt], bh);
                }
            }
        }
        __syncthreads();
    }

    // epilogue
    #pragma unroll
    for (int mt = 0; mt < 4; ++mt) {
        int row = m0 + wm + mt * 16 + g;
        #pragma unroll
        for (int nt = 0; nt < 4; ++nt) {
            int col = n0 + wn + nt * 8 + t2;
            float b0 = bias[col], b1 = bias[col + 1];
            float v00 = acc[mt][nt][0] + b0, v01 = acc[mt][nt][1] + b1;
            float v10 = acc[mt][nt][2] + b0, v11 = acc[mt][nt][3] + b1;
            if (outF) {
                *(float2*)(outF + (size_t)row * N + col)       = make_float2(v00, v01);
                *(float2*)(outF + (size_t)(row + 8) * N + col) = make_float2(v10, v11);
            } else if (outLo) {
                __half h00 = __float2half_rn(v00);
                __half h01 = __float2half_rn(v01);
                __half h10 = __float2half_rn(v10);
                __half h11 = __float2half_rn(v11);
                *(uint32_t*)(outHi + (size_t)row * N + col)       = pack_h2(h00, h01);
                *(uint32_t*)(outHi + (size_t)(row + 8) * N + col) = pack_h2(h10, h11);
                *(uint32_t*)(outLo + (size_t)row * N + col) = pack_h2(
                    __float2half_rn(v00 - __half2float(h00)),
                    __float2half_rn(v01 - __half2float(h01)));
                *(uint32_t*)(outLo + (size_t)(row + 8) * N + col) = pack_h2(
                    __float2half_rn(v10 - __half2float(h10)),
                    __float2half_rn(v11 - __half2float(h11)));
            } else {
                *(uint32_t*)(outHi + (size_t)row * N + col) =
                    pack_h2(__float2half_rn(v00), __float2half_rn(v01));
                *(uint32_t*)(outHi + (size_t)(row + 8) * N + col) =
                    pack_h2(__float2half_rn(v10), __float2half_rn(v11));
            }
        }
    }
}

// ---------------- split fp32 -> fp16 hi/lo (no transpose) -------------------
__global__ __launch_bounds__(256) void split_rows(
    const float* __restrict__ X, __half* __restrict__ Hi,
    __half* __restrict__ Lo)
{
    size_t e0 = ((size_t)blockIdx.x * 256 + threadIdx.x) * 4;
    float4 v = *(const float4*)(X + e0);
    __half h0 = __float2half_rn(v.x), h1 = __float2half_rn(v.y);
    __half h2 = __float2half_rn(v.z), h3 = __float2half_rn(v.w);
    uint2 hh = make_uint2(pack_h2(h0, h1), pack_h2(h2, h3));
    uint2 ll = make_uint2(
        pack_h2(__float2half_rn(v.x - __half2float(h0)),
                __float2half_rn(v.y - __half2float(h1))),
        pack_h2(__float2half_rn(v.z - __half2float(h2)),
                __float2half_rn(v.w - __half2float(h3))));
    *(uint2*)(Hi + e0) = hh;
    *(uint2*)(Lo + e0) = ll;
}

// ------- weight transpose + round: W[K,N] -> Wt[N,K] fp16 -------------------
__global__ __launch_bounds__(256) void round_weightT(
    const float* __restrict__ W, __half* __restrict__ Wh, int K, int N)
{
    __shared__ float t[32][33];
    int kb = blockIdx.y * 32, nb = blockIdx.x * 32;
    int x = threadIdx.x & 31, y = threadIdx.x >> 5;
    #pragma unroll
    for (int i = 0; i < 32; i += 8)
        t[y + i][x] = W[(size_t)(kb + y + i) * N + nb + x];
    __syncthreads();
    #pragma unroll
    for (int i = 0; i < 32; i += 8)
        Wh[(size_t)(nb + y + i) * K + kb + x] = __float2half_rn(t[x][y + i]);
}

// ---------------- rope cos/sin table ----------------------------------------
__global__ __launch_bounds__(128) void rope_table()
{
    int idx = blockIdx.x * 128 + threadIdx.x;    // T_*32
    int t = idx >> 5, j = idx & 31;
    const float LOG2_1E4 = 13.2877123795494f;
    float freq = exp2f(-(float)j * (LOG2_1E4 / 32.f));
    float s, c;
    sincosf((float)t * freq, &s, &c);
    g_RopC[idx] = c;
    g_RopS[idx] = s;
}

__device__ __forceinline__ float elu1(float x) {
    return (x > 0.f) ? (x + 1.f) : expf(x);
}

// ------- context[b,h] = sum_t rope_elu(k)(t) outer v(t); ksum too -----------
__global__ __launch_bounds__(256) void context_kernel()
{
    const int p  = blockIdx.y;
    const int b  = p >> 3;
    const int h  = p & 7;
    const int t0 = blockIdx.x * 256;

    __shared__ float Ks[32][64];
    __shared__ float Vs[32][64];

    const int tid = threadIdx.x;
    const int tx  = tid & 15;
    const int ty  = tid >> 4;
    const int kr_ = tid >> 3;          // 0..31
    const int kc4 = (tid & 7) * 4;     // 0..28

    float acc[4][4];
    #pragma unroll
    for (int i = 0; i < 4; ++i)
        #pragma unroll
        for (int j = 0; j < 4; ++j) acc[i][j] = 0.f;
    float ksm[4] = {0.f, 0.f, 0.f, 0.f};

    for (int tt = 0; tt < 256; tt += 32) {
        {
            int t = t0 + tt + kr_;
            const __half* kp = g_KV + (size_t)(b * T_ + t) * 1024 + h * 128;
            float x1[4], x2[4];
            ld4h(kp + kc4, x1);
            ld4h(kp + 32 + kc4, x2);
            float4 cs = *(const float4*)(g_RopC + t * 32 + kc4);
            float4 sn = *(const float4*)(g_RopS + t * 32 + kc4);
            Ks[kr_][kc4+0]    = elu1(x1[0]*cs.x - x2[0]*sn.x);
            Ks[kr_][kc4+1]    = elu1(x1[1]*cs.y - x2[1]*sn.y);
            Ks[kr_][kc4+2]    = elu1(x1[2]*cs.z - x2[2]*sn.z);
            Ks[kr_][kc4+3]    = elu1(x1[3]*cs.w - x2[3]*sn.w);
            Ks[kr_][kc4+32]   = elu1(x1[0]*sn.x + x2[0]*cs.x);
            Ks[kr_][kc4+33]   = elu1(x1[1]*sn.y + x2[1]*cs.y);
            Ks[kr_][kc4+34]   = elu1(x1[2]*sn.z + x2[2]*cs.z);
            Ks[kr_][kc4+35]   = elu1(x1[3]*sn.w + x2[3]*cs.w);
        }
        #pragma unroll
        for (int ii = 0; ii < 2; ++ii) {
            int i = tid + ii * 256;
            int r = i >> 4;
            int c = (i & 15) * 4;
            const __half* vp = g_KV + (size_t)(b * T_ + t0 + tt + r) * 1024 + h * 128 + 64;
            float vv[4];
            ld4h(vp + c, vv);
            Vs[r][c]   = vv[0]; Vs[r][c+1] = vv[1];
            Vs[r][c+2] = vv[2]; Vs[r][c+3] = vv[3];
        }
        __syncthreads();
        #pragma unroll 8
        for (int t = 0; t < 32; ++t) {
            float kr[4], vr[4];
            *(float4*)kr = *(const float4*)&Ks[t][ty*4];
            *(float4*)vr = *(const float4*)&Vs[t][tx*4];
            #pragma unroll
            for (int i = 0; i < 4; ++i)
                #pragma unroll
                for (int j = 0; j < 4; ++j)
                    acc[i][j] = fmaf(kr[i], vr[j], acc[i][j]);
            if (tx == 0) {
                #pragma unroll
                for (int i = 0; i < 4; ++i) ksm[i] += kr[i];
            }
        }
        __syncthreads();
    }

    float* ctx = g_Ctx + (size_t)p * HD * HD;
    #pragma unroll
    for (int i = 0; i < 4; ++i)
        #pragma unroll
        for (int j = 0; j < 4; ++j)
            atomicAdd(&ctx[(ty*4 + i) * HD + tx*4 + j], acc[i][j]);
    if (tx == 0) {
        #pragma unroll
        for (int i = 0; i < 4; ++i)
            atomicAdd(&g_Ksum[p * HD + ty*4 + i], ksm[i]);
    }
}

// ------- M_b[n][h*64+d] = (1/S) * sum_e Ctx_{b,h}[d][e] * Wo[h*64+e][n] -----
__global__ __launch_bounds__(256) void mker(const float* __restrict__ Wo)
{
    const int n0 = blockIdx.x * 64;
    const int p  = blockIdx.y;           // b*8 + h
    const int b  = p >> 3;
    const int h  = p & 7;

    __shared__ float Ct[64][65];
    __shared__ float Ws[16][68];

    const int tid = threadIdx.x;
    const int tx  = tid & 15;
    const int ty  = tid >> 4;

    const float* ctx = g_Ctx + (size_t)p * HD * HD;
    #pragma unroll
    for (int i = 0; i < 16; ++i) {
        int lin = tid + i * 256;
        Ct[lin >> 6][lin & 63] = ctx[lin];
    }

    float acc[4][4];
    #pragma unroll
    for (int i = 0; i < 4; ++i)
        #pragma unroll
        for (int j = 0; j < 4; ++j) acc[i][j] = 0.f;

    for (int e0 = 0; e0 < 64; e0 += 16) {
        __syncthreads();
        {
            int e_l = tid >> 4;          // 0..15
            int n_l = (tid & 15) * 4;
            float4 w = *(const float4*)(Wo + (size_t)(h*64 + e0 + e_l) * 512 + n0 + n_l);
            Ws[e_l][n_l]   = w.x; Ws[e_l][n_l+1] = w.y;
            Ws[e_l][n_l+2] = w.z; Ws[e_l][n_l+3] = w.w;
        }
        __syncthreads();
        #pragma unroll
        for (int e = 0; e < 16; ++e) {
            float c0 = Ct[ty*4+0][e0+e];
            float c1 = Ct[ty*4+1][e0+e];
            float c2 = Ct[ty*4+2][e0+e];
            float c3 = Ct[ty*4+3][e0+e];
            float4 w = *(const float4*)&Ws[e][tx*4];
            acc[0][0] = fmaf(c0, w.x, acc[0][0]); acc[0][1] = fmaf(c0, w.y, acc[0][1]);
            acc[0][2] = fmaf(c0, w.z, acc[0][2]); acc[0][3] = fmaf(c0, w.w, acc[0][3]);
            acc[1][0] = fmaf(c1, w.x, acc[1][0]); acc[1][1] = fmaf(c1, w.y, acc[1][1]);
            acc[1][2] = fmaf(c1, w.z, acc[1][2]); acc[1][3] = fmaf(c1, w.w, acc[1][3]);
            acc[2][0] = fmaf(c2, w.x, acc[2][0]); acc[2][1] = fmaf(c2, w.y, acc[2][1]);
            acc[2][2] = fmaf(c2, w.z, acc[2][2]); acc[2][3] = fmaf(c2, w.w, acc[2][3]);
            acc[3][0] = fmaf(c3, w.x, acc[3][0]); acc[3][1] = fmaf(c3, w.y, acc[3][1]);
            acc[3][2] = fmaf(c3, w.z, acc[3][2]); acc[3][3] = fmaf(c3, w.w, acc[3][3]);
        }
    }

    // write fp16, transposed into B-layout [n][k=h*64+d], scaled by 1/S
    __half* Mb = g_M + (size_t)b * 512 * 512;
    #pragma unroll
    for (int j = 0; j < 4; ++j) {
        int n = n0 + tx*4 + j;
        #pragma unroll
        for (int i = 0; i < 4; ++i) {
            int d = ty*4 + i;
            Mb[(size_t)n * 512 + h*64 + d] = __float2half_rn(acc[i][j] * INV_ZSCALE);
        }
    }
}

// ------- qprep: Q'' = (S*z) * elu1(rope(q)); writes fp16 hi/lo --------------
__global__ __launch_bounds__(256) void qprep_kernel()
{
    const int h  = blockIdx.y;
    const int r0 = blockIdx.x * 64;
    const int b  = r0 >> 12;
    const int p  = b * NH + h;

    __shared__ float Qs[64][65];
    __shared__ float ks[64];
    __shared__ float zs[64];

    const int tid = threadIdx.x;

    if (tid < 64) ks[tid] = g_Ksum[p * HD + tid];

    #pragma unroll
    for (int ii = 0; ii < 2; ++ii) {
        int i = tid + ii * 256;
        int r = i >> 3;
        int c4 = (i & 7) * 4;
        int t = (r0 + r) & (T_ - 1);
        size_t base = (size_t)(r0 + r) * DM + h * HD;
        float4 x1 = *(const float4*)(g_Q + base + c4);
        float4 x2 = *(const float4*)(g_Q + base + 32 + c4);
        float4 cs = *(const float4*)(g_RopC + t * 32 + c4);
        float4 sn = *(const float4*)(g_RopS + t * 32 + c4);
        Qs[r][c4+0]  = elu1(x1.x*cs.x - x2.x*sn.x);
        Qs[r][c4+1]  = elu1(x1.y*cs.y - x2.y*sn.y);
        Qs[r][c4+2]  = elu1(x1.z*cs.z - x2.z*sn.z);
        Qs[r][c4+3]  = elu1(x1.w*cs.w - x2.w*sn.w);
        Qs[r][c4+32] = elu1(x1.x*sn.x + x2.x*cs.x);
        Qs[r][c4+33] = elu1(x1.y*sn.y + x2.y*cs.y);
        Qs[r][c4+34] = elu1(x1.z*sn.z + x2.z*cs.z);
        Qs[r][c4+35] = elu1(x1.w*sn.w + x2.w*cs.w);
    }
    __syncthreads();

    if (tid < 64) {
        float dsum = 0.f;
        #pragma unroll
        for (int d = 0; d < 64; ++d) dsum += Qs[tid][d] * ks[d];
        zs[tid] = ZSCALE / (dsum + 1e-6f);
    }
    __syncthreads();

    #pragma unroll
    for (int ii = 0; ii < 2; ++ii) {
        int i = tid + ii * 256;
        int r = i >> 3;
        int c4 = (i & 7) * 4;
        float z = zs[r];
        size_t base = (size_t)(r0 + r) * DM + h * HD;
        #pragma unroll
        for (int half_sel = 0; half_sel < 2; ++half_sel) {
            int c = c4 + half_sel * 32;
            float v0 = Qs[r][c+0] * z, v1 = Qs[r][c+1] * z;
            float v2 = Qs[r][c+2] * z, v3 = Qs[r][c+3] * z;
            __half h0 = __float2half_rn(v0), h1 = __float2half_rn(v1);
            __half h2 = __float2half_rn(v2), h3 = __float2half_rn(v3);
            *(uint2*)(g_QsH + base + c) =
                make_uint2(pack_h2(h0, h1), pack_h2(h2, h3));
            *(uint2*)(g_QsL + base + c) = make_uint2(
                pack_h2(__float2half_rn(v0 - __half2float(h0)),
                        __float2half_rn(v1 - __half2float(h1))),
                pack_h2(__float2half_rn(v2 - __half2float(h2)),
                        __float2half_rn(v3 - __half2float(h3))));
        }
    }
}

// ---------------------------------------------------------------------------
extern "C" void kernel_launch(void* const* d_in, const int* in_sizes, int n_in,
                              void* d_out, int out_size)
{
    const float* x  = (const float*)d_in[0];
    const float* Wq = (const float*)d_in[1];
    const float* bq = (const float*)d_in[2];
    const float* Wd = (const float*)d_in[3];
    const float* bd = (const float*)d_in[4];
    const float* Wu = (const float*)d_in[5];
    const float* bu = (const float*)d_in[6];
    const float* Wo = (const float*)d_in[7];
    const float* bo = (const float*)d_in[8];
    float* out = (float*)d_out;

    float *pQ, *pCtx, *pKsum;
    __half *pKV, *pXh, *pXl, *pCh, *pCl, *pQsH, *pQsL, *pM;
    __half *pWqH, *pWdH, *pWuH;
    cudaGetSymbolAddress((void**)&pQ,    g_Q);
    cudaGetSymbolAddress((void**)&pKV,   g_KV);
    cudaGetSymbolAddress((void**)&pCtx,  g_Ctx);
    cudaGetSymbolAddress((void**)&pKsum, g_Ksum);
    cudaGetSymbolAddress((void**)&pXh,   g_Xhi);
    cudaGetSymbolAddress((void**)&pXl,   g_Xlo);
    cudaGetSymbolAddress((void**)&pCh,   g_Chi);
    cudaGetSymbolAddress((void**)&pCl,   g_Clo);
    cudaGetSymbolAddress((void**)&pQsH,  g_QsH);
    cudaGetSymbolAddress((void**)&pQsL,  g_QsL);
    cudaGetSymbolAddress((void**)&pM,    g_M);
    cudaGetSymbolAddress((void**)&pWqH,  g_WqH);
    cudaGetSymbolAddress((void**)&pWdH,  g_WdH);
    cudaGetSymbolAddress((void**)&pWuH,  g_WuH);

    static bool init = false;
    static cudaStream_t s1;
    static cudaEvent_t evFork, evSplit, evQ;
    if (!init) {
        cudaStreamCreateWithFlags(&s1, cudaStreamNonBlocking);
        cudaEventCreateWithFlags(&evFork,  cudaEventDisableTiming);
        cudaEventCreateWithFlags(&evSplit, cudaEventDisableTiming);
        cudaEventCreateWithFlags(&evQ,     cudaEventDisableTiming);
        init = true;
    }

    // --- fork side stream early: Wq rounding has no deps ---------------------
    cudaEventRecord(evFork, 0);
    cudaStreamWaitEvent(s1, evFork, 0);
    round_weightT<<<dim3(512/32, 512/32), 256, 0, s1>>>(Wq, pWqH, 512, 512);

    // --- preprocessing (default stream) --------------------------------------
    cudaMemsetAsync(pCtx,  0, sizeof(float) * B_*NH*HD*HD);
    cudaMemsetAsync(pKsum, 0, sizeof(float) * B_*NH*HD);
    rope_table<<<T_*32/128, 128>>>();
    round_weightT<<<dim3(128/32, 512/32), 256>>>(Wd, pWdH, 512, 128);
    round_weightT<<<dim3(1024/32, 128/32), 256>>>(Wu, pWuH, 128, 1024);
    split_rows<<<(size_t)BT*512/4/256, 256>>>(x, pXh, pXl);
    cudaEventRecord(evSplit, 0);

    // --- side stream: Q = x @ Wq + bq (fp32) ---------------------------------
    cudaStreamWaitEvent(s1, evSplit, 0);
    bgemm2<<<dim3(4, BT/128), 256, 0, s1>>>(pXh, pXl, pWqH, bq,
                                            pQ, nullptr, nullptr, 512, 512, 0);
    cudaEventRecord(evQ, s1);

    // --- default: C -> KV -> context -> M ------------------------------------
    bgemm2<<<dim3(1, BT/128), 256>>>(pXh, pXl, pWdH, bd,
                                     nullptr, pCh, pCl, 128, 512, 0);
    bgemm2<<<dim3(8, BT/128), 256>>>(pCh, pCl, pWuH, bu,
                                     nullptr, pKV, nullptr, 1024, 128, 0);
    context_kernel<<<dim3(T_/256, B_*NH), 256>>>();
    mker<<<dim3(8, 64), 256>>>(Wo);

    // --- join: qprep needs Q (side stream) + ksum (context) ------------------
    cudaStreamWaitEvent(0, evQ, 0);
    qprep_kernel<<<dim3(BT/64, NH), 256>>>();

    // out = Q'' @ M_b + bo  (per-batch B)
    bgemm2<<<dim3(4, BT/128), 256>>>(pQsH, pQsL, pM, bo,
                                     out, nullptr, nullptr, 512, 512, 512*512);
}

// round 10
// speedup vs baseline: 1.4524x; 1.0649x over previous
#include <cuda_runtime.h>
#include <cuda_fp16.h>
#include <math.h>
#include <stdint.h>

#define B_   8
#define T_   4096
#define BT   (B_*T_)          // 32768 rows
#define DM   512
#define NH   8
#define HD   64

#define PADH 40               // smem row stride in halves (80B; conflict-free)
#define ZSCALE     16384.0f   // 2^14: keeps z*q' and M/S in fp16-normal range
#define INV_ZSCALE (1.0f/16384.0f)

// ---------------- scratch (static device globals; no allocation) ------------
__device__ float  g_Q   [(size_t)BT * DM];     // Q fp32 (raw; roped in qprep)
__device__ __half g_KV  [(size_t)BT * 1024];   // kv fp16 (rounded once)
__device__ float  g_Ctx [B_*NH*HD*HD];
__device__ float  g_Ksum[B_*NH*HD];
__device__ float  g_RopC[T_*32];
__device__ float  g_RopS[T_*32];

__device__ __half g_Xhi[(size_t)BT*DM],  g_Xlo[(size_t)BT*DM];
__device__ __half g_Chi[(size_t)BT*128], g_Clo[(size_t)BT*128];
__device__ __half g_QsH[(size_t)BT*DM];                         // z-scaled q' (fp16)
__device__ __half g_M  [(size_t)B_*512*512];                    // per-batch Ctx@Wo / S
__device__ __half g_WqH[512*512];
__device__ __half g_WdH[128*512];
__device__ __half g_WuH[1024*128];

// ---------------- helpers ---------------------------------------------------
__device__ __forceinline__ uint32_t smem_u32(const void* p) {
    uint32_t a;
    asm("{ .reg .u64 t; cvta.to.shared.u64 t, %1; cvt.u32.u64 %0, t; }"
        : "=r"(a) : "l"(p));
    return a;
}
__device__ __forceinline__ void mma16816(float* d, const uint32_t* a, const uint32_t* b)
{
    asm volatile(
        "mma.sync.aligned.m16n8k16.row.col.f32.f16.f16.f32 "
        "{%0,%1,%2,%3}, {%4,%5,%6,%7}, {%8,%9}, {%0,%1,%2,%3};"
        : "+f"(d[0]), "+f"(d[1]), "+f"(d[2]), "+f"(d[3])
        : "r"(a[0]), "r"(a[1]), "r"(a[2]), "r"(a[3]), "r"(b[0]), "r"(b[1]));
}
__device__ __forceinline__ void ldsm_x4(uint32_t* r, uint32_t addr) {
    asm volatile("ldmatrix.sync.aligned.m8n8.x4.shared.b16 {%0,%1,%2,%3}, [%4];"
        : "=r"(r[0]), "=r"(r[1]), "=r"(r[2]), "=r"(r[3]) : "r"(addr));
}
__device__ __forceinline__ void ldsm_x2(uint32_t* r, uint32_t addr) {
    asm volatile("ldmatrix.sync.aligned.m8n8.x2.shared.b16 {%0,%1}, [%2];"
        : "=r"(r[0]), "=r"(r[1]) : "r"(addr));
}
__device__ __forceinline__ uint32_t pack_h2(__half a, __half b)
{
    __half2 p = __halves2half2(a, b);
    return *(uint32_t*)&p;
}
// load 4 consecutive halves -> 4 floats
__device__ __forceinline__ void ld4h(const __half* p, float* o)
{
    uint2 u = *(const uint2*)p;
    const __half2* h = (const __half2*)&u;
    float2 a = __half22float2(h[0]);
    float2 b = __half22float2(h[1]);
    o[0] = a.x; o[1] = a.y; o[2] = b.x; o[3] = b.y;
}

// ========== fp16 GEMM: D = (Ah [+ Al]) @ Bh^T + bias ========================
// 128x128 tile, BK=32, 256 threads (8 warps 2x4), warp tile 64x32.
// Alo == nullptr -> single-term fp16 GEMM (half the MMAs).
// Output modes: outF -> fp32; else outLo -> fp16 hi/lo; else outHi fp16 single.
// bStride: per-batch B stride (batch = m0>>12), 0 for shared B.
__global__ __launch_bounds__(256) void bgemm2(
    const __half* __restrict__ Ahi, const __half* __restrict__ Alo,
    const __half* __restrict__ Bh16,
    const float* __restrict__ bias,
    float* __restrict__ outF,
    __half* __restrict__ outHi, __half* __restrict__ outLo,
    int N, int K, int bStride)
{
    __shared__ __half sAh[128*PADH];
    __shared__ __half sAl[128*PADH];
    __shared__ __half sBh[128*PADH];

    const int tid  = threadIdx.x;
    const int lane = tid & 31;
    const int wid  = tid >> 5;
    const int wm   = (wid >> 2) * 64;
    const int wn   = (wid & 3) * 32;
    const int g    = lane >> 2;
    const int t2   = (lane & 3) * 2;
    const int m0   = blockIdx.y * 128;
    const int n0   = blockIdx.x * 128;

    const bool twoTerm = (Alo != nullptr);

    const int lrow = tid >> 2;           // 0..63
    const int lseg = tid & 3;            // 16B seg within 64B row

    const __half* gA0 = Ahi  + (size_t)(m0 + lrow) * K + lseg * 8;
    const __half* gA1 = twoTerm ? (Alo + (size_t)(m0 + lrow) * K + lseg * 8) : gA0;
    const __half* gB0 = Bh16 + (size_t)(m0 >> 12) * bStride
                             + (size_t)(n0 + lrow) * K + lseg * 8;
    const size_t rstep = (size_t)64 * K;

    const int a_row  = ((lane >> 3) & 1) * 8 + (lane & 7);
    const int a_col8 = (lane >> 4) * 8;
    const int b_row  = (lane & 7);
    const int b_col8 = ((lane >> 3) & 1) * 8;

    const uint32_t uAh = smem_u32(sAh);
    const uint32_t uAl = smem_u32(sAl);
    const uint32_t uBh = smem_u32(sBh);

    const uint32_t soff  = (uint32_t)(lrow * (PADH*2) + lseg * 16);
    const uint32_t soff2 = soff + (uint32_t)(64 * PADH * 2);

    const int nch = K >> 5;

    uint4 pA0[2], pA1[2], pB0[2];
    pA0[0] = *(const uint4*)gA0; pA0[1] = *(const uint4*)(gA0 + rstep);
    pB0[0] = *(const uint4*)gB0; pB0[1] = *(const uint4*)(gB0 + rstep);
    if (twoTerm) { pA1[0] = *(const uint4*)gA1; pA1[1] = *(const uint4*)(gA1 + rstep); }

    float acc[4][4][4];
    #pragma unroll
    for (int mt = 0; mt < 4; ++mt)
        #pragma unroll
        for (int nt = 0; nt < 4; ++nt)
            #pragma unroll
            for (int i = 0; i < 4; ++i) acc[mt][nt][i] = 0.f;

    for (int ch = 0; ch < nch; ++ch) {
        *(uint4*)((char*)sAh + soff)  = pA0[0];
        *(uint4*)((char*)sAh + soff2) = pA0[1];
        if (twoTerm) {
            *(uint4*)((char*)sAl + soff)  = pA1[0];
            *(uint4*)((char*)sAl + soff2) = pA1[1];
        }
        *(uint4*)((char*)sBh + soff)  = pB0[0];
        *(uint4*)((char*)sBh + soff2) = pB0[1];
        __syncthreads();

        if (ch + 1 < nch) {
            const int ko = (ch + 1) * 32;
            pA0[0] = *(const uint4*)(gA0 + ko); pA0[1] = *(const uint4*)(gA0 + rstep + ko);
            pB0[0] = *(const uint4*)(gB0 + ko); pB0[1] = *(const uint4*)(gB0 + rstep + ko);
            if (twoTerm) {
                pA1[0] = *(const uint4*)(gA1 + ko);
                pA1[1] = *(const uint4*)(gA1 + rstep + ko);
            }
        }

        #pragma unroll
        for (int ks = 0; ks < 2; ++ks) {
            const int k0 = ks * 16;
            uint32_t ah[4][4], al[4][4];
            #pragma unroll
            for (int mt = 0; mt < 4; ++mt) {
                uint32_t off = (uint32_t)(((wm + mt*16 + a_row) * PADH + k0 + a_col8) * 2);
                ldsm_x4(ah[mt], uAh + off);
                if (twoTerm) ldsm_x4(al[mt], uAl + off);
            }
            #pragma unroll
            for (int nt = 0; nt < 4; ++nt) {
                uint32_t boff = (uint32_t)(((wn + nt*8 + b_row) * PADH + k0 + b_col8) * 2);
                uint32_t bh[2];
                ldsm_x2(bh, uBh + boff);
                #pragma unroll
                for (int mt = 0; mt < 4; ++mt) {
                    mma16816(acc[mt][nt], ah[mt], bh);
                    if (twoTerm) mma16816(acc[mt][nt], al[mt], bh);
                }
            }
        }
        __syncthreads();
    }

    // epilogue
    #pragma unroll
    for (int mt = 0; mt < 4; ++mt) {
        int row = m0 + wm + mt * 16 + g;
        #pragma unroll
        for (int nt = 0; nt < 4; ++nt) {
            int col = n0 + wn + nt * 8 + t2;
            float b0 = bias[col], b1 = bias[col + 1];
            float v00 = acc[mt][nt][0] + b0, v01 = acc[mt][nt][1] + b1;
            float v10 = acc[mt][nt][2] + b0, v11 = acc[mt][nt][3] + b1;
            if (outF) {
                *(float2*)(outF + (size_t)row * N + col)       = make_float2(v00, v01);
                *(float2*)(outF + (size_t)(row + 8) * N + col) = make_float2(v10, v11);
            } else if (outLo) {
                __half h00 = __float2half_rn(v00);
                __half h01 = __float2half_rn(v01);
                __half h10 = __float2half_rn(v10);
                __half h11 = __float2half_rn(v11);
                *(uint32_t*)(outHi + (size_t)row * N + col)       = pack_h2(h00, h01);
                *(uint32_t*)(outHi + (size_t)(row + 8) * N + col) = pack_h2(h10, h11);
                *(uint32_t*)(outLo + (size_t)row * N + col) = pack_h2(
                    __float2half_rn(v00 - __half2float(h00)),
                    __float2half_rn(v01 - __half2float(h01)));
                *(uint32_t*)(outLo + (size_t)(row + 8) * N + col) = pack_h2(
                    __float2half_rn(v10 - __half2float(h10)),
                    __float2half_rn(v11 - __half2float(h11)));
            } else {
                *(uint32_t*)(outHi + (size_t)row * N + col) =
                    pack_h2(__float2half_rn(v00), __float2half_rn(v01));
                *(uint32_t*)(outHi + (size_t)(row + 8) * N + col) =
                    pack_h2(__float2half_rn(v10), __float2half_rn(v11));
            }
        }
    }
}

// ---------------- split fp32 -> fp16 hi/lo (no transpose) -------------------
__global__ __launch_bounds__(256) void split_rows(
    const float* __restrict__ X, __half* __restrict__ Hi,
    __half* __restrict__ Lo)
{
    size_t e0 = ((size_t)blockIdx.x * 256 + threadIdx.x) * 4;
    float4 v = *(const float4*)(X + e0);
    __half h0 = __float2half_rn(v.x), h1 = __float2half_rn(v.y);
    __half h2 = __float2half_rn(v.z), h3 = __float2half_rn(v.w);
    uint2 hh = make_uint2(pack_h2(h0, h1), pack_h2(h2, h3));
    uint2 ll = make_uint2(
        pack_h2(__float2half_rn(v.x - __half2float(h0)),
                __float2half_rn(v.y - __half2float(h1))),
        pack_h2(__float2half_rn(v.z - __half2float(h2)),
                __float2half_rn(v.w - __half2float(h3))));
    *(uint2*)(Hi + e0) = hh;
    *(uint2*)(Lo + e0) = ll;
}

// ------- weight transpose + round: W[K,N] -> Wt[N,K] fp16 -------------------
__global__ __launch_bounds__(256) void round_weightT(
    const float* __restrict__ W, __half* __restrict__ Wh, int K, int N)
{
    __shared__ float t[32][33];
    int kb = blockIdx.y * 32, nb = blockIdx.x * 32;
    int x = threadIdx.x & 31, y = threadIdx.x >> 5;
    #pragma unroll
    for (int i = 0; i < 32; i += 8)
        t[y + i][x] = W[(size_t)(kb + y + i) * N + nb + x];
    __syncthreads();
    #pragma unroll
    for (int i = 0; i < 32; i += 8)
        Wh[(size_t)(nb + y + i) * K + kb + x] = __float2half_rn(t[x][y + i]);
}

// ---------------- rope cos/sin table ----------------------------------------
__global__ __launch_bounds__(128) void rope_table()
{
    int idx = blockIdx.x * 128 + threadIdx.x;    // T_*32
    int t = idx >> 5, j = idx & 31;
    const float LOG2_1E4 = 13.2877123795494f;
    float freq = exp2f(-(float)j * (LOG2_1E4 / 32.f));
    float s, c;
    sincosf((float)t * freq, &s, &c);
    g_RopC[idx] = c;
    g_RopS[idx] = s;
}

__device__ __forceinline__ float elu1(float x) {
    return (x > 0.f) ? (x + 1.f) : expf(x);
}

// ------- context[b,h] = sum_t rope_elu(k)(t) outer v(t); ksum too -----------
__global__ __launch_bounds__(256) void context_kernel()
{
    const int p  = blockIdx.y;
    const int b  = p >> 3;
    const int h  = p & 7;
    const int t0 = blockIdx.x * 256;

    __shared__ float Ks[32][64];
    __shared__ float Vs[32][64];

    const int tid = threadIdx.x;
    const int tx  = tid & 15;
    const int ty  = tid >> 4;
    const int kr_ = tid >> 3;          // 0..31
    const int kc4 = (tid & 7) * 4;     // 0..28

    float acc[4][4];
    #pragma unroll
    for (int i = 0; i < 4; ++i)
        #pragma unroll
        for (int j = 0; j < 4; ++j) acc[i][j] = 0.f;
    float ksm[4] = {0.f, 0.f, 0.f, 0.f};

    for (int tt = 0; tt < 256; tt += 32) {
        {
            int t = t0 + tt + kr_;
            const __half* kp = g_KV + (size_t)(b * T_ + t) * 1024 + h * 128;
            float x1[4], x2[4];
            ld4h(kp + kc4, x1);
            ld4h(kp + 32 + kc4, x2);
            float4 cs = *(const float4*)(g_RopC + t * 32 + kc4);
            float4 sn = *(const float4*)(g_RopS + t * 32 + kc4);
            Ks[kr_][kc4+0]    = elu1(x1[0]*cs.x - x2[0]*sn.x);
            Ks[kr_][kc4+1]    = elu1(x1[1]*cs.y - x2[1]*sn.y);
            Ks[kr_][kc4+2]    = elu1(x1[2]*cs.z - x2[2]*sn.z);
            Ks[kr_][kc4+3]    = elu1(x1[3]*cs.w - x2[3]*sn.w);
            Ks[kr_][kc4+32]   = elu1(x1[0]*sn.x + x2[0]*cs.x);
            Ks[kr_][kc4+33]   = elu1(x1[1]*sn.y + x2[1]*cs.y);
            Ks[kr_][kc4+34]   = elu1(x1[2]*sn.z + x2[2]*cs.z);
            Ks[kr_][kc4+35]   = elu1(x1[3]*sn.w + x2[3]*cs.w);
        }
        #pragma unroll
        for (int ii = 0; ii < 2; ++ii) {
            int i = tid + ii * 256;
            int r = i >> 4;
            int c = (i & 15) * 4;
            const __half* vp = g_KV + (size_t)(b * T_ + t0 + tt + r) * 1024 + h * 128 + 64;
            float vv[4];
            ld4h(vp + c, vv);
            Vs[r][c]   = vv[0]; Vs[r][c+1] = vv[1];
            Vs[r][c+2] = vv[2]; Vs[r][c+3] = vv[3];
        }
        __syncthreads();
        #pragma unroll 8
        for (int t = 0; t < 32; ++t) {
            float kr[4], vr[4];
            *(float4*)kr = *(const float4*)&Ks[t][ty*4];
            *(float4*)vr = *(const float4*)&Vs[t][tx*4];
            #pragma unroll
            for (int i = 0; i < 4; ++i)
                #pragma unroll
                for (int j = 0; j < 4; ++j)
                    acc[i][j] = fmaf(kr[i], vr[j], acc[i][j]);
            if (tx == 0) {
                #pragma unroll
                for (int i = 0; i < 4; ++i) ksm[i] += kr[i];
            }
        }
        __syncthreads();
    }

    float* ctx = g_Ctx + (size_t)p * HD * HD;
    #pragma unroll
    for (int i = 0; i < 4; ++i)
        #pragma unroll
        for (int j = 0; j < 4; ++j)
            atomicAdd(&ctx[(ty*4 + i) * HD + tx*4 + j], acc[i][j]);
    if (tx == 0) {
        #pragma unroll
        for (int i = 0; i < 4; ++i)
            atomicAdd(&g_Ksum[p * HD + ty*4 + i], ksm[i]);
    }
}

// ------- M_b[n][h*64+d] = (1/S) * sum_e Ctx_{b,h}[d][e] * Wo[h*64+e][n] -----
__global__ __launch_bounds__(256) void mker(const float* __restrict__ Wo)
{
    const int n0 = blockIdx.x * 64;
    const int p  = blockIdx.y;           // b*8 + h
    const int b  = p >> 3;
    const int h  = p & 7;

    __shared__ float Ct[64][65];
    __shared__ float Ws[16][68];

    const int tid = threadIdx.x;
    const int tx  = tid & 15;
    const int ty  = tid >> 4;

    const float* ctx = g_Ctx + (size_t)p * HD * HD;
    #pragma unroll
    for (int i = 0; i < 16; ++i) {
        int lin = tid + i * 256;
        Ct[lin >> 6][lin & 63] = ctx[lin];
    }

    float acc[4][4];
    #pragma unroll
    for (int i = 0; i < 4; ++i)
        #pragma unroll
        for (int j = 0; j < 4; ++j) acc[i][j] = 0.f;

    for (int e0 = 0; e0 < 64; e0 += 16) {
        __syncthreads();
        {
            int e_l = tid >> 4;          // 0..15
            int n_l = (tid & 15) * 4;
            float4 w = *(const float4*)(Wo + (size_t)(h*64 + e0 + e_l) * 512 + n0 + n_l);
            Ws[e_l][n_l]   = w.x; Ws[e_l][n_l+1] = w.y;
            Ws[e_l][n_l+2] = w.z; Ws[e_l][n_l+3] = w.w;
        }
        __syncthreads();
        #pragma unroll
        for (int e = 0; e < 16; ++e) {
            float c0 = Ct[ty*4+0][e0+e];
            float c1 = Ct[ty*4+1][e0+e];
            float c2 = Ct[ty*4+2][e0+e];
            float c3 = Ct[ty*4+3][e0+e];
            float4 w = *(const float4*)&Ws[e][tx*4];
            acc[0][0] = fmaf(c0, w.x, acc[0][0]); acc[0][1] = fmaf(c0, w.y, acc[0][1]);
            acc[0][2] = fmaf(c0, w.z, acc[0][2]); acc[0][3] = fmaf(c0, w.w, acc[0][3]);
            acc[1][0] = fmaf(c1, w.x, acc[1][0]); acc[1][1] = fmaf(c1, w.y, acc[1][1]);
            acc[1][2] = fmaf(c1, w.z, acc[1][2]); acc[1][3] = fmaf(c1, w.w, acc[1][3]);
            acc[2][0] = fmaf(c2, w.x, acc[2][0]); acc[2][1] = fmaf(c2, w.y, acc[2][1]);
            acc[2][2] = fmaf(c2, w.z, acc[2][2]); acc[2][3] = fmaf(c2, w.w, acc[2][3]);
            acc[3][0] = fmaf(c3, w.x, acc[3][0]); acc[3][1] = fmaf(c3, w.y, acc[3][1]);
            acc[3][2] = fmaf(c3, w.z, acc[3][2]); acc[3][3] = fmaf(c3, w.w, acc[3][3]);
        }
    }

    // write fp16, transposed into B-layout [n][k=h*64+d], scaled by 1/S
    __half* Mb = g_M + (size_t)b * 512 * 512;
    #pragma unroll
    for (int j = 0; j < 4; ++j) {
        int n = n0 + tx*4 + j;
        #pragma unroll
        for (int i = 0; i < 4; ++i) {
            int d = ty*4 + i;
            Mb[(size_t)n * 512 + h*64 + d] = __float2half_rn(acc[i][j] * INV_ZSCALE);
        }
    }
}

// ------- qprep: Q'' = (S*z) * elu1(rope(q)); writes fp16 -------------------
__global__ __launch_bounds__(256) void qprep_kernel()
{
    const int h  = blockIdx.y;
    const int r0 = blockIdx.x * 64;
    const int b  = r0 >> 12;
    const int p  = b * NH + h;

    __shared__ float Qs[64][65];
    __shared__ float ks[64];
    __shared__ float zs[64];

    const int tid = threadIdx.x;

    if (tid < 64) ks[tid] = g_Ksum[p * HD + tid];

    #pragma unroll
    for (int ii = 0; ii < 2; ++ii) {
        int i = tid + ii * 256;
        int r = i >> 3;
        int c4 = (i & 7) * 4;
        int t = (r0 + r) & (T_ - 1);
        size_t base = (size_t)(r0 + r) * DM + h * HD;
        float4 x1 = *(const float4*)(g_Q + base + c4);
        float4 x2 = *(const float4*)(g_Q + base + 32 + c4);
        float4 cs = *(const float4*)(g_RopC + t * 32 + c4);
        float4 sn = *(const float4*)(g_RopS + t * 32 + c4);
        Qs[r][c4+0]  = elu1(x1.x*cs.x - x2.x*sn.x);
        Qs[r][c4+1]  = elu1(x1.y*cs.y - x2.y*sn.y);
        Qs[r][c4+2]  = elu1(x1.z*cs.z - x2.z*sn.z);
        Qs[r][c4+3]  = elu1(x1.w*cs.w - x2.w*sn.w);
        Qs[r][c4+32] = elu1(x1.x*sn.x + x2.x*cs.x);
        Qs[r][c4+33] = elu1(x1.y*sn.y + x2.y*cs.y);
        Qs[r][c4+34] = elu1(x1.z*sn.z + x2.z*cs.z);
        Qs[r][c4+35] = elu1(x1.w*sn.w + x2.w*cs.w);
    }
    __syncthreads();

    if (tid < 64) {
        float dsum = 0.f;
        #pragma unroll
        for (int d = 0; d < 64; ++d) dsum += Qs[tid][d] * ks[d];
        zs[tid] = ZSCALE / (dsum + 1e-6f);
    }
    __syncthreads();

    #pragma unroll
    for (int ii = 0; ii < 2; ++ii) {
        int i = tid + ii * 256;
        int r = i >> 3;
        int c4 = (i & 7) * 4;
        float z = zs[r];
        size_t base = (size_t)(r0 + r) * DM + h * HD;
        #pragma unroll
        for (int half_sel = 0; half_sel < 2; ++half_sel) {
            int c = c4 + half_sel * 32;
            float v0 = Qs[r][c+0] * z, v1 = Qs[r][c+1] * z;
            float v2 = Qs[r][c+2] * z, v3 = Qs[r][c+3] * z;
            *(uint2*)(g_QsH + base + c) = make_uint2(
                pack_h2(__float2half_rn(v0), __float2half_rn(v1)),
                pack_h2(__float2half_rn(v2), __float2half_rn(v3)));
        }
    }
}

// ---------------------------------------------------------------------------
extern "C" void kernel_launch(void* const* d_in, const int* in_sizes, int n_in,
                              void* d_out, int out_size)
{
    const float* x  = (const float*)d_in[0];
    const float* Wq = (const float*)d_in[1];
    const float* bq = (const float*)d_in[2];
    const float* Wd = (const float*)d_in[3];
    const float* bd = (const float*)d_in[4];
    const float* Wu = (const float*)d_in[5];
    const float* bu = (const float*)d_in[6];
    const float* Wo = (const float*)d_in[7];
    const float* bo = (const float*)d_in[8];
    float* out = (float*)d_out;

    float *pQ, *pCtx, *pKsum;
    __half *pKV, *pXh, *pXl, *pCh, *pCl, *pQsH, *pM;
    __half *pWqH, *pWdH, *pWuH;
    cudaGetSymbolAddress((void**)&pQ,    g_Q);
    cudaGetSymbolAddress((void**)&pKV,   g_KV);
    cudaGetSymbolAddress((void**)&pCtx,  g_Ctx);
    cudaGetSymbolAddress((void**)&pKsum, g_Ksum);
    cudaGetSymbolAddress((void**)&pXh,   g_Xhi);
    cudaGetSymbolAddress((void**)&pXl,   g_Xlo);
    cudaGetSymbolAddress((void**)&pCh,   g_Chi);
    cudaGetSymbolAddress((void**)&pCl,   g_Clo);
    cudaGetSymbolAddress((void**)&pQsH,  g_QsH);
    cudaGetSymbolAddress((void**)&pM,    g_M);
    cudaGetSymbolAddress((void**)&pWqH,  g_WqH);
    cudaGetSymbolAddress((void**)&pWdH,  g_WdH);
    cudaGetSymbolAddress((void**)&pWuH,  g_WuH);

    static bool init = false;
    static cudaStream_t s1;
    static cudaEvent_t evFork, evSplit, evQ;
    if (!init) {
        cudaStreamCreateWithFlags(&s1, cudaStreamNonBlocking);
        cudaEventCreateWithFlags(&evFork,  cudaEventDisableTiming);
        cudaEventCreateWithFlags(&evSplit, cudaEventDisableTiming);
        cudaEventCreateWithFlags(&evQ,     cudaEventDisableTiming);
        init = true;
    }

    // --- fork side stream early: Wq rounding has no deps ---------------------
    cudaEventRecord(evFork, 0);
    cudaStreamWaitEvent(s1, evFork, 0);
    round_weightT<<<dim3(512/32, 512/32), 256, 0, s1>>>(Wq, pWqH, 512, 512);

    // --- preprocessing (default stream) --------------------------------------
    cudaMemsetAsync(pCtx,  0, sizeof(float) * B_*NH*HD*HD);
    cudaMemsetAsync(pKsum, 0, sizeof(float) * B_*NH*HD);
    rope_table<<<T_*32/128, 128>>>();
    round_weightT<<<dim3(128/32, 512/32), 256>>>(Wd, pWdH, 512, 128);
    round_weightT<<<dim3(1024/32, 128/32), 256>>>(Wu, pWuH, 128, 1024);
    split_rows<<<(size_t)BT*512/4/256, 256>>>(x, pXh, pXl);
    cudaEventRecord(evSplit, 0);

    // --- side stream: Q = x @ Wq + bq (fp32; single fp16 term) ---------------
    cudaStreamWaitEvent(s1, evSplit, 0);
    bgemm2<<<dim3(4, BT/128), 256, 0, s1>>>(pXh, nullptr, pWqH, bq,
                                            pQ, nullptr, nullptr, 512, 512, 0);
    cudaEventRecord(evQ, s1);

    // --- default: C -> KV -> context -> M ------------------------------------
    bgemm2<<<dim3(1, BT/128), 256>>>(pXh, pXl, pWdH, bd,
                                     nullptr, pCh, pCl, 128, 512, 0);
    bgemm2<<<dim3(8, BT/128), 256>>>(pCh, pCl, pWuH, bu,
                                     nullptr, pKV, nullptr, 1024, 128, 0);
    context_kernel<<<dim3(T_/256, B_*NH), 256>>>();
    mker<<<dim3(8, 64), 256>>>(Wo);

    // --- join: qprep needs Q (side stream) + ksum (context) ------------------
    cudaStreamWaitEvent(0, evQ, 0);
    qprep_kernel<<<dim3(BT/64, NH), 256>>>();

    // out = Q'' @ M_b + bo  (per-batch B; single fp16 term)
    bgemm2<<<dim3(4, BT/128), 256>>>(pQsH, nullptr, pM, bo,
                                     out, nullptr, nullptr, 512, 512, 512*512);
}

// round 12
// speedup vs baseline: 1.4650x; 1.0087x over previous
#include <cuda_runtime.h>
#include <cuda_fp16.h>
#include <math.h>
#include <stdint.h>

#define B_   8
#define T_   4096
#define BT   (B_*T_)          // 32768 rows
#define DM   512
#define NH   8
#define HD   64

#define PADH 40               // smem row stride in halves (80B; conflict-free)
#define ZSCALE     16384.0f   // 2^14: keeps z*q' and M/S in fp16-normal range
#define INV_ZSCALE (1.0f/16384.0f)

// ---------------- scratch (static device globals; no allocation) ------------
__device__ float  g_Q   [(size_t)BT * DM];     // Q fp32 (raw; roped in qprep)
__device__ __half g_KV  [(size_t)BT * 1024];   // kv fp16 (rounded once)
__device__ float  g_Ctx [B_*NH*HD*HD];
__device__ float  g_Ksum[B_*NH*HD];
__device__ float  g_RopC[T_*32];
__device__ float  g_RopS[T_*32];

__device__ __half g_Xhi[(size_t)BT*DM],  g_Xlo[(size_t)BT*DM];
__device__ __half g_Chi[(size_t)BT*128], g_Clo[(size_t)BT*128];
__device__ __half g_QsH[(size_t)BT*DM];                         // z-scaled q' (fp16)
__device__ __half g_M  [(size_t)B_*512*512];                    // per-batch Ctx@Wo / S
__device__ __half g_WqH[512*512];
__device__ __half g_WdH[128*512];
__device__ __half g_WuH[1024*128];

// ---------------- helpers ---------------------------------------------------
__device__ __forceinline__ uint32_t smem_u32(const void* p) {
    uint32_t a;
    asm("{ .reg .u64 t; cvta.to.shared.u64 t, %1; cvt.u32.u64 %0, t; }"
        : "=r"(a) : "l"(p));
    return a;
}
__device__ __forceinline__ void mma16816(float* d, const uint32_t* a, const uint32_t* b)
{
    asm volatile(
        "mma.sync.aligned.m16n8k16.row.col.f32.f16.f16.f32 "
        "{%0,%1,%2,%3}, {%4,%5,%6,%7}, {%8,%9}, {%0,%1,%2,%3};"
        : "+f"(d[0]), "+f"(d[1]), "+f"(d[2]), "+f"(d[3])
        : "r"(a[0]), "r"(a[1]), "r"(a[2]), "r"(a[3]), "r"(b[0]), "r"(b[1]));
}
__device__ __forceinline__ void ldsm_x4(uint32_t* r, uint32_t addr) {
    asm volatile("ldmatrix.sync.aligned.m8n8.x4.shared.b16 {%0,%1,%2,%3}, [%4];"
        : "=r"(r[0]), "=r"(r[1]), "=r"(r[2]), "=r"(r[3]) : "r"(addr));
}
__device__ __forceinline__ void ldsm_x2(uint32_t* r, uint32_t addr) {
    asm volatile("ldmatrix.sync.aligned.m8n8.x2.shared.b16 {%0,%1}, [%2];"
        : "=r"(r[0]), "=r"(r[1]) : "r"(addr));
}
__device__ __forceinline__ uint32_t pack_h2(__half a, __half b)
{
    __half2 p = __halves2half2(a, b);
    return *(uint32_t*)&p;
}
// load 4 consecutive halves -> 4 floats
__device__ __forceinline__ void ld4h(const __half* p, float* o)
{
    uint2 u = *(const uint2*)p;
    const __half2* h = (const __half2*)&u;
    float2 a = __half22float2(h[0]);
    float2 b = __half22float2(h[1]);
    o[0] = a.x; o[1] = a.y; o[2] = b.x; o[3] = b.y;
}

// ---- elu(x)+1, branchless, FMA/ALU pipes only (no MUFU) --------------------
// x>0: x+1.  x<=0: exp(x) via 2^(x*log2e) with degree-5 poly on [-0.5,0.5].
__device__ __forceinline__ float elu1(float x)
{
    float t = fminf(x, 0.f) * 1.44269504089f;   // log2(e); t <= 0
    t = fmaxf(t, -28.f);                        // exp underflow clamp
    float n = rintf(t);
    float f = t - n;                            // [-0.5, 0.5]
    float p = 1.33336498402e-3f;                // Taylor(2^f), err ~2.4e-6
    p = fmaf(p, f, 9.61812910763e-3f);
    p = fmaf(p, f, 5.55041086648e-2f);
    p = fmaf(p, f, 2.40226506959e-1f);
    p = fmaf(p, f, 6.93147180560e-1f);
    p = fmaf(p, f, 1.0f);
    float e = __int_as_float(((int)n + 127) << 23) * p;   // 2^n * 2^f
    return (x > 0.f) ? (x + 1.f) : e;
}

// ========== fp16 GEMM: D = (Ah [+ Al]) @ Bh^T + bias ========================
// 128x128 tile, BK=32, 256 threads (8 warps 2x4), warp tile 64x32.
// Alo == nullptr -> single-term fp16 GEMM (half the MMAs).
// Output modes: outF -> fp32; else outLo -> fp16 hi/lo; else outHi fp16 single.
// bStride: per-batch B stride (batch = m0>>12), 0 for shared B.
__global__ __launch_bounds__(256) void bgemm2(
    const __half* __restrict__ Ahi, const __half* __restrict__ Alo,
    const __half* __restrict__ Bh16,
    const float* __restrict__ bias,
    float* __restrict__ outF,
    __half* __restrict__ outHi, __half* __restrict__ outLo,
    int N, int K, int bStride)
{
    __shared__ __half sAh[128*PADH];
    __shared__ __half sAl[128*PADH];
    __shared__ __half sBh[128*PADH];

    const int tid  = threadIdx.x;
    const int lane = tid & 31;
    const int wid  = tid >> 5;
    const int wm   = (wid >> 2) * 64;
    const int wn   = (wid & 3) * 32;
    const int g    = lane >> 2;
    const int t2   = (lane & 3) * 2;
    const int m0   = blockIdx.y * 128;
    const int n0   = blockIdx.x * 128;

    const bool twoTerm = (Alo != nullptr);

    const int lrow = tid >> 2;           // 0..63
    const int lseg = tid & 3;            // 16B seg within 64B row

    const __half* gA0 = Ahi  + (size_t)(m0 + lrow) * K + lseg * 8;
    const __half* gA1 = twoTerm ? (Alo + (size_t)(m0 + lrow) * K + lseg * 8) : gA0;
    const __half* gB0 = Bh16 + (size_t)(m0 >> 12) * bStride
                             + (size_t)(n0 + lrow) * K + lseg * 8;
    const size_t rstep = (size_t)64 * K;

    const int a_row  = ((lane >> 3) & 1) * 8 + (lane & 7);
    const int a_col8 = (lane >> 4) * 8;
    const int b_row  = (lane & 7);
    const int b_col8 = ((lane >> 3) & 1) * 8;

    const uint32_t uAh = smem_u32(sAh);
    const uint32_t uAl = smem_u32(sAl);
    const uint32_t uBh = smem_u32(sBh);

    const uint32_t soff  = (uint32_t)(lrow * (PADH*2) + lseg * 16);
    const uint32_t soff2 = soff + (uint32_t)(64 * PADH * 2);

    const int nch = K >> 5;

    uint4 pA0[2], pA1[2], pB0[2];
    pA0[0] = *(const uint4*)gA0; pA0[1] = *(const uint4*)(gA0 + rstep);
    pB0[0] = *(const uint4*)gB0; pB0[1] = *(const uint4*)(gB0 + rstep);
    if (twoTerm) { pA1[0] = *(const uint4*)gA1; pA1[1] = *(const uint4*)(gA1 + rstep); }

    float acc[4][4][4];
    #pragma unroll
    for (int mt = 0; mt < 4; ++mt)
        #pragma unroll
        for (int nt = 0; nt < 4; ++nt)
            #pragma unroll
            for (int i = 0; i < 4; ++i) acc[mt][nt][i] = 0.f;

    for (int ch = 0; ch < nch; ++ch) {
        *(uint4*)((char*)sAh + soff)  = pA0[0];
        *(uint4*)((char*)sAh + soff2) = pA0[1];
        if (twoTerm) {
            *(uint4*)((char*)sAl + soff)  = pA1[0];
            *(uint4*)((char*)sAl + soff2) = pA1[1];
        }
        *(uint4*)((char*)sBh + soff)  = pB0[0];
        *(uint4*)((char*)sBh + soff2) = pB0[1];
        __syncthreads();

        if (ch + 1 < nch) {
            const int ko = (ch + 1) * 32;
            pA0[0] = *(const uint4*)(gA0 + ko); pA0[1] = *(const uint4*)(gA0 + rstep + ko);
            pB0[0] = *(const uint4*)(gB0 + ko); pB0[1] = *(const uint4*)(gB0 + rstep + ko);
            if (twoTerm) {
                pA1[0] = *(const uint4*)(gA1 + ko);
                pA1[1] = *(const uint4*)(gA1 + rstep + ko);
            }
        }

        #pragma unroll
        for (int ks = 0; ks < 2; ++ks) {
            const int k0 = ks * 16;
            uint32_t ah[4][4], al[4][4];
            #pragma unroll
            for (int mt = 0; mt < 4; ++mt) {
                uint32_t off = (uint32_t)(((wm + mt*16 + a_row) * PADH + k0 + a_col8) * 2);
                ldsm_x4(ah[mt], uAh + off);
                if (twoTerm) ldsm_x4(al[mt], uAl + off);
            }
            #pragma unroll
            for (int nt = 0; nt < 4; ++nt) {
                uint32_t boff = (uint32_t)(((wn + nt*8 + b_row) * PADH + k0 + b_col8) * 2);
                uint32_t bh[2];
                ldsm_x2(bh, uBh + boff);
                #pragma unroll
                for (int mt = 0; mt < 4; ++mt) {
                    mma16816(acc[mt][nt], ah[mt], bh);
                    if (twoTerm) mma16816(acc[mt][nt], al[mt], bh);
                }
            }
        }
        __syncthreads();
    }

    // epilogue
    #pragma unroll
    for (int mt = 0; mt < 4; ++mt) {
        int row = m0 + wm + mt * 16 + g;
        #pragma unroll
        for (int nt = 0; nt < 4; ++nt) {
            int col = n0 + wn + nt * 8 + t2;
            float b0 = bias[col], b1 = bias[col + 1];
            float v00 = acc[mt][nt][0] + b0, v01 = acc[mt][nt][1] + b1;
            float v10 = acc[mt][nt][2] + b0, v11 = acc[mt][nt][3] + b1;
            if (outF) {
                *(float2*)(outF + (size_t)row * N + col)       = make_float2(v00, v01);
                *(float2*)(outF + (size_t)(row + 8) * N + col) = make_float2(v10, v11);
            } else if (outLo) {
                __half h00 = __float2half_rn(v00);
                __half h01 = __float2half_rn(v01);
                __half h10 = __float2half_rn(v10);
                __half h11 = __float2half_rn(v11);
                *(uint32_t*)(outHi + (size_t)row * N + col)       = pack_h2(h00, h01);
                *(uint32_t*)(outHi + (size_t)(row + 8) * N + col) = pack_h2(h10, h11);
                *(uint32_t*)(outLo + (size_t)row * N + col) = pack_h2(
                    __float2half_rn(v00 - __half2float(h00)),
                    __float2half_rn(v01 - __half2float(h01)));
                *(uint32_t*)(outLo + (size_t)(row + 8) * N + col) = pack_h2(
                    __float2half_rn(v10 - __half2float(h10)),
                    __float2half_rn(v11 - __half2float(h11)));
            } else {
                *(uint32_t*)(outHi + (size_t)row * N + col) =
                    pack_h2(__float2half_rn(v00), __float2half_rn(v01));
                *(uint32_t*)(outHi + (size_t)(row + 8) * N + col) =
                    pack_h2(__float2half_rn(v10), __float2half_rn(v11));
            }
        }
    }
}

// ---------------- split fp32 -> fp16 hi/lo (no transpose) -------------------
__global__ __launch_bounds__(256) void split_rows(
    const float* __restrict__ X, __half* __restrict__ Hi,
    __half* __restrict__ Lo)
{
    size_t e0 = ((size_t)blockIdx.x * 256 + threadIdx.x) * 4;
    float4 v = *(const float4*)(X + e0);
    __half h0 = __float2half_rn(v.x), h1 = __float2half_rn(v.y);
    __half h2 = __float2half_rn(v.z), h3 = __float2half_rn(v.w);
    uint2 hh = make_uint2(pack_h2(h0, h1), pack_h2(h2, h3));
    uint2 ll = make_uint2(
        pack_h2(__float2half_rn(v.x - __half2float(h0)),
                __float2half_rn(v.y - __half2float(h1))),
        pack_h2(__float2half_rn(v.z - __half2float(h2)),
                __float2half_rn(v.w - __half2float(h3))));
    *(uint2*)(Hi + e0) = hh;
    *(uint2*)(Lo + e0) = ll;
}

// ------- weight transpose + round: W[K,N] -> Wt[N,K] fp16 -------------------
__global__ __launch_bounds__(256) void round_weightT(
    const float* __restrict__ W, __half* __restrict__ Wh, int K, int N)
{
    __shared__ float t[32][33];
    int kb = blockIdx.y * 32, nb = blockIdx.x * 32;
    int x = threadIdx.x & 31, y = threadIdx.x >> 5;
    #pragma unroll
    for (int i = 0; i < 32; i += 8)
        t[y + i][x] = W[(size_t)(kb + y + i) * N + nb + x];
    __syncthreads();
    #pragma unroll
    for (int i = 0; i < 32; i += 8)
        Wh[(size_t)(nb + y + i) * K + kb + x] = __float2half_rn(t[x][y + i]);
}

// ---------------- rope cos/sin table ----------------------------------------
__global__ __launch_bounds__(128) void rope_table()
{
    int idx = blockIdx.x * 128 + threadIdx.x;    // T_*32
    int t = idx >> 5, j = idx & 31;
    const float LOG2_1E4 = 13.2877123795494f;
    float freq = exp2f(-(float)j * (LOG2_1E4 / 32.f));
    float s, c;
    sincosf((float)t * freq, &s, &c);
    g_RopC[idx] = c;
    g_RopS[idx] = s;
}

// ------- context[b,h] = sum_t rope_elu(k)(t) outer v(t); ksum too -----------
__global__ __launch_bounds__(256) void context_kernel()
{
    const int p  = blockIdx.y;
    const int b  = p >> 3;
    const int h  = p & 7;
    const int t0 = blockIdx.x * 256;

    __shared__ float Ks[32][64];
    __shared__ float Vs[32][64];

    const int tid = threadIdx.x;
    const int tx  = tid & 15;
    const int ty  = tid >> 4;
    const int kr_ = tid >> 3;          // 0..31
    const int kc4 = (tid & 7) * 4;     // 0..28

    float acc[4][4];
    #pragma unroll
    for (int i = 0; i < 4; ++i)
        #pragma unroll
        for (int j = 0; j < 4; ++j) acc[i][j] = 0.f;
    float ksm[4] = {0.f, 0.f, 0.f, 0.f};

    for (int tt = 0; tt < 256; tt += 32) {
        {
            int t = t0 + tt + kr_;
            const __half* kp = g_KV + (size_t)(b * T_ + t) * 1024 + h * 128;
            float x1[4], x2[4];
            ld4h(kp + kc4, x1);
            ld4h(kp + 32 + kc4, x2);
            float4 cs = *(const float4*)(g_RopC + t * 32 + kc4);
            float4 sn = *(const float4*)(g_RopS + t * 32 + kc4);
            Ks[kr_][kc4+0]    = elu1(x1[0]*cs.x - x2[0]*sn.x);
            Ks[kr_][kc4+1]    = elu1(x1[1]*cs.y - x2[1]*sn.y);
            Ks[kr_][kc4+2]    = elu1(x1[2]*cs.z - x2[2]*sn.z);
            Ks[kr_][kc4+3]    = elu1(x1[3]*cs.w - x2[3]*sn.w);
            Ks[kr_][kc4+32]   = elu1(x1[0]*sn.x + x2[0]*cs.x);
            Ks[kr_][kc4+33]   = elu1(x1[1]*sn.y + x2[1]*cs.y);
            Ks[kr_][kc4+34]   = elu1(x1[2]*sn.z + x2[2]*cs.z);
            Ks[kr_][kc4+35]   = elu1(x1[3]*sn.w + x2[3]*cs.w);
        }
        #pragma unroll
        for (int ii = 0; ii < 2; ++ii) {
            int i = tid + ii * 256;
            int r = i >> 4;
            int c = (i & 15) * 4;
            const __half* vp = g_KV + (size_t)(b * T_ + t0 + tt + r) * 1024 + h * 128 + 64;
            float vv[4];
            ld4h(vp + c, vv);
            Vs[r][c]   = vv[0]; Vs[r][c+1] = vv[1];
            Vs[r][c+2] = vv[2]; Vs[r][c+3] = vv[3];
        }
        __syncthreads();
        #pragma unroll 8
        for (int t = 0; t < 32; ++t) {
            float kr[4], vr[4];
            *(float4*)kr = *(const float4*)&Ks[t][ty*4];
            *(float4*)vr = *(const float4*)&Vs[t][tx*4];
            #pragma unroll
            for (int i = 0; i < 4; ++i)
                #pragma unroll
                for (int j = 0; j < 4; ++j)
                    acc[i][j] = fmaf(kr[i], vr[j], acc[i][j]);
            if (tx == 0) {
                #pragma unroll
                for (int i = 0; i < 4; ++i) ksm[i] += kr[i];
            }
        }
        __syncthreads();
    }

    float* ctx = g_Ctx + (size_t)p * HD * HD;
    #pragma unroll
    for (int i = 0; i < 4; ++i)
        #pragma unroll
        for (int j = 0; j < 4; ++j)
            atomicAdd(&ctx[(ty*4 + i) * HD + tx*4 + j], acc[i][j]);
    if (tx == 0) {
        #pragma unroll
        for (int i = 0; i < 4; ++i)
            atomicAdd(&g_Ksum[p * HD + ty*4 + i], ksm[i]);
    }
}

// ------- M_b[n][h*64+d] = (1/S) * sum_e Ctx_{b,h}[d][e] * Wo[h*64+e][n] -----
__global__ __launch_bounds__(256) void mker(const float* __restrict__ Wo)
{
    const int n0 = blockIdx.x * 64;
    const int p  = blockIdx.y;           // b*8 + h
    const int b  = p >> 3;
    const int h  = p & 7;

    __shared__ float Ct[64][65];
    __shared__ float Ws[16][68];

    const int tid = threadIdx.x;
    const int tx  = tid & 15;
    const int ty  = tid >> 4;

    const float* ctx = g_Ctx + (size_t)p * HD * HD;
    #pragma unroll
    for (int i = 0; i < 16; ++i) {
        int lin = tid + i * 256;
        Ct[lin >> 6][lin & 63] = ctx[lin];
    }

    float acc[4][4];
    #pragma unroll
    for (int i = 0; i < 4; ++i)
        #pragma unroll
        for (int j = 0; j < 4; ++j) acc[i][j] = 0.f;

    for (int e0 = 0; e0 < 64; e0 += 16) {
        __syncthreads();
        {
            int e_l = tid >> 4;          // 0..15
            int n_l = (tid & 15) * 4;
            float4 w = *(const float4*)(Wo + (size_t)(h*64 + e0 + e_l) * 512 + n0 + n_l);
            Ws[e_l][n_l]   = w.x; Ws[e_l][n_l+1] = w.y;
            Ws[e_l][n_l+2] = w.z; Ws[e_l][n_l+3] = w.w;
        }
        __syncthreads();
        #pragma unroll
        for (int e = 0; e < 16; ++e) {
            float c0 = Ct[ty*4+0][e0+e];
            float c1 = Ct[ty*4+1][e0+e];
            float c2 = Ct[ty*4+2][e0+e];
            float c3 = Ct[ty*4+3][e0+e];
            float4 w = *(const float4*)&Ws[e][tx*4];
            acc[0][0] = fmaf(c0, w.x, acc[0][0]); acc[0][1] = fmaf(c0, w.y, acc[0][1]);
            acc[0][2] = fmaf(c0, w.z, acc[0][2]); acc[0][3] = fmaf(c0, w.w, acc[0][3]);
            acc[1][0] = fmaf(c1, w.x, acc[1][0]); acc[1][1] = fmaf(c1, w.y, acc[1][1]);
            acc[1][2] = fmaf(c1, w.z, acc[1][2]); acc[1][3] = fmaf(c1, w.w, acc[1][3]);
            acc[2][0] = fmaf(c2, w.x, acc[2][0]); acc[2][1] = fmaf(c2, w.y, acc[2][1]);
            acc[2][2] = fmaf(c2, w.z, acc[2][2]); acc[2][3] = fmaf(c2, w.w, acc[2][3]);
            acc[3][0] = fmaf(c3, w.x, acc[3][0]); acc[3][1] = fmaf(c3, w.y, acc[3][1]);
            acc[3][2] = fmaf(c3, w.z, acc[3][2]); acc[3][3] = fmaf(c3, w.w, acc[3][3]);
        }
    }

    // write fp16, transposed into B-layout [n][k=h*64+d], scaled by 1/S
    __half* Mb = g_M + (size_t)b * 512 * 512;
    #pragma unroll
    for (int j = 0; j < 4; ++j) {
        int n = n0 + tx*4 + j;
        #pragma unroll
        for (int i = 0; i < 4; ++i) {
            int d = ty*4 + i;
            Mb[(size_t)n * 512 + h*64 + d] = __float2half_rn(acc[i][j] * INV_ZSCALE);
        }
    }
}

// ------- qprep: Q'' = (S*z) * elu1(rope(q)); writes fp16 -------------------
__global__ __launch_bounds__(256) void qprep_kernel()
{
    const int h  = blockIdx.y;
    const int r0 = blockIdx.x * 64;
    const int b  = r0 >> 12;
    const int p  = b * NH + h;

    __shared__ float Qs[64][65];
    __shared__ float ks[64];
    __shared__ float zs[64];

    const int tid = threadIdx.x;

    if (tid < 64) ks[tid] = g_Ksum[p * HD + tid];

    #pragma unroll
    for (int ii = 0; ii < 2; ++ii) {
        int i = tid + ii * 256;
        int r = i >> 3;
        int c4 = (i & 7) * 4;
        int t = (r0 + r) & (T_ - 1);
        size_t base = (size_t)(r0 + r) * DM + h * HD;
        float4 x1 = *(const float4*)(g_Q + base + c4);
        float4 x2 = *(const float4*)(g_Q + base + 32 + c4);
        float4 cs = *(const float4*)(g_RopC + t * 32 + c4);
        float4 sn = *(const float4*)(g_RopS + t * 32 + c4);
        Qs[r][c4+0]  = elu1(x1.x*cs.x - x2.x*sn.x);
        Qs[r][c4+1]  = elu1(x1.y*cs.y - x2.y*sn.y);
        Qs[r][c4+2]  = elu1(x1.z*cs.z - x2.z*sn.z);
        Qs[r][c4+3]  = elu1(x1.w*cs.w - x2.w*sn.w);
        Qs[r][c4+32] = elu1(x1.x*sn.x + x2.x*cs.x);
        Qs[r][c4+33] = elu1(x1.y*sn.y + x2.y*cs.y);
        Qs[r][c4+34] = elu1(x1.z*sn.z + x2.z*cs.z);
        Qs[r][c4+35] = elu1(x1.w*sn.w + x2.w*cs.w);
    }
    __syncthreads();

    if (tid < 64) {
        float dsum = 0.f;
        #pragma unroll
        for (int d = 0; d < 64; ++d) dsum += Qs[tid][d] * ks[d];
        zs[tid] = ZSCALE / (dsum + 1e-6f);
    }
    __syncthreads();

    #pragma unroll
    for (int ii = 0; ii < 2; ++ii) {
        int i = tid + ii * 256;
        int r = i >> 3;
        int c4 = (i & 7) * 4;
        float z = zs[r];
        size_t base = (size_t)(r0 + r) * DM + h * HD;
        #pragma unroll
        for (int half_sel = 0; half_sel < 2; ++half_sel) {
            int c = c4 + half_sel * 32;
            float v0 = Qs[r][c+0] * z, v1 = Qs[r][c+1] * z;
            float v2 = Qs[r][c+2] * z, v3 = Qs[r][c+3] * z;
            *(uint2*)(g_QsH + base + c) = make_uint2(
                pack_h2(__float2half_rn(v0), __float2half_rn(v1)),
                pack_h2(__float2half_rn(v2), __float2half_rn(v3)));
        }
    }
}

// ---------------------------------------------------------------------------
extern "C" void kernel_launch(void* const* d_in, const int* in_sizes, int n_in,
                              void* d_out, int out_size)
{
    const float* x  = (const float*)d_in[0];
    const float* Wq = (const float*)d_in[1];
    const float* bq = (const float*)d_in[2];
    const float* Wd = (const float*)d_in[3];
    const float* bd = (const float*)d_in[4];
    const float* Wu = (const float*)d_in[5];
    const float* bu = (const float*)d_in[6];
    const float* Wo = (const float*)d_in[7];
    const float* bo = (const float*)d_in[8];
    float* out = (float*)d_out;

    float *pQ, *pCtx, *pKsum;
    __half *pKV, *pXh, *pXl, *pCh, *pCl, *pQsH, *pM;
    __half *pWqH, *pWdH, *pWuH;
    cudaGetSymbolAddress((void**)&pQ,    g_Q);
    cudaGetSymbolAddress((void**)&pKV,   g_KV);
    cudaGetSymbolAddress((void**)&pCtx,  g_Ctx);
    cudaGetSymbolAddress((void**)&pKsum, g_Ksum);
    cudaGetSymbolAddress((void**)&pXh,   g_Xhi);
    cudaGetSymbolAddress((void**)&pXl,   g_Xlo);
    cudaGetSymbolAddress((void**)&pCh,   g_Chi);
    cudaGetSymbolAddress((void**)&pCl,   g_Clo);
    cudaGetSymbolAddress((void**)&pQsH,  g_QsH);
    cudaGetSymbolAddress((void**)&pM,    g_M);
    cudaGetSymbolAddress((void**)&pWqH,  g_WqH);
    cudaGetSymbolAddress((void**)&pWdH,  g_WdH);
    cudaGetSymbolAddress((void**)&pWuH,  g_WuH);

    static bool init = false;
    static cudaStream_t s1;
    static cudaEvent_t evFork, evSplit, evQ;
    if (!init) {
        cudaStreamCreateWithFlags(&s1, cudaStreamNonBlocking);
        cudaEventCreateWithFlags(&evFork,  cudaEventDisableTiming);
        cudaEventCreateWithFlags(&evSplit, cudaEventDisableTiming);
        cudaEventCreateWithFlags(&evQ,     cudaEventDisableTiming);
        init = true;
    }

    // --- fork side stream early: Wq rounding has no deps ---------------------
    cudaEventRecord(evFork, 0);
    cudaStreamWaitEvent(s1, evFork, 0);
    round_weightT<<<dim3(512/32, 512/32), 256, 0, s1>>>(Wq, pWqH, 512, 512);

    // --- preprocessing (default stream) --------------------------------------
    cudaMemsetAsync(pCtx,  0, sizeof(float) * B_*NH*HD*HD);
    cudaMemsetAsync(pKsum, 0, sizeof(float) * B_*NH*HD);
    rope_table<<<T_*32/128, 128>>>();
    round_weightT<<<dim3(128/32, 512/32), 256>>>(Wd, pWdH, 512, 128);
    round_weightT<<<dim3(1024/32, 128/32), 256>>>(Wu, pWuH, 128, 1024);
    split_rows<<<(size_t)BT*512/4/256, 256>>>(x, pXh, pXl);
    cudaEventRecord(evSplit, 0);

    // --- side stream: Q = x @ Wq + bq (fp32; single fp16 term) ---------------
    cudaStreamWaitEvent(s1, evSplit, 0);
    bgemm2<<<dim3(4, BT/128), 256, 0, s1>>>(pXh, nullptr, pWqH, bq,
                                            pQ, nullptr, nullptr, 512, 512, 0);
    cudaEventRecord(evQ, s1);

    // --- default: C -> KV -> context -> M ------------------------------------
    bgemm2<<<dim3(1, BT/128), 256>>>(pXh, pXl, pWdH, bd,
                                     nullptr, pCh, pCl, 128, 512, 0);
    bgemm2<<<dim3(8, BT/128), 256>>>(pCh, pCl, pWuH, bu,
                                     nullptr, pKV, nullptr, 1024, 128, 0);
    context_kernel<<<dim3(T_/256, B_*NH), 256>>>();
    mker<<<dim3(8, 64), 256>>>(Wo);

    // --- join: qprep needs Q (side stream) + ksum (context) ------------------
    cudaStreamWaitEvent(0, evQ, 0);
    qprep_kernel<<<dim3(BT/64, NH), 256>>>();

    // out = Q'' @ M_b + bo  (per-batch B; single fp16 term)
    bgemm2<<<dim3(4, BT/128), 256>>>(pQsH, nullptr, pM, bo,
                                     out, nullptr, nullptr, 512, 512, 512*512);
}

// round 14
// speedup vs baseline: 1.5060x; 1.0280x over previous
#include <cuda_runtime.h>
#include <cuda_fp16.h>
#include <math.h>
#include <stdint.h>

#define B_   8
#define T_   4096
#define BT   (B_*T_)          // 32768 rows
#define DM   512
#define NH   8
#define HD   64

#define PADH 40               // smem row stride in halves (80B; conflict-free)
#define ZSCALE     16384.0f   // 2^14: keeps z*q' and M/S in fp16-normal range
#define INV_ZSCALE (1.0f/16384.0f)

// ---------------- scratch (static device globals; no allocation) ------------
__device__ float  g_Q   [(size_t)BT * DM];     // Q fp32 (raw; roped in qprep)
__device__ __half g_KV  [(size_t)BT * 1024];   // kv fp16 (rounded once)
__device__ float  g_Ctx [B_*NH*HD*HD];
__device__ float  g_Ksum[B_*NH*HD];
__device__ float  g_RopC[T_*32];
__device__ float  g_RopS[T_*32];

__device__ __half g_Xhi[(size_t)BT*DM],  g_Xlo[(size_t)BT*DM];
__device__ __half g_Chi[(size_t)BT*128];
__device__ __half g_QsH[(size_t)BT*DM];                         // z-scaled q' (fp16)
__device__ __half g_M  [(size_t)B_*512*512];                    // per-batch Ctx@Wo / S
__device__ __half g_WqH[512*512];
__device__ __half g_WdH[128*512];
__device__ __half g_WuH[1024*128];

// ---------------- helpers ---------------------------------------------------
__device__ __forceinline__ uint32_t smem_u32(const void* p) {
    uint32_t a;
    asm("{ .reg .u64 t; cvta.to.shared.u64 t, %1; cvt.u32.u64 %0, t; }"
        : "=r"(a) : "l"(p));
    return a;
}
__device__ __forceinline__ void mma16816(float* d, const uint32_t* a, const uint32_t* b)
{
    asm volatile(
        "mma.sync.aligned.m16n8k16.row.col.f32.f16.f16.f32 "
        "{%0,%1,%2,%3}, {%4,%5,%6,%7}, {%8,%9}, {%0,%1,%2,%3};"
        : "+f"(d[0]), "+f"(d[1]), "+f"(d[2]), "+f"(d[3])
        : "r"(a[0]), "r"(a[1]), "r"(a[2]), "r"(a[3]), "r"(b[0]), "r"(b[1]));
}
__device__ __forceinline__ void ldsm_x4(uint32_t* r, uint32_t addr) {
    asm volatile("ldmatrix.sync.aligned.m8n8.x4.shared.b16 {%0,%1,%2,%3}, [%4];"
        : "=r"(r[0]), "=r"(r[1]), "=r"(r[2]), "=r"(r[3]) : "r"(addr));
}
__device__ __forceinline__ void ldsm_x2(uint32_t* r, uint32_t addr) {
    asm volatile("ldmatrix.sync.aligned.m8n8.x2.shared.b16 {%0,%1}, [%2];"
        : "=r"(r[0]), "=r"(r[1]) : "r"(addr));
}
__device__ __forceinline__ uint32_t pack_h2(__half a, __half b)
{
    __half2 p = __halves2half2(a, b);
    return *(uint32_t*)&p;
}
// load 4 consecutive halves -> 4 floats
__device__ __forceinline__ void ld4h(const __half* p, float* o)
{
    uint2 u = *(const uint2*)p;
    const __half2* h = (const __half2*)&u;
    float2 a = __half22float2(h[0]);
    float2 b = __half22float2(h[1]);
    o[0] = a.x; o[1] = a.y; o[2] = b.x; o[3] = b.y;
}

// ---- elu(x)+1, branchless, FMA/ALU pipes only (no MUFU) --------------------
__device__ __forceinline__ float elu1(float x)
{
    float t = fminf(x, 0.f) * 1.44269504089f;   // log2(e); t <= 0
    t = fmaxf(t, -28.f);                        // exp underflow clamp
    float n = rintf(t);
    float f = t - n;                            // [-0.5, 0.5]
    float p = 1.33336498402e-3f;                // Taylor(2^f), err ~2.4e-6
    p = fmaf(p, f, 9.61812910763e-3f);
    p = fmaf(p, f, 5.55041086648e-2f);
    p = fmaf(p, f, 2.40226506959e-1f);
    p = fmaf(p, f, 6.93147180560e-1f);
    p = fmaf(p, f, 1.0f);
    float e = __int_as_float(((int)n + 127) << 23) * p;   // 2^n * 2^f
    return (x > 0.f) ? (x + 1.f) : e;
}

// ========== fp16 GEMM: D = (Ah [+ Al]) @ Bh^T + bias ========================
// 128x128 tile, BK=32, 256 threads (8 warps 2x4), warp tile 64x32.
// Alo == nullptr -> single-term fp16 GEMM (half the MMAs).
// Output modes: outF -> fp32; else outLo -> fp16 hi/lo; else outHi fp16 single.
// bStride: per-batch B stride (batch = m0>>12), 0 for shared B.
__global__ __launch_bounds__(256) void bgemm2(
    const __half* __restrict__ Ahi, const __half* __restrict__ Alo,
    const __half* __restrict__ Bh16,
    const float* __restrict__ bias,
    float* __restrict__ outF,
    __half* __restrict__ outHi, __half* __restrict__ outLo,
    int N, int K, int bStride)
{
    __shared__ __half sAh[128*PADH];
    __shared__ __half sAl[128*PADH];
    __shared__ __half sBh[128*PADH];

    const int tid  = threadIdx.x;
    const int lane = tid & 31;
    const int wid  = tid >> 5;
    const int wm   = (wid >> 2) * 64;
    const int wn   = (wid & 3) * 32;
    const int g    = lane >> 2;
    const int t2   = (lane & 3) * 2;
    const int m0   = blockIdx.y * 128;
    const int n0   = blockIdx.x * 128;

    const bool twoTerm = (Alo != nullptr);

    const int lrow = tid >> 2;           // 0..63
    const int lseg = tid & 3;            // 16B seg within 64B row

    const __half* gA0 = Ahi  + (size_t)(m0 + lrow) * K + lseg * 8;
    const __half* gA1 = twoTerm ? (Alo + (size_t)(m0 + lrow) * K + lseg * 8) : gA0;
    const __half* gB0 = Bh16 + (size_t)(m0 >> 12) * bStride
                             + (size_t)(n0 + lrow) * K + lseg * 8;
    const size_t rstep = (size_t)64 * K;

    const int a_row  = ((lane >> 3) & 1) * 8 + (lane & 7);
    const int a_col8 = (lane >> 4) * 8;
    const int b_row  = (lane & 7);
    const int b_col8 = ((lane >> 3) & 1) * 8;

    const uint32_t uAh = smem_u32(sAh);
    const uint32_t uAl = smem_u32(sAl);
    const uint32_t uBh = smem_u32(sBh);

    const uint32_t soff  = (uint32_t)(lrow * (PADH*2) + lseg * 16);
    const uint32_t soff2 = soff + (uint32_t)(64 * PADH * 2);

    const int nch = K >> 5;

    uint4 pA0[2], pA1[2], pB0[2];
    pA0[0] = *(const uint4*)gA0; pA0[1] = *(const uint4*)(gA0 + rstep);
    pB0[0] = *(const uint4*)gB0; pB0[1] = *(const uint4*)(gB0 + rstep);
    if (twoTerm) { pA1[0] = *(const uint4*)gA1; pA1[1] = *(const uint4*)(gA1 + rstep); }

    float acc[4][4][4];
    #pragma unroll
    for (int mt = 0; mt < 4; ++mt)
        #pragma unroll
        for (int nt = 0; nt < 4; ++nt)
            #pragma unroll
            for (int i = 0; i < 4; ++i) acc[mt][nt][i] = 0.f;

    for (int ch = 0; ch < nch; ++ch) {
        *(uint4*)((char*)sAh + soff)  = pA0[0];
        *(uint4*)((char*)sAh + soff2) = pA0[1];
        if (twoTerm) {
            *(uint4*)((char*)sAl + soff)  = pA1[0];
            *(uint4*)((char*)sAl + soff2) = pA1[1];
        }
        *(uint4*)((char*)sBh + soff)  = pB0[0];
        *(uint4*)((char*)sBh + soff2) = pB0[1];
        __syncthreads();

        if (ch + 1 < nch) {
            const int ko = (ch + 1) * 32;
            pA0[0] = *(const uint4*)(gA0 + ko); pA0[1] = *(const uint4*)(gA0 + rstep + ko);
            pB0[0] = *(const uint4*)(gB0 + ko); pB0[1] = *(const uint4*)(gB0 + rstep + ko);
            if (twoTerm) {
                pA1[0] = *(const uint4*)(gA1 + ko);
                pA1[1] = *(const uint4*)(gA1 + rstep + ko);
            }
        }

        #pragma unroll
        for (int ks = 0; ks < 2; ++ks) {
            const int k0 = ks * 16;
            uint32_t ah[4][4], al[4][4];
            #pragma unroll
            for (int mt = 0; mt < 4; ++mt) {
                uint32_t off = (uint32_t)(((wm + mt*16 + a_row) * PADH + k0 + a_col8) * 2);
                ldsm_x4(ah[mt], uAh + off);
                if (twoTerm) ldsm_x4(al[mt], uAl + off);
            }
            #pragma unroll
            for (int nt = 0; nt < 4; ++nt) {
                uint32_t boff = (uint32_t)(((wn + nt*8 + b_row) * PADH + k0 + b_col8) * 2);
                uint32_t bh[2];
                ldsm_x2(bh, uBh + boff);
                #pragma unroll
                for (int mt = 0; mt < 4; ++mt) {
                    mma16816(acc[mt][nt], ah[mt], bh);
                    if (twoTerm) mma16816(acc[mt][nt], al[mt], bh);
                }
            }
        }
        __syncthreads();
    }

    // epilogue
    #pragma unroll
    for (int mt = 0; mt < 4; ++mt) {
        int row = m0 + wm + mt * 16 + g;
        #pragma unroll
        for (int nt = 0; nt < 4; ++nt) {
            int col = n0 + wn + nt * 8 + t2;
            float b0 = bias[col], b1 = bias[col + 1];
            float v00 = acc[mt][nt][0] + b0, v01 = acc[mt][nt][1] + b1;
            float v10 = acc[mt][nt][2] + b0, v11 = acc[mt][nt][3] + b1;
            if (outF) {
                *(float2*)(outF + (size_t)row * N + col)       = make_float2(v00, v01);
                *(float2*)(outF + (size_t)(row + 8) * N + col) = make_float2(v10, v11);
            } else if (outLo) {
                __half h00 = __float2half_rn(v00);
                __half h01 = __float2half_rn(v01);
                __half h10 = __float2half_rn(v10);
                __half h11 = __float2half_rn(v11);
                *(uint32_t*)(outHi + (size_t)row * N + col)       = pack_h2(h00, h01);
                *(uint32_t*)(outHi + (size_t)(row + 8) * N + col) = pack_h2(h10, h11);
                *(uint32_t*)(outLo + (size_t)row * N + col) = pack_h2(
                    __float2half_rn(v00 - __half2float(h00)),
                    __float2half_rn(v01 - __half2float(h01)));
                *(uint32_t*)(outLo + (size_t)(row + 8) * N + col) = pack_h2(
                    __float2half_rn(v10 - __half2float(h10)),
                    __float2half_rn(v11 - __half2float(h11)));
            } else {
                *(uint32_t*)(outHi + (size_t)row * N + col) =
                    pack_h2(__float2half_rn(v00), __float2half_rn(v01));
                *(uint32_t*)(outHi + (size_t)(row + 8) * N + col) =
                    pack_h2(__float2half_rn(v10), __float2half_rn(v11));
            }
        }
    }
}

// ---------------- split fp32 -> fp16 hi/lo (no transpose) -------------------
__global__ __launch_bounds__(256) void split_rows(
    const float* __restrict__ X, __half* __restrict__ Hi,
    __half* __restrict__ Lo)
{
    size_t e0 = ((size_t)blockIdx.x * 256 + threadIdx.x) * 4;
    float4 v = *(const float4*)(X + e0);
    __half h0 = __float2half_rn(v.x), h1 = __float2half_rn(v.y);
    __half h2 = __float2half_rn(v.z), h3 = __float2half_rn(v.w);
    uint2 hh = make_uint2(pack_h2(h0, h1), pack_h2(h2, h3));
    uint2 ll = make_uint2(
        pack_h2(__float2half_rn(v.x - __half2float(h0)),
                __float2half_rn(v.y - __half2float(h1))),
        pack_h2(__float2half_rn(v.z - __half2float(h2)),
                __float2half_rn(v.w - __half2float(h3))));
    *(uint2*)(Hi + e0) = hh;
    *(uint2*)(Lo + e0) = ll;
}

// ------- weight transpose + round: W[K,N] -> Wt[N,K] fp16 -------------------
__global__ __launch_bounds__(256) void round_weightT(
    const float* __restrict__ W, __half* __restrict__ Wh, int K, int N)
{
    __shared__ float t[32][33];
    int kb = blockIdx.y * 32, nb = blockIdx.x * 32;
    int x = threadIdx.x & 31, y = threadIdx.x >> 5;
    #pragma unroll
    for (int i = 0; i < 32; i += 8)
        t[y + i][x] = W[(size_t)(kb + y + i) * N + nb + x];
    __syncthreads();
    #pragma unroll
    for (int i = 0; i < 32; i += 8)
        Wh[(size_t)(nb + y + i) * K + kb + x] = __float2half_rn(t[x][y + i]);
}

// ---------------- rope cos/sin table ----------------------------------------
__global__ __launch_bounds__(128) void rope_table()
{
    int idx = blockIdx.x * 128 + threadIdx.x;    // T_*32
    int t = idx >> 5, j = idx & 31;
    const float LOG2_1E4 = 13.2877123795494f;
    float freq = exp2f(-(float)j * (LOG2_1E4 / 32.f));
    float s, c;
    sincosf((float)t * freq, &s, &c);
    g_RopC[idx] = c;
    g_RopS[idx] = s;
}

// ------- context[b,h] = sum_t rope_elu(k)(t) outer v(t); ksum too -----------
__global__ __launch_bounds__(256) void context_kernel()
{
    const int p  = blockIdx.y;
    const int b  = p >> 3;
    const int h  = p & 7;
    const int t0 = blockIdx.x * 256;

    __shared__ float Ks[32][64];
    __shared__ float Vs[32][64];

    const int tid = threadIdx.x;
    const int tx  = tid & 15;
    const int ty  = tid >> 4;
    const int kr_ = tid >> 3;          // 0..31
    const int kc4 = (tid & 7) * 4;     // 0..28

    float acc[4][4];
    #pragma unroll
    for (int i = 0; i < 4; ++i)
        #pragma unroll
        for (int j = 0; j < 4; ++j) acc[i][j] = 0.f;
    float ksm[4] = {0.f, 0.f, 0.f, 0.f};

    for (int tt = 0; tt < 256; tt += 32) {
        {
            int t = t0 + tt + kr_;
            const __half* kp = g_KV + (size_t)(b * T_ + t) * 1024 + h * 128;
            float x1[4], x2[4];
            ld4h(kp + kc4, x1);
            ld4h(kp + 32 + kc4, x2);
            float4 cs = *(const float4*)(g_RopC + t * 32 + kc4);
            float4 sn = *(const float4*)(g_RopS + t * 32 + kc4);
            Ks[kr_][kc4+0]    = elu1(x1[0]*cs.x - x2[0]*sn.x);
            Ks[kr_][kc4+1]    = elu1(x1[1]*cs.y - x2[1]*sn.y);
            Ks[kr_][kc4+2]    = elu1(x1[2]*cs.z - x2[2]*sn.z);
            Ks[kr_][kc4+3]    = elu1(x1[3]*cs.w - x2[3]*sn.w);
            Ks[kr_][kc4+32]   = elu1(x1[0]*sn.x + x2[0]*cs.x);
            Ks[kr_][kc4+33]   = elu1(x1[1]*sn.y + x2[1]*cs.y);
            Ks[kr_][kc4+34]   = elu1(x1[2]*sn.z + x2[2]*cs.z);
            Ks[kr_][kc4+35]   = elu1(x1[3]*sn.w + x2[3]*cs.w);
        }
        #pragma unroll
        for (int ii = 0; ii < 2; ++ii) {
            int i = tid + ii * 256;
            int r = i >> 4;
            int c = (i & 15) * 4;
            const __half* vp = g_KV + (size_t)(b * T_ + t0 + tt + r) * 1024 + h * 128 + 64;
            float vv[4];
            ld4h(vp + c, vv);
            Vs[r][c]   = vv[0]; Vs[r][c+1] = vv[1];
            Vs[r][c+2] = vv[2]; Vs[r][c+3] = vv[3];
        }
        __syncthreads();
        #pragma unroll 8
        for (int t = 0; t < 32; ++t) {
            float kr[4], vr[4];
            *(float4*)kr = *(const float4*)&Ks[t][ty*4];
            *(float4*)vr = *(const float4*)&Vs[t][tx*4];
            #pragma unroll
            for (int i = 0; i < 4; ++i)
                #pragma unroll
                for (int j = 0; j < 4; ++j)
                    acc[i][j] = fmaf(kr[i], vr[j], acc[i][j]);
            if (tx == 0) {
                #pragma unroll
                for (int i = 0; i < 4; ++i) ksm[i] += kr[i];
            }
        }
        __syncthreads();
    }

    float* ctx = g_Ctx + (size_t)p * HD * HD;
    #pragma unroll
    for (int i = 0; i < 4; ++i)
        #pragma unroll
        for (int j = 0; j < 4; ++j)
            atomicAdd(&ctx[(ty*4 + i) * HD + tx*4 + j], acc[i][j]);
    if (tx == 0) {
        #pragma unroll
        for (int i = 0; i < 4; ++i)
            atomicAdd(&g_Ksum[p * HD + ty*4 + i], ksm[i]);
    }
}

// ------- M_b[n][h*64+d] = (1/S) * sum_e Ctx_{b,h}[d][e] * Wo[h*64+e][n] -----
__global__ __launch_bounds__(256) void mker(const float* __restrict__ Wo)
{
    const int n0 = blockIdx.x * 64;
    const int p  = blockIdx.y;           // b*8 + h
    const int b  = p >> 3;
    const int h  = p & 7;

    __shared__ float Ct[64][65];
    __shared__ float Ws[16][68];

    const int tid = threadIdx.x;
    const int tx  = tid & 15;
    const int ty  = tid >> 4;

    const float* ctx = g_Ctx + (size_t)p * HD * HD;
    #pragma unroll
    for (int i = 0; i < 16; ++i) {
        int lin = tid + i * 256;
        Ct[lin >> 6][lin & 63] = ctx[lin];
    }

    float acc[4][4];
    #pragma unroll
    for (int i = 0; i < 4; ++i)
        #pragma unroll
        for (int j = 0; j < 4; ++j) acc[i][j] = 0.f;

    for (int e0 = 0; e0 < 64; e0 += 16) {
        __syncthreads();
        {
            int e_l = tid >> 4;          // 0..15
            int n_l = (tid & 15) * 4;
            float4 w = *(const float4*)(Wo + (size_t)(h*64 + e0 + e_l) * 512 + n0 + n_l);
            Ws[e_l][n_l]   = w.x; Ws[e_l][n_l+1] = w.y;
            Ws[e_l][n_l+2] = w.z; Ws[e_l][n_l+3] = w.w;
        }
        __syncthreads();
        #pragma unroll
        for (int e = 0; e < 16; ++e) {
            float c0 = Ct[ty*4+0][e0+e];
            float c1 = Ct[ty*4+1][e0+e];
            float c2 = Ct[ty*4+2][e0+e];
            float c3 = Ct[ty*4+3][e0+e];
            float4 w = *(const float4*)&Ws[e][tx*4];
            acc[0][0] = fmaf(c0, w.x, acc[0][0]); acc[0][1] = fmaf(c0, w.y, acc[0][1]);
            acc[0][2] = fmaf(c0, w.z, acc[0][2]); acc[0][3] = fmaf(c0, w.w, acc[0][3]);
            acc[1][0] = fmaf(c1, w.x, acc[1][0]); acc[1][1] = fmaf(c1, w.y, acc[1][1]);
            acc[1][2] = fmaf(c1, w.z, acc[1][2]); acc[1][3] = fmaf(c1, w.w, acc[1][3]);
            acc[2][0] = fmaf(c2, w.x, acc[2][0]); acc[2][1] = fmaf(c2, w.y, acc[2][1]);
            acc[2][2] = fmaf(c2, w.z, acc[2][2]); acc[2][3] = fmaf(c2, w.w, acc[2][3]);
            acc[3][0] = fmaf(c3, w.x, acc[3][0]); acc[3][1] = fmaf(c3, w.y, acc[3][1]);
            acc[3][2] = fmaf(c3, w.z, acc[3][2]); acc[3][3] = fmaf(c3, w.w, acc[3][3]);
        }
    }

    // write fp16, transposed into B-layout [n][k=h*64+d], scaled by 1/S
    __half* Mb = g_M + (size_t)b * 512 * 512;
    #pragma unroll
    for (int j = 0; j < 4; ++j) {
        int n = n0 + tx*4 + j;
        #pragma unroll
        for (int i = 0; i < 4; ++i) {
            int d = ty*4 + i;
            Mb[(size_t)n * 512 + h*64 + d] = __float2half_rn(acc[i][j] * INV_ZSCALE);
        }
    }
}

// ------- qprep: Q'' = (S*z) * elu1(rope(q)); writes fp16 -------------------
__global__ __launch_bounds__(256) void qprep_kernel()
{
    const int h  = blockIdx.y;
    const int r0 = blockIdx.x * 64;
    const int b  = r0 >> 12;
    const int p  = b * NH + h;

    __shared__ float Qs[64][65];
    __shared__ float ks[64];
    __shared__ float zs[64];

    const int tid = threadIdx.x;

    if (tid < 64) ks[tid] = g_Ksum[p * HD + tid];

    #pragma unroll
    for (int ii = 0; ii < 2; ++ii) {
        int i = tid + ii * 256;
        int r = i >> 3;
        int c4 = (i & 7) * 4;
        int t = (r0 + r) & (T_ - 1);
        size_t base = (size_t)(r0 + r) * DM + h * HD;
        float4 x1 = *(const float4*)(g_Q + base + c4);
        float4 x2 = *(const float4*)(g_Q + base + 32 + c4);
        float4 cs = *(const float4*)(g_RopC + t * 32 + c4);
        float4 sn = *(const float4*)(g_RopS + t * 32 + c4);
        Qs[r][c4+0]  = elu1(x1.x*cs.x - x2.x*sn.x);
        Qs[r][c4+1]  = elu1(x1.y*cs.y - x2.y*sn.y);
        Qs[r][c4+2]  = elu1(x1.z*cs.z - x2.z*sn.z);
        Qs[r][c4+3]  = elu1(x1.w*cs.w - x2.w*sn.w);
        Qs[r][c4+32] = elu1(x1.x*sn.x + x2.x*cs.x);
        Qs[r][c4+33] = elu1(x1.y*sn.y + x2.y*cs.y);
        Qs[r][c4+34] = elu1(x1.z*sn.z + x2.z*cs.z);
        Qs[r][c4+35] = elu1(x1.w*sn.w + x2.w*cs.w);
    }
    __syncthreads();

    if (tid < 64) {
        float dsum = 0.f;
        #pragma unroll
        for (int d = 0; d < 64; ++d) dsum += Qs[tid][d] * ks[d];
        zs[tid] = ZSCALE / (dsum + 1e-6f);
    }
    __syncthreads();

    #pragma unroll
    for (int ii = 0; ii < 2; ++ii) {
        int i = tid + ii * 256;
        int r = i >> 3;
        int c4 = (i & 7) * 4;
        float z = zs[r];
        size_t base = (size_t)(r0 + r) * DM + h * HD;
        #pragma unroll
        for (int half_sel = 0; half_sel < 2; ++half_sel) {
            int c = c4 + half_sel * 32;
            float v0 = Qs[r][c+0] * z, v1 = Qs[r][c+1] * z;
            float v2 = Qs[r][c+2] * z, v3 = Qs[r][c+3] * z;
            *(uint2*)(g_QsH + base + c) = make_uint2(
                pack_h2(__float2half_rn(v0), __float2half_rn(v1)),
                pack_h2(__float2half_rn(v2), __float2half_rn(v3)));
        }
    }
}

// ---------------------------------------------------------------------------
extern "C" void kernel_launch(void* const* d_in, const int* in_sizes, int n_in,
                              void* d_out, int out_size)
{
    const float* x  = (const float*)d_in[0];
    const float* Wq = (const float*)d_in[1];
    const float* bq = (const float*)d_in[2];
    const float* Wd = (const float*)d_in[3];
    const float* bd = (const float*)d_in[4];
    const float* Wu = (const float*)d_in[5];
    const float* bu = (const float*)d_in[6];
    const float* Wo = (const float*)d_in[7];
    const float* bo = (const float*)d_in[8];
    float* out = (float*)d_out;

    float *pQ, *pCtx, *pKsum;
    __half *pKV, *pXh, *pXl, *pCh, *pQsH, *pM;
    __half *pWqH, *pWdH, *pWuH;
    cudaGetSymbolAddress((void**)&pQ,    g_Q);
    cudaGetSymbolAddress((void**)&pKV,   g_KV);
    cudaGetSymbolAddress((void**)&pCtx,  g_Ctx);
    cudaGetSymbolAddress((void**)&pKsum, g_Ksum);
    cudaGetSymbolAddress((void**)&pXh,   g_Xhi);
    cudaGetSymbolAddress((void**)&pXl,   g_Xlo);
    cudaGetSymbolAddress((void**)&pCh,   g_Chi);
    cudaGetSymbolAddress((void**)&pQsH,  g_QsH);
    cudaGetSymbolAddress((void**)&pM,    g_M);
    cudaGetSymbolAddress((void**)&pWqH,  g_WqH);
    cudaGetSymbolAddress((void**)&pWdH,  g_WdH);
    cudaGetSymbolAddress((void**)&pWuH,  g_WuH);

    static bool init = false;
    static cudaStream_t s1;
    static cudaEvent_t evFork, evKV, evQ;
    if (!init) {
        cudaStreamCreateWithFlags(&s1, cudaStreamNonBlocking);
        cudaEventCreateWithFlags(&evFork, cudaEventDisableTiming);
        cudaEventCreateWithFlags(&evKV,   cudaEventDisableTiming);
        cudaEventCreateWithFlags(&evQ,    cudaEventDisableTiming);
        init = true;
    }

    // --- fork side stream early: Wq rounding has no deps ---------------------
    cudaEventRecord(evFork, 0);
    cudaStreamWaitEvent(s1, evFork, 0);
    round_weightT<<<dim3(512/32, 512/32), 256, 0, s1>>>(Wq, pWqH, 512, 512);

    // --- preprocessing (default stream) --------------------------------------
    cudaMemsetAsync(pCtx,  0, sizeof(float) * B_*NH*HD*HD);
    cudaMemsetAsync(pKsum, 0, sizeof(float) * B_*NH*HD);
    rope_table<<<T_*32/128, 128>>>();
    round_weightT<<<dim3(128/32, 512/32), 256>>>(Wd, pWdH, 512, 128);
    round_weightT<<<dim3(1024/32, 128/32), 256>>>(Wu, pWuH, 128, 1024);
    split_rows<<<(size_t)BT*512/4/256, 256>>>(x, pXh, pXl);

    // --- default: C -> KV (tensor-serial; KV single-term) --------------------
    bgemm2<<<dim3(1, BT/128), 256>>>(pXh, pXl, pWdH, bd,
                                     nullptr, pCh, nullptr, 128, 512, 0);
    bgemm2<<<dim3(8, BT/128), 256>>>(pCh, nullptr, pWuH, bu,
                                     nullptr, pKV, nullptr, 1024, 128, 0);
    cudaEventRecord(evKV, 0);

    // --- side stream: Q GEMM AFTER KV, so it overlaps context/mker (no
    //     tensor-pipe contention with C/KV; context uses no tensor pipe) ------
    cudaStreamWaitEvent(s1, evKV, 0);
    bgemm2<<<dim3(4, BT/128), 256, 0, s1>>>(pXh, nullptr, pWqH, bq,
                                            pQ, nullptr, nullptr, 512, 512, 0);
    cudaEventRecord(evQ, s1);

    // --- default: context + M (FFMA/LDS-bound; runs under Q GEMM) ------------
    context_kernel<<<dim3(T_/256, B_*NH), 256>>>();
    mker<<<dim3(8, 64), 256>>>(Wo);

    // --- join: qprep needs Q (side stream) + ksum (context) ------------------
    cudaStreamWaitEvent(0, evQ, 0);
    qprep_kernel<<<dim3(BT/64, NH), 256>>>();

    // out = Q'' @ M_b + bo  (per-batch B; single fp16 term)
    bgemm2<<<dim3(4, BT/128), 256>>>(pQsH, nullptr, pM, bo,
                                     out, nullptr, nullptr, 512, 512, 512*512);
}

// round 16
// speedup vs baseline: 1.5983x; 1.0613x over previous
#include <cuda_runtime.h>
#include <cuda_fp16.h>
#include <math.h>
#include <stdint.h>

#define B_   8
#define T_   4096
#define BT   (B_*T_)          // 32768 rows
#define DM   512
#define NH   8
#define HD   64

#define PADH 40               // smem row stride in halves (80B; conflict-free)
#define ZSCALE     16384.0f
#define INV_ZSCALE (1.0f/16384.0f)

// ---------------- scratch (static device globals; no allocation) ------------
__device__ float  g_Q   [(size_t)BT * DM];     // Q fp32 (raw; roped in qprep)
__device__ __half g_KV  [(size_t)BT * 1024];   // kv fp16
__device__ float  g_Ctx [B_*NH*HD*HD];
__device__ float  g_Ksum[B_*NH*HD];
__device__ float  g_RopC[T_*32];
__device__ float  g_RopS[T_*32];

__device__ __half g_Xhi[(size_t)BT*DM],  g_Xlo[(size_t)BT*DM];
__device__ __half g_Chi[(size_t)BT*128];
__device__ __half g_QsH[(size_t)BT*DM];                         // z-scaled q'
__device__ __half g_M  [(size_t)B_*512*512];                    // per-batch Ctx@Wo / S
__device__ __half g_WqH[512*512];
__device__ __half g_WdH[128*512];
__device__ __half g_WuH[1024*128];

// ---------------- helpers ---------------------------------------------------
__device__ __forceinline__ uint32_t smem_u32(const void* p) {
    uint32_t a;
    asm("{ .reg .u64 t; cvta.to.shared.u64 t, %1; cvt.u32.u64 %0, t; }"
        : "=r"(a) : "l"(p));
    return a;
}
__device__ __forceinline__ void mma16816(float* d, const uint32_t* a, const uint32_t* b)
{
    asm volatile(
        "mma.sync.aligned.m16n8k16.row.col.f32.f16.f16.f32 "
        "{%0,%1,%2,%3}, {%4,%5,%6,%7}, {%8,%9}, {%0,%1,%2,%3};"
        : "+f"(d[0]), "+f"(d[1]), "+f"(d[2]), "+f"(d[3])
        : "r"(a[0]), "r"(a[1]), "r"(a[2]), "r"(a[3]), "r"(b[0]), "r"(b[1]));
}
__device__ __forceinline__ void ldsm_x4(uint32_t* r, uint32_t addr) {
    asm volatile("ldmatrix.sync.aligned.m8n8.x4.shared.b16 {%0,%1,%2,%3}, [%4];"
        : "=r"(r[0]), "=r"(r[1]), "=r"(r[2]), "=r"(r[3]) : "r"(addr));
}
__device__ __forceinline__ void ldsm_x2(uint32_t* r, uint32_t addr) {
    asm volatile("ldmatrix.sync.aligned.m8n8.x2.shared.b16 {%0,%1}, [%2];"
        : "=r"(r[0]), "=r"(r[1]) : "r"(addr));
}
__device__ __forceinline__ uint32_t pack_h2(__half a, __half b)
{
    __half2 p = __halves2half2(a, b);
    return *(uint32_t*)&p;
}
__device__ __forceinline__ void ld4h(const __half* p, float* o)
{
    uint2 u = *(const uint2*)p;
    const __half2* h = (const __half2*)&u;
    float2 a = __half22float2(h[0]);
    float2 b = __half22float2(h[1]);
    o[0] = a.x; o[1] = a.y; o[2] = b.x; o[3] = b.y;
}

// ---- elu(x)+1, branchless, FMA/ALU pipes only ------------------------------
__device__ __forceinline__ float elu1(float x)
{
    float t = fminf(x, 0.f) * 1.44269504089f;
    t = fmaxf(t, -28.f);
    float n = rintf(t);
    float f = t - n;
    float p = 1.33336498402e-3f;
    p = fmaf(p, f, 9.61812910763e-3f);
    p = fmaf(p, f, 5.55041086648e-2f);
    p = fmaf(p, f, 2.40226506959e-1f);
    p = fmaf(p, f, 6.93147180560e-1f);
    p = fmaf(p, f, 1.0f);
    float e = __int_as_float(((int)n + 127) << 23) * p;
    return (x > 0.f) ? (x + 1.f) : e;
}

// ========== fp16 GEMM body (device fn; smem passed in) ======================
__device__ __forceinline__ void gemm_body(
    __half* sAh, __half* sAl, __half* sBh,
    const __half* __restrict__ Ahi, const __half* __restrict__ Alo,
    const __half* __restrict__ Bh16,
    const float* __restrict__ bias,
    float* __restrict__ outF,
    __half* __restrict__ outHi, __half* __restrict__ outLo,
    int N, int K, int bStride, int m0, int n0)
{
    const int tid  = threadIdx.x;
    const int lane = tid & 31;
    const int wid  = tid >> 5;
    const int wm   = (wid >> 2) * 64;
    const int wn   = (wid & 3) * 32;
    const int g    = lane >> 2;
    const int t2   = (lane & 3) * 2;

    const bool twoTerm = (Alo != nullptr);

    const int lrow = tid >> 2;
    const int lseg = tid & 3;

    const __half* gA0 = Ahi  + (size_t)(m0 + lrow) * K + lseg * 8;
    const __half* gA1 = twoTerm ? (Alo + (size_t)(m0 + lrow) * K + lseg * 8) : gA0;
    const __half* gB0 = Bh16 + (size_t)(m0 >> 12) * bStride
                             + (size_t)(n0 + lrow) * K + lseg * 8;
    const size_t rstep = (size_t)64 * K;

    const int a_row  = ((lane >> 3) & 1) * 8 + (lane & 7);
    const int a_col8 = (lane >> 4) * 8;
    const int b_row  = (lane & 7);
    const int b_col8 = ((lane >> 3) & 1) * 8;

    const uint32_t uAh = smem_u32(sAh);
    const uint32_t uAl = smem_u32(sAl);
    const uint32_t uBh = smem_u32(sBh);

    const uint32_t soff  = (uint32_t)(lrow * (PADH*2) + lseg * 16);
    const uint32_t soff2 = soff + (uint32_t)(64 * PADH * 2);

    const int nch = K >> 5;

    uint4 pA0[2], pA1[2], pB0[2];
    pA0[0] = *(const uint4*)gA0; pA0[1] = *(const uint4*)(gA0 + rstep);
    pB0[0] = *(const uint4*)gB0; pB0[1] = *(const uint4*)(gB0 + rstep);
    if (twoTerm) { pA1[0] = *(const uint4*)gA1; pA1[1] = *(const uint4*)(gA1 + rstep); }

    float acc[4][4][4];
    #pragma unroll
    for (int mt = 0; mt < 4; ++mt)
        #pragma unroll
        for (int nt = 0; nt < 4; ++nt)
            #pragma unroll
            for (int i = 0; i < 4; ++i) acc[mt][nt][i] = 0.f;

    for (int ch = 0; ch < nch; ++ch) {
        *(uint4*)((char*)sAh + soff)  = pA0[0];
        *(uint4*)((char*)sAh + soff2) = pA0[1];
        if (twoTerm) {
            *(uint4*)((char*)sAl + soff)  = pA1[0];
            *(uint4*)((char*)sAl + soff2) = pA1[1];
        }
        *(uint4*)((char*)sBh + soff)  = pB0[0];
        *(uint4*)((char*)sBh + soff2) = pB0[1];
        __syncthreads();

        if (ch + 1 < nch) {
            const int ko = (ch + 1) * 32;
            pA0[0] = *(const uint4*)(gA0 + ko); pA0[1] = *(const uint4*)(gA0 + rstep + ko);
            pB0[0] = *(const uint4*)(gB0 + ko); pB0[1] = *(const uint4*)(gB0 + rstep + ko);
            if (twoTerm) {
                pA1[0] = *(const uint4*)(gA1 + ko);
                pA1[1] = *(const uint4*)(gA1 + rstep + ko);
            }
        }

        #pragma unroll
        for (int ks = 0; ks < 2; ++ks) {
            const int k0 = ks * 16;
            uint32_t ah[4][4], al[4][4];
            #pragma unroll
            for (int mt = 0; mt < 4; ++mt) {
                uint32_t off = (uint32_t)(((wm + mt*16 + a_row) * PADH + k0 + a_col8) * 2);
                ldsm_x4(ah[mt], uAh + off);
                if (twoTerm) ldsm_x4(al[mt], uAl + off);
            }
            #pragma unroll
            for (int nt = 0; nt < 4; ++nt) {
                uint32_t boff = (uint32_t)(((wn + nt*8 + b_row) * PADH + k0 + b_col8) * 2);
                uint32_t bh[2];
                ldsm_x2(bh, uBh + boff);
                #pragma unroll
                for (int mt = 0; mt < 4; ++mt) {
                    mma16816(acc[mt][nt], ah[mt], bh);
                    if (twoTerm) mma16816(acc[mt][nt], al[mt], bh);
                }
            }
        }
        __syncthreads();
    }

    #pragma unroll
    for (int mt = 0; mt < 4; ++mt) {
        int row = m0 + wm + mt * 16 + g;
        #pragma unroll
        for (int nt = 0; nt < 4; ++nt) {
            int col = n0 + wn + nt * 8 + t2;
            float b0 = bias[col], b1 = bias[col + 1];
            float v00 = acc[mt][nt][0] + b0, v01 = acc[mt][nt][1] + b1;
            float v10 = acc[mt][nt][2] + b0, v11 = acc[mt][nt][3] + b1;
            if (outF) {
                *(float2*)(outF + (size_t)row * N + col)       = make_float2(v00, v01);
                *(float2*)(outF + (size_t)(row + 8) * N + col) = make_float2(v10, v11);
            } else {
                *(uint32_t*)(outHi + (size_t)row * N + col) =
                    pack_h2(__float2half_rn(v00), __float2half_rn(v01));
                *(uint32_t*)(outHi + (size_t)(row + 8) * N + col) =
                    pack_h2(__float2half_rn(v10), __float2half_rn(v11));
            }
        }
    }
}

// ---------------- standalone GEMM kernel ------------------------------------
__global__ __launch_bounds__(256) void bgemm2(
    const __half* __restrict__ Ahi, const __half* __restrict__ Alo,
    const __half* __restrict__ Bh16,
    const float* __restrict__ bias,
    float* __restrict__ outF,
    __half* __restrict__ outHi,
    int N, int K, int bStride)
{
    __shared__ __align__(16) char sm[3*10240];
    gemm_body((__half*)sm, (__half*)(sm + 10240), (__half*)(sm + 20480),
              Ahi, Alo, Bh16, bias, outF, outHi, nullptr,
              N, K, bStride, blockIdx.y * 128, blockIdx.x * 128);
}

// ---------------- context body (device fn; smem passed in) ------------------
__device__ __forceinline__ void ctx_body(char* smc, int p, int t0)
{
    float (*Ks)[64] = (float(*)[64])smc;
    float (*Vs)[64] = (float(*)[64])(smc + 8192);

    const int b  = p >> 3;
    const int h  = p & 7;

    const int tid = threadIdx.x;
    const int tx  = tid & 15;
    const int ty  = tid >> 4;
    const int kr_ = tid >> 3;
    const int kc4 = (tid & 7) * 4;

    float acc[4][4];
    #pragma unroll
    for (int i = 0; i < 4; ++i)
        #pragma unroll
        for (int j = 0; j < 4; ++j) acc[i][j] = 0.f;
    float ksm[4] = {0.f, 0.f, 0.f, 0.f};

    for (int tt = 0; tt < 256; tt += 32) {
        {
            int t = t0 + tt + kr_;
            const __half* kp = g_KV + (size_t)(b * T_ + t) * 1024 + h * 128;
            float x1[4], x2[4];
            ld4h(kp + kc4, x1);
            ld4h(kp + 32 + kc4, x2);
            float4 cs = *(const float4*)(g_RopC + t * 32 + kc4);
            float4 sn = *(const float4*)(g_RopS + t * 32 + kc4);
            Ks[kr_][kc4+0]    = elu1(x1[0]*cs.x - x2[0]*sn.x);
            Ks[kr_][kc4+1]    = elu1(x1[1]*cs.y - x2[1]*sn.y);
            Ks[kr_][kc4+2]    = elu1(x1[2]*cs.z - x2[2]*sn.z);
            Ks[kr_][kc4+3]    = elu1(x1[3]*cs.w - x2[3]*sn.w);
            Ks[kr_][kc4+32]   = elu1(x1[0]*sn.x + x2[0]*cs.x);
            Ks[kr_][kc4+33]   = elu1(x1[1]*sn.y + x2[1]*cs.y);
            Ks[kr_][kc4+34]   = elu1(x1[2]*sn.z + x2[2]*cs.z);
            Ks[kr_][kc4+35]   = elu1(x1[3]*sn.w + x2[3]*cs.w);
        }
        #pragma unroll
        for (int ii = 0; ii < 2; ++ii) {
            int i = tid + ii * 256;
            int r = i >> 4;
            int c = (i & 15) * 4;
            const __half* vp = g_KV + (size_t)(b * T_ + t0 + tt + r) * 1024 + h * 128 + 64;
            float vv[4];
            ld4h(vp + c, vv);
            Vs[r][c]   = vv[0]; Vs[r][c+1] = vv[1];
            Vs[r][c+2] = vv[2]; Vs[r][c+3] = vv[3];
        }
        __syncthreads();
        #pragma unroll 8
        for (int t = 0; t < 32; ++t) {
            float kr[4], vr[4];
            *(float4*)kr = *(const float4*)&Ks[t][ty*4];
            *(float4*)vr = *(const float4*)&Vs[t][tx*4];
            #pragma unroll
            for (int i = 0; i < 4; ++i)
                #pragma unroll
                for (int j = 0; j < 4; ++j)
                    acc[i][j] = fmaf(kr[i], vr[j], acc[i][j]);
            if (tx == 0) {
                #pragma unroll
                for (int i = 0; i < 4; ++i) ksm[i] += kr[i];
            }
        }
        __syncthreads();
    }

    float* ctx = g_Ctx + (size_t)p * HD * HD;
    #pragma unroll
    for (int i = 0; i < 4; ++i)
        #pragma unroll
        for (int j = 0; j < 4; ++j)
            atomicAdd(&ctx[(ty*4 + i) * HD + tx*4 + j], acc[i][j]);
    if (tx == 0) {
        #pragma unroll
        for (int i = 0; i < 4; ++i)
            atomicAdd(&g_Ksum[p * HD + ty*4 + i], ksm[i]);
    }
}

// ====== fused: Q GEMM (even CTAs) + context (odd CTAs) ======================
// Grid 2048 x 256thr. Interleaved so SMs co-host tensor-bound and FMA-bound
// CTAs -> real pipe overlap (streams cannot: full-chip grids serialize).
__global__ __launch_bounds__(256) void fused_q_ctx(const float* __restrict__ bq)
{
    __shared__ __align__(16) char sm[3*10240];
    const int bid = blockIdx.x;
    const int idx = bid >> 1;
    if (bid & 1) {
        ctx_body(sm, idx & 63, (idx >> 6) * 256);
    } else {
        gemm_body((__half*)sm, (__half*)(sm + 10240), (__half*)(sm + 20480),
                  g_Xhi, nullptr, g_WqH, bq, g_Q, nullptr, nullptr,
                  512, 512, 0, (idx >> 2) * 128, (idx & 3) * 128);
    }
}

// ====== fused preprocessing: x split + 3 weight rounds + rope table =========
#define NSPLIT 16384           // BT*512/4/256
#define NWD    64              // Wd round: 4 x 16
#define NWU    128             // Wu round: 32 x 4
#define NWQ    256             // Wq round: 16 x 16
#define NROPE  512             // T*32/256

__device__ __forceinline__ void round_body(
    float (*t)[33], const float* __restrict__ W, __half* __restrict__ Wh,
    int K, int N, int bx, int by)
{
    int kb = by * 32, nb = bx * 32;
    int x = threadIdx.x & 31, y = threadIdx.x >> 5;
    #pragma unroll
    for (int i = 0; i < 32; i += 8)
        t[y + i][x] = W[(size_t)(kb + y + i) * N + nb + x];
    __syncthreads();
    #pragma unroll
    for (int i = 0; i < 32; i += 8)
        Wh[(size_t)(nb + y + i) * K + kb + x] = __float2half_rn(t[x][y + i]);
}

__global__ __launch_bounds__(256) void prep_kernel(
    const float* __restrict__ x,
    const float* __restrict__ Wd, const float* __restrict__ Wu,
    const float* __restrict__ Wq)
{
    __shared__ float tsh[32][33];
    const int bid = blockIdx.x;
    const int tid = threadIdx.x;

    if (bid < NSPLIT) {
        size_t e0 = ((size_t)bid * 256 + tid) * 4;
        float4 v = *(const float4*)(x + e0);
        __half h0 = __float2half_rn(v.x), h1 = __float2half_rn(v.y);
        __half h2 = __float2half_rn(v.z), h3 = __float2half_rn(v.w);
        *(uint2*)(g_Xhi + e0) = make_uint2(pack_h2(h0, h1), pack_h2(h2, h3));
        *(uint2*)(g_Xlo + e0) = make_uint2(
            pack_h2(__float2half_rn(v.x - __half2float(h0)),
                    __float2half_rn(v.y - __half2float(h1))),
            pack_h2(__float2half_rn(v.z - __half2float(h2)),
                    __float2half_rn(v.w - __half2float(h3))));
        return;
    }
    int j = bid - NSPLIT;
    if (j < NWD) {
        round_body(tsh, Wd, g_WdH, 512, 128, j & 3, j >> 2);
        return;
    }
    j -= NWD;
    if (j < NWU) {
        round_body(tsh, Wu, g_WuH, 128, 1024, j & 31, j >> 5);
        return;
    }
    j -= NWU;
    if (j < NWQ) {
        round_body(tsh, Wq, g_WqH, 512, 512, j & 15, j >> 4);
        return;
    }
    j -= NWQ;
    {   // rope table
        int idx = j * 256 + tid;
        int t = idx >> 5, jj = idx & 31;
        const float LOG2_1E4 = 13.2877123795494f;
        float freq = exp2f(-(float)jj * (LOG2_1E4 / 32.f));
        float s, c;
        sincosf((float)t * freq, &s, &c);
        g_RopC[idx] = c;
        g_RopS[idx] = s;
    }
}

// ====== fused: mker (bid<512) + qprep (bid>=512) ============================
__global__ __launch_bounds__(256) void fused_mq(const float* __restrict__ Wo)
{
    __shared__ __align__(16) char sm[21056];
    const int bid = blockIdx.x;
    const int tid = threadIdx.x;

    if (bid < 512) {
        // ---- mker: M_b[n][h*64+d] = (1/S) * sum_e Ctx[d][e] * Wo[h*64+e][n]
        float (*Ct)[65] = (float(*)[65])sm;
        float (*Ws)[68] = (float(*)[68])(sm + 64*65*4);
        const int n0 = (bid & 7) * 64;
        const int p  = bid >> 3;
        const int b  = p >> 3;
        const int h  = p & 7;
        const int tx = tid & 15;
        const int ty = tid >> 4;

        const float* ctx = g_Ctx + (size_t)p * HD * HD;
        #pragma unroll
        for (int i = 0; i < 16; ++i) {
            int lin = tid + i * 256;
            Ct[lin >> 6][lin & 63] = ctx[lin];
        }

        float acc[4][4];
        #pragma unroll
        for (int i = 0; i < 4; ++i)
            #pragma unroll
            for (int j = 0; j < 4; ++j) acc[i][j] = 0.f;

        for (int e0 = 0; e0 < 64; e0 += 16) {
            __syncthreads();
            {
                int e_l = tid >> 4;
                int n_l = (tid & 15) * 4;
                float4 w = *(const float4*)(Wo + (size_t)(h*64 + e0 + e_l) * 512 + n0 + n_l);
                Ws[e_l][n_l]   = w.x; Ws[e_l][n_l+1] = w.y;
                Ws[e_l][n_l+2] = w.z; Ws[e_l][n_l+3] = w.w;
            }
            __syncthreads();
            #pragma unroll
            for (int e = 0; e < 16; ++e) {
                float c0 = Ct[ty*4+0][e0+e];
                float c1 = Ct[ty*4+1][e0+e];
                float c2 = Ct[ty*4+2][e0+e];
                float c3 = Ct[ty*4+3][e0+e];
                float4 w = *(const float4*)&Ws[e][tx*4];
                acc[0][0] = fmaf(c0, w.x, acc[0][0]); acc[0][1] = fmaf(c0, w.y, acc[0][1]);
                acc[0][2] = fmaf(c0, w.z, acc[0][2]); acc[0][3] = fmaf(c0, w.w, acc[0][3]);
                acc[1][0] = fmaf(c1, w.x, acc[1][0]); acc[1][1] = fmaf(c1, w.y, acc[1][1]);
                acc[1][2] = fmaf(c1, w.z, acc[1][2]); acc[1][3] = fmaf(c1, w.w, acc[1][3]);
                acc[2][0] = fmaf(c2, w.x, acc[2][0]); acc[2][1] = fmaf(c2, w.y, acc[2][1]);
                acc[2][2] = fmaf(c2, w.z, acc[2][2]); acc[2][3] = fmaf(c2, w.w, acc[2][3]);
                acc[3][0] = fmaf(c3, w.x, acc[3][0]); acc[3][1] = fmaf(c3, w.y, acc[3][1]);
                acc[3][2] = fmaf(c3, w.z, acc[3][2]); acc[3][3] = fmaf(c3, w.w, acc[3][3]);
            }
        }

        __half* Mb = g_M + (size_t)b * 512 * 512;
        #pragma unroll
        for (int j = 0; j < 4; ++j) {
            int n = n0 + tx*4 + j;
            #pragma unroll
            for (int i = 0; i < 4; ++i) {
                int d = ty*4 + i;
                Mb[(size_t)n * 512 + h*64 + d] = __float2half_rn(acc[i][j] * INV_ZSCALE);
            }
        }
    } else {
        // ---- qprep: Q'' = (S*z) * elu1(rope(q)) -> fp16
        float (*Qs)[65] = (float(*)[65])sm;
        float* ks = (float*)(sm + 64*65*4);
        float* zs = ks + 64;
        const int idx = bid - 512;
        const int h  = idx & 7;
        const int r0 = (idx >> 3) * 64;
        const int b  = r0 >> 12;
        const int p  = b * NH + h;

        if (tid < 64) ks[tid] = g_Ksum[p * HD + tid];

        #pragma unroll
        for (int ii = 0; ii < 2; ++ii) {
            int i = tid + ii * 256;
            int r = i >> 3;
            int c4 = (i & 7) * 4;
            int t = (r0 + r) & (T_ - 1);
            size_t base = (size_t)(r0 + r) * DM + h * HD;
            float4 x1 = *(const float4*)(g_Q + base + c4);
            float4 x2 = *(const float4*)(g_Q + base + 32 + c4);
            float4 cs = *(const float4*)(g_RopC + t * 32 + c4);
            float4 sn = *(const float4*)(g_RopS + t * 32 + c4);
            Qs[r][c4+0]  = elu1(x1.x*cs.x - x2.x*sn.x);
            Qs[r][c4+1]  = elu1(x1.y*cs.y - x2.y*sn.y);
            Qs[r][c4+2]  = elu1(x1.z*cs.z - x2.z*sn.z);
            Qs[r][c4+3]  = elu1(x1.w*cs.w - x2.w*sn.w);
            Qs[r][c4+32] = elu1(x1.x*sn.x + x2.x*cs.x);
            Qs[r][c4+33] = elu1(x1.y*sn.y + x2.y*cs.y);
            Qs[r][c4+34] = elu1(x1.z*sn.z + x2.z*cs.z);
            Qs[r][c4+35] = elu1(x1.w*sn.w + x2.w*cs.w);
        }
        __syncthreads();

        if (tid < 64) {
            float dsum = 0.f;
            #pragma unroll
            for (int d = 0; d < 64; ++d) dsum += Qs[tid][d] * ks[d];
            zs[tid] = ZSCALE / (dsum + 1e-6f);
        }
        __syncthreads();

        #pragma unroll
        for (int ii = 0; ii < 2; ++ii) {
            int i = tid + ii * 256;
            int r = i >> 3;
            int c4 = (i & 7) * 4;
            float z = zs[r];
            size_t base = (size_t)(r0 + r) * DM + h * HD;
            #pragma unroll
            for (int half_sel = 0; half_sel < 2; ++half_sel) {
                int c = c4 + half_sel * 32;
                float v0 = Qs[r][c+0] * z, v1 = Qs[r][c+1] * z;
                float v2 = Qs[r][c+2] * z, v3 = Qs[r][c+3] * z;
                *(uint2*)(g_QsH + base + c) = make_uint2(
                    pack_h2(__float2half_rn(v0), __float2half_rn(v1)),
                    pack_h2(__float2half_rn(v2), __float2half_rn(v3)));
            }
        }
    }
}

// ---------------------------------------------------------------------------
extern "C" void kernel_launch(void* const* d_in, const int* in_sizes, int n_in,
                              void* d_out, int out_size)
{
    const float* x  = (const float*)d_in[0];
    const float* Wq = (const float*)d_in[1];
    const float* bq = (const float*)d_in[2];
    const float* Wd = (const float*)d_in[3];
    const float* bd = (const float*)d_in[4];
    const float* Wu = (const float*)d_in[5];
    const float* bu = (const float*)d_in[6];
    const float* Wo = (const float*)d_in[7];
    const float* bo = (const float*)d_in[8];
    float* out = (float*)d_out;

    float *pCtx, *pKsum;
    __half *pKV, *pXh, *pXl, *pCh, *pQsH, *pM, *pWdH, *pWuH;
    cudaGetSymbolAddress((void**)&pCtx,  g_Ctx);
    cudaGetSymbolAddress((void**)&pKsum, g_Ksum);
    cudaGetSymbolAddress((void**)&pKV,   g_KV);
    cudaGetSymbolAddress((void**)&pXh,   g_Xhi);
    cudaGetSymbolAddress((void**)&pXl,   g_Xlo);
    cudaGetSymbolAddress((void**)&pCh,   g_Chi);
    cudaGetSymbolAddress((void**)&pQsH,  g_QsH);
    cudaGetSymbolAddress((void**)&pM,    g_M);
    cudaGetSymbolAddress((void**)&pWdH,  g_WdH);
    cudaGetSymbolAddress((void**)&pWuH,  g_WuH);

    // accumulator zeroing
    cudaMemsetAsync(pCtx,  0, sizeof(float) * B_*NH*HD*HD);
    cudaMemsetAsync(pKsum, 0, sizeof(float) * B_*NH*HD);

    // 1) fused preprocessing (x split, weight rounds, rope table)
    prep_kernel<<<NSPLIT + NWD + NWU + NWQ + NROPE, 256>>>(x, Wd, Wu, Wq);

    // 2) C = x @ Wd + bd (2-term, fp16 out)
    bgemm2<<<dim3(1, BT/128), 256>>>(pXh, pXl, pWdH, bd,
                                     nullptr, pCh, 128, 512, 0);
    // 3) KV = C @ Wu + bu (1-term, fp16 out)
    bgemm2<<<dim3(8, BT/128), 256>>>(pCh, nullptr, pWuH, bu,
                                     nullptr, pKV, 1024, 128, 0);

    // 4) fused Q GEMM + context (interleaved CTAs -> pipe-level overlap)
    fused_q_ctx<<<2048, 256>>>(bq);

    // 5) fused mker + qprep
    fused_mq<<<512 + 4096, 256>>>(Wo);

    // 6) out = Q'' @ M_b + bo (per-batch B; 1-term)
    bgemm2<<<dim3(4, BT/128), 256>>>(pQsH, nullptr, pM, bo,
                                     out, nullptr, 512, 512, 512*512);
}

// round 17
// speedup vs baseline: 1.7295x; 1.0821x over previous
#include <cuda_runtime.h>
#include <cuda_fp16.h>
#include <math.h>
#include <stdint.h>

#define B_   8
#define T_   4096
#define BT   (B_*T_)          // 32768 rows
#define DM   512
#define NH   8
#define HD   64

#define PADH 40               // GEMM smem row stride in halves
#define CPAD 72               // ctx smem row stride in halves (conflict-free ldsm)
#define ZSCALE     16384.0f
#define INV_ZSCALE (1.0f/16384.0f)

// ---------------- scratch (static device globals; no allocation) ------------
__device__ float  g_Q   [(size_t)BT * DM];
__device__ __half g_KV  [(size_t)BT * 1024];
__device__ float  g_Ctx [B_*NH*HD*HD];
__device__ float  g_Ksum[B_*NH*HD];
__device__ float  g_RopC[T_*32];
__device__ float  g_RopS[T_*32];

__device__ __half g_Xhi[(size_t)BT*DM],  g_Xlo[(size_t)BT*DM];
__device__ __half g_Chi[(size_t)BT*128];
__device__ __half g_QsH[(size_t)BT*DM];
__device__ __half g_M  [(size_t)B_*512*512];
__device__ __half g_WqH[512*512];
__device__ __half g_WdH[128*512];
__device__ __half g_WuH[1024*128];

// ---------------- helpers ---------------------------------------------------
__device__ __forceinline__ uint32_t smem_u32(const void* p) {
    uint32_t a;
    asm("{ .reg .u64 t; cvta.to.shared.u64 t, %1; cvt.u32.u64 %0, t; }"
        : "=r"(a) : "l"(p));
    return a;
}
__device__ __forceinline__ void mma16816(float* d, const uint32_t* a, const uint32_t* b)
{
    asm volatile(
        "mma.sync.aligned.m16n8k16.row.col.f32.f16.f16.f32 "
        "{%0,%1,%2,%3}, {%4,%5,%6,%7}, {%8,%9}, {%0,%1,%2,%3};"
        : "+f"(d[0]), "+f"(d[1]), "+f"(d[2]), "+f"(d[3])
        : "r"(a[0]), "r"(a[1]), "r"(a[2]), "r"(a[3]), "r"(b[0]), "r"(b[1]));
}
__device__ __forceinline__ void ldsm_x4(uint32_t* r, uint32_t addr) {
    asm volatile("ldmatrix.sync.aligned.m8n8.x4.shared.b16 {%0,%1,%2,%3}, [%4];"
        : "=r"(r[0]), "=r"(r[1]), "=r"(r[2]), "=r"(r[3]) : "r"(addr));
}
__device__ __forceinline__ void ldsm_x2(uint32_t* r, uint32_t addr) {
    asm volatile("ldmatrix.sync.aligned.m8n8.x2.shared.b16 {%0,%1}, [%2];"
        : "=r"(r[0]), "=r"(r[1]) : "r"(addr));
}
__device__ __forceinline__ void ldsm_x4_t(uint32_t* r, uint32_t addr) {
    asm volatile("ldmatrix.sync.aligned.m8n8.x4.trans.shared.b16 {%0,%1,%2,%3}, [%4];"
        : "=r"(r[0]), "=r"(r[1]), "=r"(r[2]), "=r"(r[3]) : "r"(addr));
}
__device__ __forceinline__ uint32_t pack_h2(__half a, __half b)
{
    __half2 p = __halves2half2(a, b);
    return *(uint32_t*)&p;
}
__device__ __forceinline__ void ld4h(const __half* p, float* o)
{
    uint2 u = *(const uint2*)p;
    const __half2* h = (const __half2*)&u;
    float2 a = __half22float2(h[0]);
    float2 b = __half22float2(h[1]);
    o[0] = a.x; o[1] = a.y; o[2] = b.x; o[3] = b.y;
}

// ---- elu(x)+1, branchless, FMA/ALU pipes only ------------------------------
__device__ __forceinline__ float elu1(float x)
{
    float t = fminf(x, 0.f) * 1.44269504089f;
    t = fmaxf(t, -28.f);
    float n = rintf(t);
    float f = t - n;
    float p = 1.33336498402e-3f;
    p = fmaf(p, f, 9.61812910763e-3f);
    p = fmaf(p, f, 5.55041086648e-2f);
    p = fmaf(p, f, 2.40226506959e-1f);
    p = fmaf(p, f, 6.93147180560e-1f);
    p = fmaf(p, f, 1.0f);
    float e = __int_as_float(((int)n + 127) << 23) * p;
    return (x > 0.f) ? (x + 1.f) : e;
}

// ========== fp16 GEMM body (device fn; smem passed in) ======================
__device__ __forceinline__ void gemm_body(
    __half* sAh, __half* sAl, __half* sBh,
    const __half* __restrict__ Ahi, const __half* __restrict__ Alo,
    const __half* __restrict__ Bh16,
    const float* __restrict__ bias,
    float* __restrict__ outF,
    __half* __restrict__ outHi,
    int N, int K, int bStride, int m0, int n0)
{
    const int tid  = threadIdx.x;
    const int lane = tid & 31;
    const int wid  = tid >> 5;
    const int wm   = (wid >> 2) * 64;
    const int wn   = (wid & 3) * 32;
    const int g    = lane >> 2;
    const int t2   = (lane & 3) * 2;

    const bool twoTerm = (Alo != nullptr);

    const int lrow = tid >> 2;
    const int lseg = tid & 3;

    const __half* gA0 = Ahi  + (size_t)(m0 + lrow) * K + lseg * 8;
    const __half* gA1 = twoTerm ? (Alo + (size_t)(m0 + lrow) * K + lseg * 8) : gA0;
    const __half* gB0 = Bh16 + (size_t)(m0 >> 12) * bStride
                             + (size_t)(n0 + lrow) * K + lseg * 8;
    const size_t rstep = (size_t)64 * K;

    const int a_row  = ((lane >> 3) & 1) * 8 + (lane & 7);
    const int a_col8 = (lane >> 4) * 8;
    const int b_row  = (lane & 7);
    const int b_col8 = ((lane >> 3) & 1) * 8;

    const uint32_t uAh = smem_u32(sAh);
    const uint32_t uAl = smem_u32(sAl);
    const uint32_t uBh = smem_u32(sBh);

    const uint32_t soff  = (uint32_t)(lrow * (PADH*2) + lseg * 16);
    const uint32_t soff2 = soff + (uint32_t)(64 * PADH * 2);

    const int nch = K >> 5;

    uint4 pA0[2], pA1[2], pB0[2];
    pA0[0] = *(const uint4*)gA0; pA0[1] = *(const uint4*)(gA0 + rstep);
    pB0[0] = *(const uint4*)gB0; pB0[1] = *(const uint4*)(gB0 + rstep);
    if (twoTerm) { pA1[0] = *(const uint4*)gA1; pA1[1] = *(const uint4*)(gA1 + rstep); }

    float acc[4][4][4];
    #pragma unroll
    for (int mt = 0; mt < 4; ++mt)
        #pragma unroll
        for (int nt = 0; nt < 4; ++nt)
            #pragma unroll
            for (int i = 0; i < 4; ++i) acc[mt][nt][i] = 0.f;

    for (int ch = 0; ch < nch; ++ch) {
        *(uint4*)((char*)sAh + soff)  = pA0[0];
        *(uint4*)((char*)sAh + soff2) = pA0[1];
        if (twoTerm) {
            *(uint4*)((char*)sAl + soff)  = pA1[0];
            *(uint4*)((char*)sAl + soff2) = pA1[1];
        }
        *(uint4*)((char*)sBh + soff)  = pB0[0];
        *(uint4*)((char*)sBh + soff2) = pB0[1];
        __syncthreads();

        if (ch + 1 < nch) {
            const int ko = (ch + 1) * 32;
            pA0[0] = *(const uint4*)(gA0 + ko); pA0[1] = *(const uint4*)(gA0 + rstep + ko);
            pB0[0] = *(const uint4*)(gB0 + ko); pB0[1] = *(const uint4*)(gB0 + rstep + ko);
            if (twoTerm) {
                pA1[0] = *(const uint4*)(gA1 + ko);
                pA1[1] = *(const uint4*)(gA1 + rstep + ko);
            }
        }

        #pragma unroll
        for (int ks = 0; ks < 2; ++ks) {
            const int k0 = ks * 16;
            uint32_t ah[4][4], al[4][4];
            #pragma unroll
            for (int mt = 0; mt < 4; ++mt) {
                uint32_t off = (uint32_t)(((wm + mt*16 + a_row) * PADH + k0 + a_col8) * 2);
                ldsm_x4(ah[mt], uAh + off);
                if (twoTerm) ldsm_x4(al[mt], uAl + off);
            }
            #pragma unroll
            for (int nt = 0; nt < 4; ++nt) {
                uint32_t boff = (uint32_t)(((wn + nt*8 + b_row) * PADH + k0 + b_col8) * 2);
                uint32_t bh[2];
                ldsm_x2(bh, uBh + boff);
                #pragma unroll
                for (int mt = 0; mt < 4; ++mt) {
                    mma16816(acc[mt][nt], ah[mt], bh);
                    if (twoTerm) mma16816(acc[mt][nt], al[mt], bh);
                }
            }
        }
        __syncthreads();
    }

    #pragma unroll
    for (int mt = 0; mt < 4; ++mt) {
        int row = m0 + wm + mt * 16 + g;
        #pragma unroll
        for (int nt = 0; nt < 4; ++nt) {
            int col = n0 + wn + nt * 8 + t2;
            float b0 = bias[col], b1 = bias[col + 1];
            float v00 = acc[mt][nt][0] + b0, v01 = acc[mt][nt][1] + b1;
            float v10 = acc[mt][nt][2] + b0, v11 = acc[mt][nt][3] + b1;
            if (outF) {
                *(float2*)(outF + (size_t)row * N + col)       = make_float2(v00, v01);
                *(float2*)(outF + (size_t)(row + 8) * N + col) = make_float2(v10, v11);
            } else {
                *(uint32_t*)(outHi + (size_t)row * N + col) =
                    pack_h2(__float2half_rn(v00), __float2half_rn(v01));
                *(uint32_t*)(outHi + (size_t)(row + 8) * N + col) =
                    pack_h2(__float2half_rn(v10), __float2half_rn(v11));
            }
        }
    }
}

// ---------------- standalone GEMM kernel ------------------------------------
__global__ __launch_bounds__(256) void bgemm2(
    const __half* __restrict__ Ahi, const __half* __restrict__ Alo,
    const __half* __restrict__ Bh16,
    const float* __restrict__ bias,
    float* __restrict__ outF,
    __half* __restrict__ outHi,
    int N, int K, int bStride)
{
    __shared__ __align__(16) char sm[3*10240];
    gemm_body((__half*)sm, (__half*)(sm + 10240), (__half*)(sm + 20480),
              Ahi, Alo, Bh16, bias, outF, outHi,
              N, K, bStride, blockIdx.y * 128, blockIdx.x * 128);
}

// ---------------- context body: tensorized (mma over t) ---------------------
// Ctx[d][e] += sum_t elu1(rope(K))[t][d] * V[t][e]  via m16n8k16 with k = t.
// smem: sKh [32][CPAD] fp16, sVh [32][CPAD] fp16, sKsum[64] f32.
__device__ __forceinline__ void ctx_body(char* smc, int p, int t0)
{
    __half* sKh = (__half*)smc;                 // 32*72*2 = 4608 B
    __half* sVh = (__half*)(smc + 4608);        // 4608 B
    float*  sKsum = (float*)(smc + 9216);       // 256 B

    const int b  = p >> 3;
    const int h  = p & 7;

    const int tid  = threadIdx.x;
    const int lane = tid & 31;
    const int wid  = tid >> 5;
    const int kr_ = tid >> 3;          // t within 32-chunk
    const int kc4 = (tid & 7) * 4;     // d base (first half)
    const int vc8 = (tid & 7) * 8;     // e base for V copy

    // mma tile: 8 warps over 64x64 -> warp tile 32x16
    const int wm = (wid >> 2) * 32;
    const int wn = (wid & 3) * 16;
    const int g  = lane >> 2;
    const int t2 = (lane & 3) * 2;
    // ldmatrix.trans lane maps (derived from non-trans tile order)
    const int at_row = (lane & 7) + ((lane >> 4) & 1) * 8;   // t
    const int at_col = ((lane >> 3) & 1) * 8;                // d offset
    const int bt_row = (lane & 7) + ((lane >> 3) & 1) * 8;   // t
    const int bt_col = ((lane >> 4) & 1) * 8;                // e offset

    const uint32_t uK = smem_u32(sKh);
    const uint32_t uV = smem_u32(sVh);

    if (tid < 64) sKsum[tid] = 0.f;

    float acc[2][2][4];
    #pragma unroll
    for (int mt = 0; mt < 2; ++mt)
        #pragma unroll
        for (int nt = 0; nt < 2; ++nt)
            #pragma unroll
            for (int i = 0; i < 4; ++i) acc[mt][nt][i] = 0.f;
    float ksm[8];
    #pragma unroll
    for (int i = 0; i < 8; ++i) ksm[i] = 0.f;

    for (int tt = 0; tt < 256; tt += 32) {
        // --- convert K (rope+elu -> fp16 [t][d]); copy V raw fp16 [t][e] ----
        {
            int t = t0 + tt + kr_;
            const __half* kp = g_KV + (size_t)(b * T_ + t) * 1024 + h * 128;
            float x1[4], x2[4];
            ld4h(kp + kc4, x1);
            ld4h(kp + 32 + kc4, x2);
            float4 cs = *(const float4*)(g_RopC + t * 32 + kc4);
            float4 sn = *(const float4*)(g_RopS + t * 32 + kc4);
            float v0 = elu1(x1[0]*cs.x - x2[0]*sn.x);
            float v1 = elu1(x1[1]*cs.y - x2[1]*sn.y);
            float v2 = elu1(x1[2]*cs.z - x2[2]*sn.z);
            float v3 = elu1(x1[3]*cs.w - x2[3]*sn.w);
            float w0 = elu1(x1[0]*sn.x + x2[0]*cs.x);
            float w1 = elu1(x1[1]*sn.y + x2[1]*cs.y);
            float w2 = elu1(x1[2]*sn.z + x2[2]*cs.z);
            float w3 = elu1(x1[3]*sn.w + x2[3]*cs.w);
            ksm[0] += v0; ksm[1] += v1; ksm[2] += v2; ksm[3] += v3;
            ksm[4] += w0; ksm[5] += w1; ksm[6] += w2; ksm[7] += w3;
            *(uint2*)(sKh + kr_ * CPAD + kc4) = make_uint2(
                pack_h2(__float2half_rn(v0), __float2half_rn(v1)),
                pack_h2(__float2half_rn(v2), __float2half_rn(v3)));
            *(uint2*)(sKh + kr_ * CPAD + kc4 + 32) = make_uint2(
                pack_h2(__float2half_rn(w0), __float2half_rn(w1)),
                pack_h2(__float2half_rn(w2), __float2half_rn(w3)));
            // V: raw 16B copy (already fp16)
            *(uint4*)(sVh + kr_ * CPAD + vc8) =
                *(const uint4*)(kp + 64 + vc8);
        }
        __syncthreads();

        // --- mma: k = t (2 k16 steps per 32-chunk) --------------------------
        #pragma unroll
        for (int ks = 0; ks < 2; ++ks) {
            const int k0 = ks * 16;
            uint32_t ah[2][4], bv[4];
            #pragma unroll
            for (int mt = 0; mt < 2; ++mt)
                ldsm_x4_t(ah[mt], uK + (uint32_t)(((k0 + at_row) * CPAD
                                         + wm + mt*16 + at_col) * 2));
            ldsm_x4_t(bv, uV + (uint32_t)(((k0 + bt_row) * CPAD
                                         + wn + bt_col) * 2));
            #pragma unroll
            for (int mt = 0; mt < 2; ++mt) {
                mma16816(acc[mt][0], ah[mt], &bv[0]);
                mma16816(acc[mt][1], ah[mt], &bv[2]);
            }
        }
        __syncthreads();
    }

    // --- reduce ksum: regs -> smem -> global --------------------------------
    #pragma unroll
    for (int i = 0; i < 4; ++i) {
        atomicAdd(&sKsum[kc4 + i], ksm[i]);
        atomicAdd(&sKsum[kc4 + 32 + i], ksm[4 + i]);
    }
    __syncthreads();
    if (tid < 64) atomicAdd(&g_Ksum[p * HD + tid], sKsum[tid]);

    // --- merge ctx ----------------------------------------------------------
    float* ctx = g_Ctx + (size_t)p * HD * HD;
    #pragma unroll
    for (int mt = 0; mt < 2; ++mt) {
        int d0 = wm + mt * 16 + g;
        #pragma unroll
        for (int nt = 0; nt < 2; ++nt) {
            int e0 = wn + nt * 8 + t2;
            atomicAdd(&ctx[(size_t)d0 * HD + e0],     acc[mt][nt][0]);
            atomicAdd(&ctx[(size_t)d0 * HD + e0 + 1], acc[mt][nt][1]);
            atomicAdd(&ctx[(size_t)(d0+8) * HD + e0],     acc[mt][nt][2]);
            atomicAdd(&ctx[(size_t)(d0+8) * HD + e0 + 1], acc[mt][nt][3]);
        }
    }
}

// ====== fused: Q GEMM (even CTAs) + context (odd CTAs) ======================
__global__ __launch_bounds__(256) void fused_q_ctx(const float* __restrict__ bq)
{
    __shared__ __align__(16) char sm[3*10240];
    const int bid = blockIdx.x;
    const int idx = bid >> 1;
    if (bid & 1) {
        ctx_body(sm, idx & 63, (idx >> 6) * 256);
    } else {
        gemm_body((__half*)sm, (__half*)(sm + 10240), (__half*)(sm + 20480),
                  g_Xhi, nullptr, g_WqH, bq, g_Q, nullptr,
                  512, 512, 0, (idx >> 2) * 128, (idx & 3) * 128);
    }
}

// ====== fused preprocessing: x split + 3 weight rounds + rope table =========
#define NSPLIT 16384
#define NWD    64
#define NWU    128
#define NWQ    256
#define NROPE  512

__device__ __forceinline__ void round_body(
    float (*t)[33], const float* __restrict__ W, __half* __restrict__ Wh,
    int K, int N, int bx, int by)
{
    int kb = by * 32, nb = bx * 32;
    int x = threadIdx.x & 31, y = threadIdx.x >> 5;
    #pragma unroll
    for (int i = 0; i < 32; i += 8)
        t[y + i][x] = W[(size_t)(kb + y + i) * N + nb + x];
    __syncthreads();
    #pragma unroll
    for (int i = 0; i < 32; i += 8)
        Wh[(size_t)(nb + y + i) * K + kb + x] = __float2half_rn(t[x][y + i]);
}

__global__ __launch_bounds__(256) void prep_kernel(
    const float* __restrict__ x,
    const float* __restrict__ Wd, const float* __restrict__ Wu,
    const float* __restrict__ Wq)
{
    __shared__ float tsh[32][33];
    const int bid = blockIdx.x;
    const int tid = threadIdx.x;

    if (bid < NSPLIT) {
        size_t e0 = ((size_t)bid * 256 + tid) * 4;
        float4 v = *(const float4*)(x + e0);
        __half h0 = __float2half_rn(v.x), h1 = __float2half_rn(v.y);
        __half h2 = __float2half_rn(v.z), h3 = __float2half_rn(v.w);
        *(uint2*)(g_Xhi + e0) = make_uint2(pack_h2(h0, h1), pack_h2(h2, h3));
        *(uint2*)(g_Xlo + e0) = make_uint2(
            pack_h2(__float2half_rn(v.x - __half2float(h0)),
                    __float2half_rn(v.y - __half2float(h1))),
            pack_h2(__float2half_rn(v.z - __half2float(h2)),
                    __float2half_rn(v.w - __half2float(h3))));
        return;
    }
    int j = bid - NSPLIT;
    if (j < NWD) { round_body(tsh, Wd, g_WdH, 512, 128, j & 3, j >> 2); return; }
    j -= NWD;
    if (j < NWU) { round_body(tsh, Wu, g_WuH, 128, 1024, j & 31, j >> 5); return; }
    j -= NWU;
    if (j < NWQ) { round_body(tsh, Wq, g_WqH, 512, 512, j & 15, j >> 4); return; }
    j -= NWQ;
    {
        int idx = j * 256 + tid;
        int t = idx >> 5, jj = idx & 31;
        const float LOG2_1E4 = 13.2877123795494f;
        float freq = exp2f(-(float)jj * (LOG2_1E4 / 32.f));
        float s, c;
        sincosf((float)t * freq, &s, &c);
        g_RopC[idx] = c;
        g_RopS[idx] = s;
    }
}

// ====== fused: mker (bid<512) + qprep (bid>=512) ============================
__global__ __launch_bounds__(256) void fused_mq(const float* __restrict__ Wo)
{
    __shared__ __align__(16) char sm[21056];
    const int bid = blockIdx.x;
    const int tid = threadIdx.x;

    if (bid < 512) {
        float (*Ct)[65] = (float(*)[65])sm;
        float (*Ws)[68] = (float(*)[68])(sm + 64*65*4);
        const int n0 = (bid & 7) * 64;
        const int p  = bid >> 3;
        const int b  = p >> 3;
        const int h  = p & 7;
        const int tx = tid & 15;
        const int ty = tid >> 4;

        const float* ctx = g_Ctx + (size_t)p * HD * HD;
        #pragma unroll
        for (int i = 0; i < 16; ++i) {
            int lin = tid + i * 256;
            Ct[lin >> 6][lin & 63] = ctx[lin];
        }

        float acc[4][4];
        #pragma unroll
        for (int i = 0; i < 4; ++i)
            #pragma unroll
            for (int j = 0; j < 4; ++j) acc[i][j] = 0.f;

        for (int e0 = 0; e0 < 64; e0 += 16) {
            __syncthreads();
            {
                int e_l = tid >> 4;
                int n_l = (tid & 15) * 4;
                float4 w = *(const float4*)(Wo + (size_t)(h*64 + e0 + e_l) * 512 + n0 + n_l);
                Ws[e_l][n_l]   = w.x; Ws[e_l][n_l+1] = w.y;
                Ws[e_l][n_l+2] = w.z; Ws[e_l][n_l+3] = w.w;
            }
            __syncthreads();
            #pragma unroll
            for (int e = 0; e < 16; ++e) {
                float c0 = Ct[ty*4+0][e0+e];
                float c1 = Ct[ty*4+1][e0+e];
                float c2 = Ct[ty*4+2][e0+e];
                float c3 = Ct[ty*4+3][e0+e];
                float4 w = *(const float4*)&Ws[e][tx*4];
                acc[0][0] = fmaf(c0, w.x, acc[0][0]); acc[0][1] = fmaf(c0, w.y, acc[0][1]);
                acc[0][2] = fmaf(c0, w.z, acc[0][2]); acc[0][3] = fmaf(c0, w.w, acc[0][3]);
                acc[1][0] = fmaf(c1, w.x, acc[1][0]); acc[1][1] = fmaf(c1, w.y, acc[1][1]);
                acc[1][2] = fmaf(c1, w.z, acc[1][2]); acc[1][3] = fmaf(c1, w.w, acc[1][3]);
                acc[2][0] = fmaf(c2, w.x, acc[2][0]); acc[2][1] = fmaf(c2, w.y, acc[2][1]);
                acc[2][2] = fmaf(c2, w.z, acc[2][2]); acc[2][3] = fmaf(c2, w.w, acc[2][3]);
                acc[3][0] = fmaf(c3, w.x, acc[3][0]); acc[3][1] = fmaf(c3, w.y, acc[3][1]);
                acc[3][2] = fmaf(c3, w.z, acc[3][2]); acc[3][3] = fmaf(c3, w.w, acc[3][3]);
            }
        }

        __half* Mb = g_M + (size_t)b * 512 * 512;
        #pragma unroll
        for (int j = 0; j < 4; ++j) {
            int n = n0 + tx*4 + j;
            #pragma unroll
            for (int i = 0; i < 4; ++i) {
                int d = ty*4 + i;
                Mb[(size_t)n * 512 + h*64 + d] = __float2half_rn(acc[i][j] * INV_ZSCALE);
            }
        }
    } else {
        float (*Qs)[65] = (float(*)[65])sm;
        float* ks = (float*)(sm + 64*65*4);
        float* zs = ks + 64;
        const int idx = bid - 512;
        const int h  = idx & 7;
        const int r0 = (idx >> 3) * 64;
        const int b  = r0 >> 12;
        const int p  = b * NH + h;

        if (tid < 64) ks[tid] = g_Ksum[p * HD + tid];

        #pragma unroll
        for (int ii = 0; ii < 2; ++ii) {
            int i = tid + ii * 256;
            int r = i >> 3;
            int c4 = (i & 7) * 4;
            int t = (r0 + r) & (T_ - 1);
            size_t base = (size_t)(r0 + r) * DM + h * HD;
            float4 x1 = *(const float4*)(g_Q + base + c4);
            float4 x2 = *(const float4*)(g_Q + base + 32 + c4);
            float4 cs = *(const float4*)(g_RopC + t * 32 + c4);
            float4 sn = *(const float4*)(g_RopS + t * 32 + c4);
            Qs[r][c4+0]  = elu1(x1.x*cs.x - x2.x*sn.x);
            Qs[r][c4+1]  = elu1(x1.y*cs.y - x2.y*sn.y);
            Qs[r][c4+2]  = elu1(x1.z*cs.z - x2.z*sn.z);
            Qs[r][c4+3]  = elu1(x1.w*cs.w - x2.w*sn.w);
            Qs[r][c4+32] = elu1(x1.x*sn.x + x2.x*cs.x);
            Qs[r][c4+33] = elu1(x1.y*sn.y + x2.y*cs.y);
            Qs[r][c4+34] = elu1(x1.z*sn.z + x2.z*cs.z);
            Qs[r][c4+35] = elu1(x1.w*sn.w + x2.w*cs.w);
        }
        __syncthreads();

        if (tid < 64) {
            float dsum = 0.f;
            #pragma unroll
            for (int d = 0; d < 64; ++d) dsum += Qs[tid][d] * ks[d];
            zs[tid] = ZSCALE / (dsum + 1e-6f);
        }
        __syncthreads();

        #pragma unroll
        for (int ii = 0; ii < 2; ++ii) {
            int i = tid + ii * 256;
            int r = i >> 3;
            int c4 = (i & 7) * 4;
            float z = zs[r];
            size_t base = (size_t)(r0 + r) * DM + h * HD;
            #pragma unroll
            for (int half_sel = 0; half_sel < 2; ++half_sel) {
                int c = c4 + half_sel * 32;
                float v0 = Qs[r][c+0] * z, v1 = Qs[r][c+1] * z;
                float v2 = Qs[r][c+2] * z, v3 = Qs[r][c+3] * z;
                *(uint2*)(g_QsH + base + c) = make_uint2(
                    pack_h2(__float2half_rn(v0), __float2half_rn(v1)),
                    pack_h2(__float2half_rn(v2), __float2half_rn(v3)));
            }
        }
    }
}

// ---------------------------------------------------------------------------
extern "C" void kernel_launch(void* const* d_in, const int* in_sizes, int n_in,
                              void* d_out, int out_size)
{
    const float* x  = (const float*)d_in[0];
    const float* Wq = (const float*)d_in[1];
    const float* bq = (const float*)d_in[2];
    const float* Wd = (const float*)d_in[3];
    const float* bd = (const float*)d_in[4];
    const float* Wu = (const float*)d_in[5];
    const float* bu = (const float*)d_in[6];
    const float* Wo = (const float*)d_in[7];
    const float* bo = (const float*)d_in[8];
    float* out = (float*)d_out;

    float *pCtx, *pKsum;
    __half *pKV, *pXh, *pXl, *pCh, *pQsH, *pM, *pWdH, *pWuH;
    cudaGetSymbolAddress((void**)&pCtx,  g_Ctx);
    cudaGetSymbolAddress((void**)&pKsum, g_Ksum);
    cudaGetSymbolAddress((void**)&pKV,   g_KV);
    cudaGetSymbolAddress((void**)&pXh,   g_Xhi);
    cudaGetSymbolAddress((void**)&pXl,   g_Xlo);
    cudaGetSymbolAddress((void**)&pCh,   g_Chi);
    cudaGetSymbolAddress((void**)&pQsH,  g_QsH);
    cudaGetSymbolAddress((void**)&pM,    g_M);
    cudaGetSymbolAddress((void**)&pWdH,  g_WdH);
    cudaGetSymbolAddress((void**)&pWuH,  g_WuH);

    cudaMemsetAsync(pCtx,  0, sizeof(float) * B_*NH*HD*HD);
    cudaMemsetAsync(pKsum, 0, sizeof(float) * B_*NH*HD);

    // 1) fused preprocessing
    prep_kernel<<<NSPLIT + NWD + NWU + NWQ + NROPE, 256>>>(x, Wd, Wu, Wq);

    // 2) C = x @ Wd + bd (2-term, fp16 out)
    bgemm2<<<dim3(1, BT/128), 256>>>(pXh, pXl, pWdH, bd,
                                     nullptr, pCh, 128, 512, 0);
    // 3) KV = C @ Wu + bu (1-term, fp16 out)
    bgemm2<<<dim3(8, BT/128), 256>>>(pCh, nullptr, pWuH, bu,
                                     nullptr, pKV, 1024, 128, 0);

    // 4) fused Q GEMM + tensorized context
    fused_q_ctx<<<2048, 256>>>(bq);

    // 5) fused mker + qprep
    fused_mq<<<512 + 4096, 256>>>(Wo);

    // 6) out = Q'' @ M_b + bo (per-batch B; 1-term)
    bgemm2<<<dim3(4, BT/128), 256>>>(pQsH, nullptr, pM, bo,
                                     out, nullptr, 512, 512, 512*512);
}